// round 8
// baseline (speedup 1.0000x reference)
#include <cuda_runtime.h>
#include <cuda_bf16.h>
#include <cuda_fp16.h>
#include <cstdint>
#include <math.h>

#define BB 8
#define LL 1024
#define DD 768
#define INV_SCALE 0.03608439182435161f  /* 1/sqrt(768) */

typedef __nv_bfloat16 bf16;

// ---------------------------------------------------------------------------
// scratch (device globals; no allocation)
// ---------------------------------------------------------------------------
__device__ bf16 s_lhs_hi[BB * LL * DD], s_lhs_lo[BB * LL * DD];   // proj A
__device__ bf16 s_rhs_hi[BB * LL * DD], s_rhs_lo[BB * LL * DD];
__device__ __half s_lhsT_h[BB * DD * LL];   // apply B (fp16, single)
__device__ __half s_rhsT_h[BB * DD * LL];
__device__ bf16 s_Wl_hi[DD * DD], s_Wl_lo[DD * DD];
__device__ bf16 s_Wr_hi[DD * DD], s_Wr_lo[DD * DD];
__device__ int8_t g_La[BB * LL * DD], g_Lb[BB * LL * DD];  // tanh proj, s8 pair
__device__ int8_t g_Ra[BB * LL * DD], g_Rb[BB * LL * DD];
__device__ __half g_P1[BB * LL * LL];    // row-softmax probs fp16 [l][r]
__device__ __half g_P2T[BB * LL * LL];   // col-softmax probs fp16, transposed [r][l]
__device__ float g_S[BB * LL * LL];
__device__ float g_rowc[BB * LL];
__device__ float g_colc[BB * LL];

__device__ __forceinline__ float fast_tanh(float x) {
    return 1.0f - __fdividef(2.0f, __expf(2.0f * x) + 1.0f);
}

__device__ __forceinline__ uint32_t smem_to_u32(const void* p) {
    uint32_t a;
    asm("{ .reg .u64 t; cvta.to.shared.u64 t, %1; cvt.u32.u64 %0, t; }"
        : "=r"(a) : "l"(p));
    return a;
}

// ---------------------------------------------------------------------------
// MMA helpers
// ---------------------------------------------------------------------------
__device__ __forceinline__ void ldsm4(uint32_t* r, uint32_t addr) {
    asm volatile("ldmatrix.sync.aligned.m8n8.x4.shared.b16 {%0,%1,%2,%3}, [%4];"
                 : "=r"(r[0]), "=r"(r[1]), "=r"(r[2]), "=r"(r[3]) : "r"(addr));
}

__device__ __forceinline__ void mma16816_bf(float* d, const uint32_t* a,
                                            uint32_t b0, uint32_t b1) {
    asm volatile(
        "mma.sync.aligned.m16n8k16.row.col.f32.bf16.bf16.f32 "
        "{%0,%1,%2,%3}, {%4,%5,%6,%7}, {%8,%9}, {%0,%1,%2,%3};"
        : "+f"(d[0]), "+f"(d[1]), "+f"(d[2]), "+f"(d[3])
        : "r"(a[0]), "r"(a[1]), "r"(a[2]), "r"(a[3]), "r"(b0), "r"(b1));
}

__device__ __forceinline__ void mma16816_f16(float* d, const uint32_t* a,
                                             uint32_t b0, uint32_t b1) {
    asm volatile(
        "mma.sync.aligned.m16n8k16.row.col.f32.f16.f16.f32 "
        "{%0,%1,%2,%3}, {%4,%5,%6,%7}, {%8,%9}, {%0,%1,%2,%3};"
        : "+f"(d[0]), "+f"(d[1]), "+f"(d[2]), "+f"(d[3])
        : "r"(a[0]), "r"(a[1]), "r"(a[2]), "r"(a[3]), "r"(b0), "r"(b1));
}

__device__ __forceinline__ void imma16832(int* d, const uint32_t* a,
                                          uint32_t b0, uint32_t b1) {
    asm volatile(
        "mma.sync.aligned.m16n8k32.row.col.s32.s8.s8.s32 "
        "{%0,%1,%2,%3}, {%4,%5,%6,%7}, {%8,%9}, {%0,%1,%2,%3};"
        : "+r"(d[0]), "+r"(d[1]), "+r"(d[2]), "+r"(d[3])
        : "r"(a[0]), "r"(a[1]), "r"(a[2]), "r"(a[3]), "r"(b0), "r"(b1));
}

#define CP_ASYNC16(saddr, gptr) \
    asm volatile("cp.async.cg.shared.global [%0], [%1], 16;" \
        :: "r"(saddr), "l"(gptr) : "memory")
#define CP_COMMIT() asm volatile("cp.async.commit_group;" ::: "memory")
#define CP_WAIT(n) asm volatile("cp.async.wait_group %0;" :: "n"(n) : "memory")

// 64B-row tile: swizzled 16B chunks (4/row).  Works for 32 bf16 or 64 s8 cols.
__device__ __forceinline__ uint32_t tile_addr(uint32_t matbase, int row, int chunk) {
    int swz = chunk ^ (row & 3) ^ ((row >> 2) & 1);
    return matbase + row * 64 + swz * 16;
}
__device__ __forceinline__ uint32_t frag_addr(uint32_t matbase, int baserow,
                                              int kg, int lane) {
    int row = baserow + (lane & 7) + ((lane >> 3) & 1) * 8;
    int chunk = kg * 2 + ((lane >> 4) & 1);
    return tile_addr(matbase, row, chunk);
}

// 128B-row tile (fp16 K-chunk 64): swizzled 16B chunks, 8 per row
__device__ __forceinline__ uint32_t tile2_addr(uint32_t matbase, int row, int chunk) {
    int swz = chunk ^ (row & 7);
    return matbase + row * 128 + swz * 16;
}
__device__ __forceinline__ uint32_t frag2_addr(uint32_t matbase, int baserow,
                                               int kg, int lane) {
    int row = baserow + (lane & 7) + ((lane >> 3) & 1) * 8;
    int chunk = kg * 2 + ((lane >> 4) & 1);
    return tile2_addr(matbase, row, chunk);
}

#define MAT_BYTES 8192

// ---------------------------------------------------------------------------
// bf16x3 HMMA GEMM (projections).  C = tanh((Ahi+Alo) @ (Bhi+Blo)^T) -> s8 pair
// Block 128x128, 8 warps (4m x 2n), K-chunk 32, 3-stage cp.async, 2 CTAs/SM.
// zsplit: blocks with z >= zsplit use operand/output set 2 (merged launch).
// ---------------------------------------------------------------------------
#define STAGE4 32768  /* 4 matrices x 8 KB */

__global__ __launch_bounds__(256, 2) void mm_proj(
    const bf16* __restrict__ Ahi, const bf16* __restrict__ Alo,
    const bf16* __restrict__ Bhi, const bf16* __restrict__ Blo,
    const bf16* __restrict__ A2hi, const bf16* __restrict__ A2lo,
    const bf16* __restrict__ B2hi, const bf16* __restrict__ B2lo,
    int ldk, int nch, int zsplit, int ldc,
    int8_t* __restrict__ Ca, int8_t* __restrict__ Cb,
    int8_t* __restrict__ C2a, int8_t* __restrict__ C2b)
{
    extern __shared__ char smem[];
    const uint32_t sb = smem_to_u32(smem);
    const int tid = threadIdx.x;
    const int lane = tid & 31;
    const int wid = tid >> 5;
    const int warp_m = wid & 3;
    const int warp_n = wid >> 2;

    int bz = blockIdx.z;
    const bf16 *pAh = Ahi, *pAl = Alo, *pBh = Bhi, *pBl = Blo;
    int8_t *pCa = Ca, *pCb = Cb;
    if (zsplit > 0 && bz >= zsplit) {
        bz -= zsplit;
        pAh = A2hi; pAl = A2lo; pBh = B2hi; pBl = B2lo;
        pCa = C2a; pCb = C2b;
    }

    const bf16* mats[4];
    mats[0] = pAh + (long)blockIdx.y * 128 * ldk;
    mats[1] = pAl + (long)blockIdx.y * 128 * ldk;
    mats[2] = pBh + (long)blockIdx.x * 128 * ldk;
    mats[3] = pBl + (long)blockIdx.x * 128 * ldk;

    const int r0a = tid >> 2, c0a = tid & 3;
    const int r0b = (tid + 256) >> 2;

    auto load_chunk = [&](int slot, int k) {
        const uint32_t base = sb + slot * STAGE4;
        const long koff = (long)k * 32;
#pragma unroll
        for (int mat = 0; mat < 4; ++mat) {
            const bf16* g = mats[mat] + koff;
            const uint32_t mb = base + mat * MAT_BYTES;
            CP_ASYNC16(tile_addr(mb, r0a, c0a), g + (long)r0a * ldk + c0a * 8);
            CP_ASYNC16(tile_addr(mb, r0b, c0a), g + (long)r0b * ldk + c0a * 8);
        }
        CP_COMMIT();
    };

    float acc[2][8][4];
#pragma unroll
    for (int i = 0; i < 2; ++i)
#pragma unroll
        for (int j = 0; j < 8; ++j)
#pragma unroll
            for (int q = 0; q < 4; ++q) acc[i][j][q] = 0.0f;

    load_chunk(0, 0);
    load_chunk(1, 1);

#pragma unroll 1
    for (int k = 0; k < nch; ++k) {
        CP_WAIT(1);
        __syncthreads();
        if (k + 2 < nch) load_chunk((k + 2) % 3, k + 2);

        const uint32_t base = sb + (k % 3) * STAGE4;
        const uint32_t sAh = base, sAl = base + MAT_BYTES;
        const uint32_t sBh = base + 2 * MAT_BYTES, sBl = base + 3 * MAT_BYTES;

#pragma unroll
        for (int kg = 0; kg < 2; ++kg) {
            uint32_t ah[2][4], al[2][4], bh[4][4], bl[4][4];
#pragma unroll
            for (int mt = 0; mt < 2; ++mt) {
                ldsm4(ah[mt], frag_addr(sAh, warp_m * 32 + mt * 16, kg, lane));
                ldsm4(al[mt], frag_addr(sAl, warp_m * 32 + mt * 16, kg, lane));
            }
#pragma unroll
            for (int ng = 0; ng < 4; ++ng) {
                ldsm4(bh[ng], frag_addr(sBh, warp_n * 64 + ng * 16, kg, lane));
                ldsm4(bl[ng], frag_addr(sBl, warp_n * 64 + ng * 16, kg, lane));
            }
#pragma unroll
            for (int term = 0; term < 3; ++term)
#pragma unroll
                for (int mt = 0; mt < 2; ++mt)
#pragma unroll
                    for (int ng = 0; ng < 4; ++ng)
#pragma unroll
                        for (int h = 0; h < 2; ++h) {
                            float* d = acc[mt][ng * 2 + h];
                            const uint32_t* a = (term == 2) ? al[mt] : ah[mt];
                            const uint32_t* b = (term == 1) ? bl[ng] : bh[ng];
                            mma16816_bf(d, a, b[h], b[h + 2]);
                        }
        }
    }
    __syncthreads();

    // epilogue: tanh, then s8 pair quantization  v ~ a/127 + b/127^2
    const int rbase = blockIdx.y * 128 + warp_m * 32 + (lane >> 2);
    const int cbase = blockIdx.x * 128 + warp_n * 64 + (lane & 3) * 2;
#pragma unroll
    for (int mt = 0; mt < 2; ++mt)
#pragma unroll
        for (int nt = 0; nt < 8; ++nt)
#pragma unroll
            for (int half = 0; half < 2; ++half) {
                const long r = rbase + mt * 16 + half * 8;
                const long c = cbase + nt * 8;
                float v0 = fast_tanh(acc[mt][nt][half * 2 + 0]);
                float v1 = fast_tanh(acc[mt][nt][half * 2 + 1]);
                int a0 = __float2int_rn(v0 * 127.0f);
                int a1 = __float2int_rn(v1 * 127.0f);
                int b0 = __float2int_rn((v0 - a0 * (1.0f / 127.0f)) * 16129.0f);
                int b1 = __float2int_rn((v1 - a1 * (1.0f / 127.0f)) * 16129.0f);
                uint16_t pa = (uint16_t)((uint8_t)a0 | ((uint16_t)(uint8_t)a1 << 8));
                uint16_t pb = (uint16_t)((uint8_t)b0 | ((uint16_t)(uint8_t)b1 << 8));
                *(uint16_t*)(pCa + r * ldc + c) = pa;
                *(uint16_t*)(pCb + r * ldc + c) = pb;
            }
}

// ---------------------------------------------------------------------------
// int8-pair IMMA score GEMM: S = (La+Lb/127)/127 . (Ra+Rb/127)^T/127
// Block tile 128(l) x 64(r), 8 warps (4m x 2n), K-chunk 64 s8, 12 iters.
// Dual s32 accumulators:  acc1 = a.a',  acc2 = a.b' + b.a'
// S = acc1/127^2 + acc2/127^3.  3-stage cp.async, 2 CTAs/SM.
// ---------------------------------------------------------------------------
#define STAGE_SC 24576  /* Aa 8K + Ab 8K + Ba 4K + Bb 4K */

__global__ __launch_bounds__(256, 2) void mm_s8_scores(
    const int8_t* __restrict__ La, const int8_t* __restrict__ Lb,
    const int8_t* __restrict__ Ra, const int8_t* __restrict__ Rb,
    float* __restrict__ S)
{
    extern __shared__ char smem[];
    const uint32_t sb = smem_to_u32(smem);
    const int tid = threadIdx.x;
    const int lane = tid & 31;
    const int wid = tid >> 5;
    const int warp_m = wid & 3;   // 4 x 32 l-rows
    const int warp_n = wid >> 2;  // 2 x 32 r-cols
    const int bz = blockIdx.z;

    const int8_t* Aa = La + (long)bz * LL * DD + (long)blockIdx.y * 128 * DD;
    const int8_t* Ab = Lb + (long)bz * LL * DD + (long)blockIdx.y * 128 * DD;
    const int8_t* Ba = Ra + (long)bz * LL * DD + (long)blockIdx.x * 64 * DD;
    const int8_t* Bb = Rb + (long)bz * LL * DD + (long)blockIdx.x * 64 * DD;

    const int r0 = tid >> 2, c0 = tid & 3;          // A: rows 0..63 + 64..127
    const int r1 = (tid + 256) >> 2;

    auto load_chunk = [&](int slot, int k) {
        const uint32_t base = sb + slot * STAGE_SC;
        const long koff = (long)k * 64;
        CP_ASYNC16(tile_addr(base, r0, c0), Aa + (long)r0 * DD + koff + c0 * 16);
        CP_ASYNC16(tile_addr(base, r1, c0), Aa + (long)r1 * DD + koff + c0 * 16);
        CP_ASYNC16(tile_addr(base + 8192, r0, c0), Ab + (long)r0 * DD + koff + c0 * 16);
        CP_ASYNC16(tile_addr(base + 8192, r1, c0), Ab + (long)r1 * DD + koff + c0 * 16);
        CP_ASYNC16(tile_addr(base + 16384, r0, c0), Ba + (long)r0 * DD + koff + c0 * 16);
        CP_ASYNC16(tile_addr(base + 20480, r0, c0), Bb + (long)r0 * DD + koff + c0 * 16);
        CP_COMMIT();
    };

    int acc1[2][4][4], acc2[2][4][4];
#pragma unroll
    for (int i = 0; i < 2; ++i)
#pragma unroll
        for (int j = 0; j < 4; ++j)
#pragma unroll
            for (int q = 0; q < 4; ++q) { acc1[i][j][q] = 0; acc2[i][j][q] = 0; }

    load_chunk(0, 0);
    load_chunk(1, 1);

#pragma unroll 1
    for (int k = 0; k < 12; ++k) {   // 12 chunks of K=64 -> 768
        CP_WAIT(1);
        __syncthreads();
        if (k + 2 < 12) load_chunk((k + 2) % 3, k + 2);

        const uint32_t base = sb + (k % 3) * STAGE_SC;
        const uint32_t sAa = base, sAb = base + 8192;
        const uint32_t sBa = base + 16384, sBb = base + 20480;

#pragma unroll
        for (int kg = 0; kg < 2; ++kg) {
            uint32_t aa[2][4], ab[2][4], ba[2][4], bb[2][4];
#pragma unroll
            for (int mt = 0; mt < 2; ++mt) {
                ldsm4(aa[mt], frag_addr(sAa, warp_m * 32 + mt * 16, kg, lane));
                ldsm4(ab[mt], frag_addr(sAb, warp_m * 32 + mt * 16, kg, lane));
            }
#pragma unroll
            for (int ng = 0; ng < 2; ++ng) {
                ldsm4(ba[ng], frag_addr(sBa, warp_n * 32 + ng * 16, kg, lane));
                ldsm4(bb[ng], frag_addr(sBb, warp_n * 32 + ng * 16, kg, lane));
            }
            // term-outermost for latency hiding
#pragma unroll
            for (int mt = 0; mt < 2; ++mt)
#pragma unroll
                for (int ng = 0; ng < 2; ++ng)
#pragma unroll
                    for (int h = 0; h < 2; ++h)
                        imma16832(acc1[mt][ng * 2 + h], aa[mt],
                                  ba[ng][h], ba[ng][h + 2]);
#pragma unroll
            for (int mt = 0; mt < 2; ++mt)
#pragma unroll
                for (int ng = 0; ng < 2; ++ng)
#pragma unroll
                    for (int h = 0; h < 2; ++h)
                        imma16832(acc2[mt][ng * 2 + h], aa[mt],
                                  bb[ng][h], bb[ng][h + 2]);
#pragma unroll
            for (int mt = 0; mt < 2; ++mt)
#pragma unroll
                for (int ng = 0; ng < 2; ++ng)
#pragma unroll
                    for (int h = 0; h < 2; ++h)
                        imma16832(acc2[mt][ng * 2 + h], ab[mt],
                                  ba[ng][h], ba[ng][h + 2]);
        }
    }

    // epilogue: S = acc1/127^2 + acc2/127^3
    const float i2 = 1.0f / 16129.0f;
    const float i3 = 1.0f / 2048383.0f;
    const int rbase = blockIdx.y * 128 + warp_m * 32 + (lane >> 2);
    const int cbase = blockIdx.x * 64 + warp_n * 32 + (lane & 3) * 2;
    float* Sp = S + (long)bz * LL * LL;
#pragma unroll
    for (int mt = 0; mt < 2; ++mt)
#pragma unroll
        for (int nt = 0; nt < 4; ++nt) {
            const long r = rbase + mt * 16;
            const long c = cbase + nt * 8;
            float f0 = (float)acc1[mt][nt][0] * i2 + (float)acc2[mt][nt][0] * i3;
            float f1 = (float)acc1[mt][nt][1] * i2 + (float)acc2[mt][nt][1] * i3;
            float f2 = (float)acc1[mt][nt][2] * i2 + (float)acc2[mt][nt][2] * i3;
            float f3 = (float)acc1[mt][nt][3] * i2 + (float)acc2[mt][nt][3] * i3;
            *(float2*)(Sp + r * LL + c) = make_float2(f0, f1);
            *(float2*)(Sp + (r + 8) * LL + c) = make_float2(f2, f3);
        }
}

// ---------------------------------------------------------------------------
// fp16 single-V apply GEMM (both dirs merged): out = P @ V^T
// P: M x K fp16, V: N x K fp16.  K-chunk 64 (128B rows), 3 stages, 2 CTAs/SM.
// ---------------------------------------------------------------------------
#define MAT2_BYTES 16384
#define STAGEA 32768  /* 2 matrices x 16 KB */

__global__ __launch_bounds__(256, 2) void mm_f16_apply(
    const __half* __restrict__ P1, const __half* __restrict__ V1,
    float* __restrict__ out1,
    const __half* __restrict__ P2, const __half* __restrict__ V2,
    float* __restrict__ out2)
{
    extern __shared__ char smem[];
    const uint32_t sb = smem_to_u32(smem);
    const int tid = threadIdx.x;
    const int lane = tid & 31;
    const int wid = tid >> 5;
    const int warp_m = wid & 3;
    const int warp_n = wid >> 2;

    const int bz = blockIdx.z & 7;
    const int dir = blockIdx.z >> 3;
    const __half* P = dir ? P2 : P1;
    const __half* V = dir ? V2 : V1;
    float* out = dir ? out2 : out1;

    const __half* mats[2];
    mats[0] = P + (long)bz * LL * LL + (long)blockIdx.y * 128 * LL;
    mats[1] = V + (long)bz * DD * LL + (long)blockIdx.x * 128 * LL;

    const int rr0 = tid >> 3, cc0 = tid & 7;

    auto load_chunk = [&](int slot, int k) {
        const uint32_t base = sb + slot * STAGEA;
        const long koff = (long)k * 64;
#pragma unroll
        for (int mat = 0; mat < 2; ++mat) {
            const __half* g = mats[mat] + koff;
            const uint32_t mb = base + mat * MAT2_BYTES;
#pragma unroll
            for (int i = 0; i < 4; ++i) {
                const int row = rr0 + i * 32;
                CP_ASYNC16(tile2_addr(mb, row, cc0), g + (long)row * LL + cc0 * 8);
            }
        }
        CP_COMMIT();
    };

    float acc[2][8][4];
#pragma unroll
    for (int i = 0; i < 2; ++i)
#pragma unroll
        for (int j = 0; j < 8; ++j)
#pragma unroll
            for (int q = 0; q < 4; ++q) acc[i][j][q] = 0.0f;

    load_chunk(0, 0);
    load_chunk(1, 1);

#pragma unroll 1
    for (int k = 0; k < 16; ++k) {
        CP_WAIT(1);
        __syncthreads();
        if (k + 2 < 16) load_chunk((k + 2) % 3, k + 2);

        const uint32_t base = sb + (k % 3) * STAGEA;
        const uint32_t sP = base;
        const uint32_t sV = base + MAT2_BYTES;

#pragma unroll
        for (int kg = 0; kg < 4; ++kg) {
            uint32_t a[2][4], b[4][4];
#pragma unroll
            for (int mt = 0; mt < 2; ++mt)
                ldsm4(a[mt], frag2_addr(sP, warp_m * 32 + mt * 16, kg, lane));
#pragma unroll
            for (int ng = 0; ng < 4; ++ng)
                ldsm4(b[ng], frag2_addr(sV, warp_n * 64 + ng * 16, kg, lane));
#pragma unroll
            for (int mt = 0; mt < 2; ++mt)
#pragma unroll
                for (int ng = 0; ng < 4; ++ng)
#pragma unroll
                    for (int h = 0; h < 2; ++h)
                        mma16816_f16(acc[mt][ng * 2 + h], a[mt],
                                     b[ng][h], b[ng][h + 2]);
        }
    }
    __syncthreads();

    const int rbase = blockIdx.y * 128 + warp_m * 32 + (lane >> 2);
    const int cbase = blockIdx.x * 128 + warp_n * 64 + (lane & 3) * 2;
    float* Ob = out + (long)bz * LL * 1536 + DD;
#pragma unroll
    for (int mt = 0; mt < 2; ++mt)
#pragma unroll
        for (int nt = 0; nt < 8; ++nt) {
            const long r = rbase + mt * 16;
            const long c = cbase + nt * 8;
            float* Cp = Ob + r * 1536 + c;
            *(float2*)Cp = make_float2(acc[mt][nt][0], acc[mt][nt][1]);
            *(float2*)(Cp + 8L * 1536) = make_float2(acc[mt][nt][2], acc[mt][nt][3]);
        }
}

// ---------------------------------------------------------------------------
// split + transpose + passthrough
// ---------------------------------------------------------------------------
__global__ void split_tr(const float* __restrict__ X,
                         bf16* __restrict__ Xhi, bf16* __restrict__ Xlo,
                         __half* __restrict__ XTh,
                         float* __restrict__ outbase)
{
    const int b = blockIdx.z;
    const int d0 = blockIdx.x * 32, l0 = blockIdx.y * 32;
    const int tx = threadIdx.x, ty = threadIdx.y;
    __shared__ __half thi[32][33];

#pragma unroll
    for (int i = 0; i < 4; ++i) {
        const int ll = ty + 8 * i;
        const size_t idx = (size_t)b * LL * DD + (size_t)(l0 + ll) * DD + d0 + tx;
        const float x = X[idx];
        const bf16 h = __float2bfloat16(x);
        Xhi[idx] = h;
        Xlo[idx] = __float2bfloat16(x - __bfloat162float(h));
        thi[ll][tx] = __float2half(x);
        outbase[(size_t)(b * LL + l0 + ll) * 1536 + d0 + tx] = x;
    }
    __syncthreads();
#pragma unroll
    for (int i = 0; i < 4; ++i) {
        const int dd = ty + 8 * i;
        XTh[(size_t)b * DD * LL + (size_t)(d0 + dd) * LL + l0 + tx] = thi[tx][dd];
    }
}

__global__ void split_w(const float* __restrict__ Wl, const float* __restrict__ Wr,
                        bf16* __restrict__ Wlh, bf16* __restrict__ Wll,
                        bf16* __restrict__ Wrh, bf16* __restrict__ Wrl)
{
    const int i = blockIdx.x * blockDim.x + threadIdx.x;
    if (i < DD * DD) {
        float x = Wl[i];
        bf16 h = __float2bfloat16(x);
        Wlh[i] = h; Wll[i] = __float2bfloat16(x - __bfloat162float(h));
        x = Wr[i];
        h = __float2bfloat16(x);
        Wrh[i] = h; Wrl[i] = __float2bfloat16(x - __bfloat162float(h));
    }
}

// ---------------------------------------------------------------------------
// softmax stats
// ---------------------------------------------------------------------------
__global__ void row_stats(const float* __restrict__ S, float* __restrict__ rowc)
{
    const int row = blockIdx.x;
    const float* Sp = S + (size_t)row * LL;
    const int t = threadIdx.x;
    float v[4];
    float m = -1e30f;
#pragma unroll
    for (int i = 0; i < 4; ++i) { v[i] = Sp[t + i * 256]; m = fmaxf(m, v[i]); }
    __shared__ float red[256];
    red[t] = m; __syncthreads();
    for (int s = 128; s > 0; s >>= 1) {
        if (t < s) red[t] = fmaxf(red[t], red[t + s]);
        __syncthreads();
    }
    const float M = red[0];
    __syncthreads();
    float sum = 0.0f;
#pragma unroll
    for (int i = 0; i < 4; ++i) sum += __expf(v[i] - M);
    red[t] = sum; __syncthreads();
    for (int s = 128; s > 0; s >>= 1) {
        if (t < s) red[t] += red[t + s];
        __syncthreads();
    }
    if (t == 0) rowc[row] = M + __logf(red[0]);
}

__global__ void col_stats(const float* __restrict__ S, float* __restrict__ colc)
{
    const int b = blockIdx.y;
    const int tx = threadIdx.x, ty = threadIdx.y;
    const int c = blockIdx.x * 32 + tx;
    const float* Sp = S + (size_t)b * LL * LL + c;

    float m = -1e30f, s = 0.0f;
    for (int l = ty * 128; l < (ty + 1) * 128; ++l) {
        const float x = Sp[(size_t)l * LL] * INV_SCALE;
        if (x > m) { s = s * __expf(m - x) + 1.0f; m = x; }
        else s += __expf(x - m);
    }
    __shared__ float redm[8][32], reds[8][32];
    redm[ty][tx] = m; reds[ty][tx] = s;
    __syncthreads();
    if (ty == 0) {
        float M = redm[0][tx];
#pragma unroll
        for (int i = 1; i < 8; ++i) M = fmaxf(M, redm[i][tx]);
        float ss = 0.0f;
#pragma unroll
        for (int i = 0; i < 8; ++i) ss += reds[i][tx] * __expf(redm[i][tx] - M);
        colc[b * LL + c] = M + __logf(ss);
    }
}

// normalize into P1 fp16 [l][r] and P2T fp16 [r][l]
__global__ void transform(const float* __restrict__ S,
                          const float* __restrict__ rowc,
                          const float* __restrict__ colc,
                          __half* __restrict__ P1, __half* __restrict__ P2T)
{
    const int n = blockIdx.z;
    const size_t base = (size_t)n * LL * LL;
    const int l0 = blockIdx.y * 32, r0 = blockIdx.x * 32;
    const int tx = threadIdx.x, ty = threadIdx.y;
    __shared__ float tile[32][33];
    const float cc = colc[n * LL + r0 + tx];

#pragma unroll
    for (int i = 0; i < 4; ++i) {
        const int ll = ty + 8 * i;
        const size_t idx = base + (size_t)(l0 + ll) * LL + r0 + tx;
        const float s = S[idx];
        P1[idx] = __float2half(__expf(s - rowc[n * LL + l0 + ll]));
        tile[ll][tx] = s * INV_SCALE - cc;
    }
    __syncthreads();
#pragma unroll
    for (int i = 0; i < 4; ++i) {
        const int rr = ty + 8 * i;
        P2T[base + (size_t)(r0 + rr) * LL + l0 + tx] = __float2half(__expf(tile[tx][rr]));
    }
}

// ---------------------------------------------------------------------------
// launch
// ---------------------------------------------------------------------------
extern "C" void kernel_launch(void* const* d_in, const int* in_sizes, int n_in,
                              void* d_out, int out_size)
{
    const float* lhs = (const float*)d_in[0];
    const float* rhs = (const float*)d_in[1];
    const float* Wl  = (const float*)d_in[2];
    const float* Wr  = (const float*)d_in[3];
    float* out = (float*)d_out;

    bf16 *p_lhs_h, *p_lhs_l, *p_rhs_h, *p_rhs_l;
    __half *p_lhsT_h, *p_rhsT_h;
    bf16 *p_Wl_h, *p_Wl_l, *p_Wr_h, *p_Wr_l;
    int8_t *p_La, *p_Lb, *p_Ra, *p_Rb;
    __half *p_P1, *p_P2T;
    float *pS, *prc, *pcc;
    cudaGetSymbolAddress((void**)&p_lhs_h, s_lhs_hi);
    cudaGetSymbolAddress((void**)&p_lhs_l, s_lhs_lo);
    cudaGetSymbolAddress((void**)&p_rhs_h, s_rhs_hi);
    cudaGetSymbolAddress((void**)&p_rhs_l, s_rhs_lo);
    cudaGetSymbolAddress((void**)&p_lhsT_h, s_lhsT_h);
    cudaGetSymbolAddress((void**)&p_rhsT_h, s_rhsT_h);
    cudaGetSymbolAddress((void**)&p_Wl_h, s_Wl_hi);
    cudaGetSymbolAddress((void**)&p_Wl_l, s_Wl_lo);
    cudaGetSymbolAddress((void**)&p_Wr_h, s_Wr_hi);
    cudaGetSymbolAddress((void**)&p_Wr_l, s_Wr_lo);
    cudaGetSymbolAddress((void**)&p_La, g_La);
    cudaGetSymbolAddress((void**)&p_Lb, g_Lb);
    cudaGetSymbolAddress((void**)&p_Ra, g_Ra);
    cudaGetSymbolAddress((void**)&p_Rb, g_Rb);
    cudaGetSymbolAddress((void**)&p_P1, g_P1);
    cudaGetSymbolAddress((void**)&p_P2T, g_P2T);
    cudaGetSymbolAddress((void**)&pS, g_S);
    cudaGetSymbolAddress((void**)&prc, g_rowc);
    cudaGetSymbolAddress((void**)&pcc, g_colc);

    const int SMEM4 = 3 * STAGE4;    // 96 KB
    const int SMEMS = 3 * STAGE_SC;  // 72 KB
    const int SMEMA = 3 * STAGEA;    // 96 KB
    cudaFuncSetAttribute(mm_proj, cudaFuncAttributeMaxDynamicSharedMemorySize, SMEM4);
    cudaFuncSetAttribute(mm_s8_scores, cudaFuncAttributeMaxDynamicSharedMemorySize, SMEMS);
    cudaFuncSetAttribute(mm_f16_apply, cudaFuncAttributeMaxDynamicSharedMemorySize, SMEMA);

    // 1. operand prep: split + transpose + passthrough copy
    split_tr<<<dim3(DD / 32, LL / 32, BB), dim3(32, 8)>>>(
        lhs, p_lhs_h, p_lhs_l, p_lhsT_h, out);
    split_tr<<<dim3(DD / 32, LL / 32, BB), dim3(32, 8)>>>(
        rhs, p_rhs_h, p_rhs_l, p_rhsT_h, out + (size_t)BB * LL * 1536);
    split_w<<<(DD * DD + 255) / 256, 256>>>(Wl, Wr, p_Wl_h, p_Wl_l, p_Wr_h, p_Wr_l);

    // 2. both projections in ONE launch (z=0: lhs@Wl, z=1: rhs@Wr) -> s8 pairs
    mm_proj<<<dim3(DD / 128, (BB * LL) / 128, 2), 256, SMEM4>>>(
        p_lhs_h, p_lhs_l, p_Wl_h, p_Wl_l,
        p_rhs_h, p_rhs_l, p_Wr_h, p_Wr_l,
        DD, DD / 32, 1, DD,
        p_La, p_Lb, p_Ra, p_Rb);

    // 3. scores via int8-pair IMMA
    mm_s8_scores<<<dim3(LL / 64, LL / 128, BB), 256, SMEMS>>>(
        p_La, p_Lb, p_Ra, p_Rb, pS);

    // 4. softmax stats + normalized fp16 probabilities
    row_stats<<<BB * LL, 256>>>(pS, prc);
    col_stats<<<dim3(LL / 32, BB), dim3(32, 8)>>>(pS, pcc);
    transform<<<dim3(LL / 32, LL / 32, BB), dim3(32, 8)>>>(pS, prc, pcc, p_P1, p_P2T);

    // 5. both applies in ONE launch (z<8: dir 0, z>=8: dir 1), V fp16 single
    mm_f16_apply<<<dim3(DD / 128, LL / 128, 2 * BB), 256, SMEMA>>>(
        p_P1, p_rhsT_h, out,
        p_P2T, p_lhsT_h, out + (size_t)BB * LL * 1536);
}

// round 9
// speedup vs baseline: 1.3678x; 1.3678x over previous
#include <cuda_runtime.h>
#include <cuda_bf16.h>
#include <cuda_fp16.h>
#include <cstdint>
#include <math.h>

#define BB 8
#define LL 1024
#define DD 768
#define INV_SCALE 0.03608439182435161f  /* 1/sqrt(768) */

typedef __nv_bfloat16 bf16;

// ---------------------------------------------------------------------------
// scratch (device globals; no allocation)
// ---------------------------------------------------------------------------
__device__ bf16 s_lhs_hi[BB * LL * DD], s_lhs_lo[BB * LL * DD];   // proj A
__device__ bf16 s_rhs_hi[BB * LL * DD], s_rhs_lo[BB * LL * DD];
__device__ __half s_lhsT_h[BB * DD * LL];   // apply B (fp16, single)
__device__ __half s_rhsT_h[BB * DD * LL];
__device__ bf16 s_Wl_hi[DD * DD], s_Wl_lo[DD * DD];
__device__ bf16 s_Wr_hi[DD * DD], s_Wr_lo[DD * DD];
__device__ bf16 g_L_hi[BB * LL * DD], g_L_lo[BB * LL * DD];
__device__ bf16 g_R_hi[BB * LL * DD], g_R_lo[BB * LL * DD];
__device__ __half g_P1[BB * LL * LL];    // row-softmax probs fp16 [l][r]
__device__ __half g_P2T[BB * LL * LL];   // col-softmax probs fp16, transposed [r][l]
__device__ float g_S[BB * LL * LL];
__device__ float g_rowc[BB * LL];
__device__ float g_colc[BB * LL];

__device__ __forceinline__ float fast_tanh(float x) {
    return 1.0f - __fdividef(2.0f, __expf(2.0f * x) + 1.0f);
}

__device__ __forceinline__ uint32_t smem_to_u32(const void* p) {
    uint32_t a;
    asm("{ .reg .u64 t; cvta.to.shared.u64 t, %1; cvt.u32.u64 %0, t; }"
        : "=r"(a) : "l"(p));
    return a;
}

// ---------------------------------------------------------------------------
// MMA helpers
// ---------------------------------------------------------------------------
__device__ __forceinline__ void ldsm4(uint32_t* r, uint32_t addr) {
    asm volatile("ldmatrix.sync.aligned.m8n8.x4.shared.b16 {%0,%1,%2,%3}, [%4];"
                 : "=r"(r[0]), "=r"(r[1]), "=r"(r[2]), "=r"(r[3]) : "r"(addr));
}

__device__ __forceinline__ void mma16816_bf(float* d, const uint32_t* a,
                                            uint32_t b0, uint32_t b1) {
    asm volatile(
        "mma.sync.aligned.m16n8k16.row.col.f32.bf16.bf16.f32 "
        "{%0,%1,%2,%3}, {%4,%5,%6,%7}, {%8,%9}, {%0,%1,%2,%3};"
        : "+f"(d[0]), "+f"(d[1]), "+f"(d[2]), "+f"(d[3])
        : "r"(a[0]), "r"(a[1]), "r"(a[2]), "r"(a[3]), "r"(b0), "r"(b1));
}

__device__ __forceinline__ void mma16816_f16(float* d, const uint32_t* a,
                                             uint32_t b0, uint32_t b1) {
    asm volatile(
        "mma.sync.aligned.m16n8k16.row.col.f32.f16.f16.f32 "
        "{%0,%1,%2,%3}, {%4,%5,%6,%7}, {%8,%9}, {%0,%1,%2,%3};"
        : "+f"(d[0]), "+f"(d[1]), "+f"(d[2]), "+f"(d[3])
        : "r"(a[0]), "r"(a[1]), "r"(a[2]), "r"(a[3]), "r"(b0), "r"(b1));
}

#define CP_ASYNC16(saddr, gptr) \
    asm volatile("cp.async.cg.shared.global [%0], [%1], 16;" \
        :: "r"(saddr), "l"(gptr) : "memory")
#define CP_COMMIT() asm volatile("cp.async.commit_group;" ::: "memory")
#define CP_WAIT(n) asm volatile("cp.async.wait_group %0;" :: "n"(n) : "memory")

// 64B-row tile (K-chunk 32 bf16): swizzled 16B chunks (4/row)
__device__ __forceinline__ uint32_t tile_addr(uint32_t matbase, int row, int chunk) {
    int swz = chunk ^ (row & 3) ^ ((row >> 2) & 1);
    return matbase + row * 64 + swz * 16;
}
__device__ __forceinline__ uint32_t frag_addr(uint32_t matbase, int baserow,
                                              int kg, int lane) {
    int row = baserow + (lane & 7) + ((lane >> 3) & 1) * 8;
    int chunk = kg * 2 + ((lane >> 4) & 1);
    return tile_addr(matbase, row, chunk);
}

// 128B-row tile (fp16 K-chunk 64): swizzled 16B chunks, 8 per row
__device__ __forceinline__ uint32_t tile2_addr(uint32_t matbase, int row, int chunk) {
    int swz = chunk ^ (row & 7);
    return matbase + row * 128 + swz * 16;
}
__device__ __forceinline__ uint32_t frag2_addr(uint32_t matbase, int baserow,
                                               int kg, int lane) {
    int row = baserow + (lane & 7) + ((lane >> 3) & 1) * 8;
    int chunk = kg * 2 + ((lane >> 4) & 1);
    return tile2_addr(matbase, row, chunk);
}

// ---------------------------------------------------------------------------
// bf16x3 HMMA GEMM (proj + scores).  C = act((Ahi+Alo) @ (Bhi+Blo)^T)
// Block 64(m) x 128(n), 8 warps (2m x 4n), warp tile 32x32.
// K-chunk 32, 3-stage cp.async, 2 CTAs/SM, FRAGMENT DOUBLE-BUFFERING.
// smem stage: Ah 4K | Al 4K | Bh 8K | Bl 8K = 24 KB.
// ---------------------------------------------------------------------------
#define STAGE_B3 24576

template <int EPI>
__global__ __launch_bounds__(256, 2) void mm_bf16x3(
    const bf16* __restrict__ Ahi, const bf16* __restrict__ Alo,
    const bf16* __restrict__ Bhi, const bf16* __restrict__ Blo,
    const bf16* __restrict__ A2hi, const bf16* __restrict__ A2lo,
    const bf16* __restrict__ B2hi, const bf16* __restrict__ B2lo,
    long sA, long sB, int ldk, int nch, int zsplit,
    float* __restrict__ C, long sC, int ldc,
    bf16* __restrict__ Chi, bf16* __restrict__ Clo,
    bf16* __restrict__ C2hi, bf16* __restrict__ C2lo)
{
    extern __shared__ char smem[];
    const uint32_t sb = smem_to_u32(smem);
    const int tid = threadIdx.x;
    const int lane = tid & 31;
    const int wid = tid >> 5;
    const int warp_m = wid & 1;    // 2 x 32 rows
    const int warp_n = wid >> 1;   // 4 x 32 cols

    int bz = blockIdx.z;
    const bf16 *pAh = Ahi, *pAl = Alo, *pBh = Bhi, *pBl = Blo;
    bf16 *pCh = Chi, *pCl = Clo;
    if (zsplit > 0 && bz >= zsplit) {
        bz -= zsplit;
        pAh = A2hi; pAl = A2lo; pBh = B2hi; pBl = B2lo;
        pCh = C2hi; pCl = C2lo;
    }

    const bf16* Am[2];
    const bf16* Bm[2];
    Am[0] = pAh + (long)bz * sA + (long)blockIdx.y * 64 * ldk;
    Am[1] = pAl + (long)bz * sA + (long)blockIdx.y * 64 * ldk;
    Bm[0] = pBh + (long)bz * sB + (long)blockIdx.x * 128 * ldk;
    Bm[1] = pBl + (long)bz * sB + (long)blockIdx.x * 128 * ldk;

    const int rA = tid >> 2, cA = tid & 3;   // A: 64 rows x 4 chunks = 256 slots

    auto load_chunk = [&](int slot, int k) {
        const uint32_t base = sb + slot * STAGE_B3;
        const long koff = (long)k * 32;
        CP_ASYNC16(tile_addr(base, rA, cA), Am[0] + (long)rA * ldk + koff + cA * 8);
        CP_ASYNC16(tile_addr(base + 4096, rA, cA), Am[1] + (long)rA * ldk + koff + cA * 8);
        CP_ASYNC16(tile_addr(base + 8192, rA, cA), Bm[0] + (long)rA * ldk + koff + cA * 8);
        CP_ASYNC16(tile_addr(base + 8192, rA + 64, cA), Bm[0] + (long)(rA + 64) * ldk + koff + cA * 8);
        CP_ASYNC16(tile_addr(base + 16384, rA, cA), Bm[1] + (long)rA * ldk + koff + cA * 8);
        CP_ASYNC16(tile_addr(base + 16384, rA + 64, cA), Bm[1] + (long)(rA + 64) * ldk + koff + cA * 8);
        CP_COMMIT();
    };

    float acc[2][4][4];
#pragma unroll
    for (int i = 0; i < 2; ++i)
#pragma unroll
        for (int j = 0; j < 4; ++j)
#pragma unroll
            for (int q = 0; q < 4; ++q) acc[i][j][q] = 0.0f;

    load_chunk(0, 0);
    load_chunk(1, 1);

    // fragment double buffers: [buf][tile][4]
    uint32_t fah[2][2][4], fal[2][2][4], fbh[2][2][4], fbl[2][2][4];

#pragma unroll 1
    for (int k = 0; k < nch; ++k) {
        CP_WAIT(1);
        __syncthreads();
        if (k + 2 < nch) load_chunk((k + 2) % 3, k + 2);

        const uint32_t base = sb + (k % 3) * STAGE_B3;
        const uint32_t sAh = base, sAl = base + 4096;
        const uint32_t sBh = base + 8192, sBl = base + 16384;

        // preload kg=0 frags
#pragma unroll
        for (int mt = 0; mt < 2; ++mt) {
            ldsm4(fah[0][mt], frag_addr(sAh, warp_m * 32 + mt * 16, 0, lane));
            ldsm4(fal[0][mt], frag_addr(sAl, warp_m * 32 + mt * 16, 0, lane));
        }
#pragma unroll
        for (int bt = 0; bt < 2; ++bt) {
            ldsm4(fbh[0][bt], frag_addr(sBh, warp_n * 32 + bt * 16, 0, lane));
            ldsm4(fbl[0][bt], frag_addr(sBl, warp_n * 32 + bt * 16, 0, lane));
        }

#pragma unroll
        for (int kg = 0; kg < 2; ++kg) {
            if (kg == 0) {
                // prefetch kg=1 frags while kg=0 MMAs run
#pragma unroll
                for (int mt = 0; mt < 2; ++mt) {
                    ldsm4(fah[1][mt], frag_addr(sAh, warp_m * 32 + mt * 16, 1, lane));
                    ldsm4(fal[1][mt], frag_addr(sAl, warp_m * 32 + mt * 16, 1, lane));
                }
#pragma unroll
                for (int bt = 0; bt < 2; ++bt) {
                    ldsm4(fbh[1][bt], frag_addr(sBh, warp_n * 32 + bt * 16, 1, lane));
                    ldsm4(fbl[1][bt], frag_addr(sBl, warp_n * 32 + bt * 16, 1, lane));
                }
            }
#pragma unroll
            for (int term = 0; term < 3; ++term)
#pragma unroll
                for (int mt = 0; mt < 2; ++mt)
#pragma unroll
                    for (int bt = 0; bt < 2; ++bt)
#pragma unroll
                        for (int h = 0; h < 2; ++h) {
                            float* d = acc[mt][bt * 2 + h];
                            const uint32_t* a = (term == 2) ? fal[kg][mt] : fah[kg][mt];
                            const uint32_t* b = (term == 1) ? fbl[kg][bt] : fbh[kg][bt];
                            mma16816_bf(d, a, b[h], b[h + 2]);
                        }
        }
    }

    const int rbase = blockIdx.y * 64 + warp_m * 32 + (lane >> 2);
    const int cbase = blockIdx.x * 128 + warp_n * 32 + (lane & 3) * 2;

    if (EPI == 0) {
#pragma unroll
        for (int mt = 0; mt < 2; ++mt)
#pragma unroll
            for (int nt = 0; nt < 4; ++nt) {
                const long r = rbase + mt * 16;
                const long c = cbase + nt * 8;
                float* Cp = C + (long)bz * sC + r * ldc + c;
                *(float2*)Cp = make_float2(acc[mt][nt][0], acc[mt][nt][1]);
                *(float2*)(Cp + 8L * ldc) = make_float2(acc[mt][nt][2], acc[mt][nt][3]);
            }
    } else {
#pragma unroll
        for (int mt = 0; mt < 2; ++mt)
#pragma unroll
            for (int nt = 0; nt < 4; ++nt)
#pragma unroll
                for (int half = 0; half < 2; ++half) {
                    const long r = rbase + mt * 16 + half * 8;
                    const long c = cbase + nt * 8;
                    float v0 = fast_tanh(acc[mt][nt][half * 2 + 0]);
                    float v1 = fast_tanh(acc[mt][nt][half * 2 + 1]);
                    bf16 h0 = __float2bfloat16(v0);
                    bf16 h1 = __float2bfloat16(v1);
                    bf16 l0 = __float2bfloat16(v0 - __bfloat162float(h0));
                    bf16 l1 = __float2bfloat16(v1 - __bfloat162float(h1));
                    __nv_bfloat162 hh; hh.x = h0; hh.y = h1;
                    __nv_bfloat162 llv; llv.x = l0; llv.y = l1;
                    *(uint32_t*)(pCh + r * ldc + c) = *(uint32_t*)&hh;
                    *(uint32_t*)(pCl + r * ldc + c) = *(uint32_t*)&llv;
                }
    }
}

// ---------------------------------------------------------------------------
// fp16 single-V apply GEMM (both dirs merged): out = P @ V^T
// Block 128x128, 8 warps (4m x 2n), K-chunk 64, 3 stages, 2 CTAs/SM,
// fragment double-buffering across kg.
// ---------------------------------------------------------------------------
#define MAT2_BYTES 16384
#define STAGEA 32768  /* 2 matrices x 16 KB */

__global__ __launch_bounds__(256, 2) void mm_f16_apply(
    const __half* __restrict__ P1, const __half* __restrict__ V1,
    float* __restrict__ out1,
    const __half* __restrict__ P2, const __half* __restrict__ V2,
    float* __restrict__ out2)
{
    extern __shared__ char smem[];
    const uint32_t sb = smem_to_u32(smem);
    const int tid = threadIdx.x;
    const int lane = tid & 31;
    const int wid = tid >> 5;
    const int warp_m = wid & 3;
    const int warp_n = wid >> 2;

    const int bz = blockIdx.z & 7;
    const int dir = blockIdx.z >> 3;
    const __half* P = dir ? P2 : P1;
    const __half* V = dir ? V2 : V1;
    float* out = dir ? out2 : out1;

    const __half* mats[2];
    mats[0] = P + (long)bz * LL * LL + (long)blockIdx.y * 128 * LL;
    mats[1] = V + (long)bz * DD * LL + (long)blockIdx.x * 128 * LL;

    const int rr0 = tid >> 3, cc0 = tid & 7;

    auto load_chunk = [&](int slot, int k) {
        const uint32_t base = sb + slot * STAGEA;
        const long koff = (long)k * 64;
#pragma unroll
        for (int mat = 0; mat < 2; ++mat) {
            const __half* g = mats[mat] + koff;
            const uint32_t mb = base + mat * MAT2_BYTES;
#pragma unroll
            for (int i = 0; i < 4; ++i) {
                const int row = rr0 + i * 32;
                CP_ASYNC16(tile2_addr(mb, row, cc0), g + (long)row * LL + cc0 * 8);
            }
        }
        CP_COMMIT();
    };

    float acc[2][8][4];
#pragma unroll
    for (int i = 0; i < 2; ++i)
#pragma unroll
        for (int j = 0; j < 8; ++j)
#pragma unroll
            for (int q = 0; q < 4; ++q) acc[i][j][q] = 0.0f;

    load_chunk(0, 0);
    load_chunk(1, 1);

    uint32_t fa[2][2][4], fb[2][4][4];

#pragma unroll 1
    for (int k = 0; k < 16; ++k) {
        CP_WAIT(1);
        __syncthreads();
        if (k + 2 < 16) load_chunk((k + 2) % 3, k + 2);

        const uint32_t base = sb + (k % 3) * STAGEA;
        const uint32_t sP = base;
        const uint32_t sV = base + MAT2_BYTES;

        // preload kg=0
#pragma unroll
        for (int mt = 0; mt < 2; ++mt)
            ldsm4(fa[0][mt], frag2_addr(sP, warp_m * 32 + mt * 16, 0, lane));
#pragma unroll
        for (int ng = 0; ng < 4; ++ng)
            ldsm4(fb[0][ng], frag2_addr(sV, warp_n * 64 + ng * 16, 0, lane));

#pragma unroll
        for (int kg = 0; kg < 4; ++kg) {
            const int cur = kg & 1;
            if (kg < 3) {
                const int nxt = cur ^ 1;
#pragma unroll
                for (int mt = 0; mt < 2; ++mt)
                    ldsm4(fa[nxt][mt], frag2_addr(sP, warp_m * 32 + mt * 16, kg + 1, lane));
#pragma unroll
                for (int ng = 0; ng < 4; ++ng)
                    ldsm4(fb[nxt][ng], frag2_addr(sV, warp_n * 64 + ng * 16, kg + 1, lane));
            }
#pragma unroll
            for (int mt = 0; mt < 2; ++mt)
#pragma unroll
                for (int ng = 0; ng < 4; ++ng)
#pragma unroll
                    for (int h = 0; h < 2; ++h)
                        mma16816_f16(acc[mt][ng * 2 + h], fa[cur][mt],
                                     fb[cur][ng][h], fb[cur][ng][h + 2]);
        }
    }

    const int rbase = blockIdx.y * 128 + warp_m * 32 + (lane >> 2);
    const int cbase = blockIdx.x * 128 + warp_n * 64 + (lane & 3) * 2;
    float* Ob = out + (long)bz * LL * 1536 + DD;
#pragma unroll
    for (int mt = 0; mt < 2; ++mt)
#pragma unroll
        for (int nt = 0; nt < 8; ++nt) {
            const long r = rbase + mt * 16;
            const long c = cbase + nt * 8;
            float* Cp = Ob + r * 1536 + c;
            *(float2*)Cp = make_float2(acc[mt][nt][0], acc[mt][nt][1]);
            *(float2*)(Cp + 8L * 1536) = make_float2(acc[mt][nt][2], acc[mt][nt][3]);
        }
}

// ---------------------------------------------------------------------------
// split + transpose + passthrough
// ---------------------------------------------------------------------------
__global__ void split_tr(const float* __restrict__ X,
                         bf16* __restrict__ Xhi, bf16* __restrict__ Xlo,
                         __half* __restrict__ XTh,
                         float* __restrict__ outbase)
{
    const int b = blockIdx.z;
    const int d0 = blockIdx.x * 32, l0 = blockIdx.y * 32;
    const int tx = threadIdx.x, ty = threadIdx.y;
    __shared__ __half thi[32][33];

#pragma unroll
    for (int i = 0; i < 4; ++i) {
        const int ll = ty + 8 * i;
        const size_t idx = (size_t)b * LL * DD + (size_t)(l0 + ll) * DD + d0 + tx;
        const float x = X[idx];
        const bf16 h = __float2bfloat16(x);
        Xhi[idx] = h;
        Xlo[idx] = __float2bfloat16(x - __bfloat162float(h));
        thi[ll][tx] = __float2half(x);
        outbase[(size_t)(b * LL + l0 + ll) * 1536 + d0 + tx] = x;
    }
    __syncthreads();
#pragma unroll
    for (int i = 0; i < 4; ++i) {
        const int dd = ty + 8 * i;
        XTh[(size_t)b * DD * LL + (size_t)(d0 + dd) * LL + l0 + tx] = thi[tx][dd];
    }
}

__global__ void split_w(const float* __restrict__ Wl, const float* __restrict__ Wr,
                        bf16* __restrict__ Wlh, bf16* __restrict__ Wll,
                        bf16* __restrict__ Wrh, bf16* __restrict__ Wrl)
{
    const int i = blockIdx.x * blockDim.x + threadIdx.x;
    if (i < DD * DD) {
        float x = Wl[i];
        bf16 h = __float2bfloat16(x);
        Wlh[i] = h; Wll[i] = __float2bfloat16(x - __bfloat162float(h));
        x = Wr[i];
        h = __float2bfloat16(x);
        Wrh[i] = h; Wrl[i] = __float2bfloat16(x - __bfloat162float(h));
    }
}

// ---------------------------------------------------------------------------
// softmax stats
// ---------------------------------------------------------------------------
__global__ void row_stats(const float* __restrict__ S, float* __restrict__ rowc)
{
    const int row = blockIdx.x;
    const float* Sp = S + (size_t)row * LL;
    const int t = threadIdx.x;
    float v[4];
    float m = -1e30f;
#pragma unroll
    for (int i = 0; i < 4; ++i) { v[i] = Sp[t + i * 256]; m = fmaxf(m, v[i]); }
    __shared__ float red[256];
    red[t] = m; __syncthreads();
    for (int s = 128; s > 0; s >>= 1) {
        if (t < s) red[t] = fmaxf(red[t], red[t + s]);
        __syncthreads();
    }
    const float M = red[0];
    __syncthreads();
    float sum = 0.0f;
#pragma unroll
    for (int i = 0; i < 4; ++i) sum += __expf(v[i] - M);
    red[t] = sum; __syncthreads();
    for (int s = 128; s > 0; s >>= 1) {
        if (t < s) red[t] += red[t + s];
        __syncthreads();
    }
    if (t == 0) rowc[row] = M + __logf(red[0]);
}

__global__ void col_stats(const float* __restrict__ S, float* __restrict__ colc)
{
    const int b = blockIdx.y;
    const int tx = threadIdx.x, ty = threadIdx.y;
    const int c = blockIdx.x * 32 + tx;
    const float* Sp = S + (size_t)b * LL * LL + c;

    float m = -1e30f, s = 0.0f;
    for (int l = ty * 128; l < (ty + 1) * 128; ++l) {
        const float x = Sp[(size_t)l * LL] * INV_SCALE;
        if (x > m) { s = s * __expf(m - x) + 1.0f; m = x; }
        else s += __expf(x - m);
    }
    __shared__ float redm[8][32], reds[8][32];
    redm[ty][tx] = m; reds[ty][tx] = s;
    __syncthreads();
    if (ty == 0) {
        float M = redm[0][tx];
#pragma unroll
        for (int i = 1; i < 8; ++i) M = fmaxf(M, redm[i][tx]);
        float ss = 0.0f;
#pragma unroll
        for (int i = 0; i < 8; ++i) ss += reds[i][tx] * __expf(redm[i][tx] - M);
        colc[b * LL + c] = M + __logf(ss);
    }
}

// normalize into P1 fp16 [l][r] and P2T fp16 [r][l]
__global__ void transform(const float* __restrict__ S,
                          const float* __restrict__ rowc,
                          const float* __restrict__ colc,
                          __half* __restrict__ P1, __half* __restrict__ P2T)
{
    const int n = blockIdx.z;
    const size_t base = (size_t)n * LL * LL;
    const int l0 = blockIdx.y * 32, r0 = blockIdx.x * 32;
    const int tx = threadIdx.x, ty = threadIdx.y;
    __shared__ float tile[32][33];
    const float cc = colc[n * LL + r0 + tx];

#pragma unroll
    for (int i = 0; i < 4; ++i) {
        const int ll = ty + 8 * i;
        const size_t idx = base + (size_t)(l0 + ll) * LL + r0 + tx;
        const float s = S[idx];
        P1[idx] = __float2half(__expf(s - rowc[n * LL + l0 + ll]));
        tile[ll][tx] = s * INV_SCALE - cc;
    }
    __syncthreads();
#pragma unroll
    for (int i = 0; i < 4; ++i) {
        const int rr = ty + 8 * i;
        P2T[base + (size_t)(r0 + rr) * LL + l0 + tx] = __float2half(__expf(tile[tx][rr]));
    }
}

// ---------------------------------------------------------------------------
// launch
// ---------------------------------------------------------------------------
extern "C" void kernel_launch(void* const* d_in, const int* in_sizes, int n_in,
                              void* d_out, int out_size)
{
    const float* lhs = (const float*)d_in[0];
    const float* rhs = (const float*)d_in[1];
    const float* Wl  = (const float*)d_in[2];
    const float* Wr  = (const float*)d_in[3];
    float* out = (float*)d_out;

    bf16 *p_lhs_h, *p_lhs_l, *p_rhs_h, *p_rhs_l;
    __half *p_lhsT_h, *p_rhsT_h;
    bf16 *p_Wl_h, *p_Wl_l, *p_Wr_h, *p_Wr_l;
    bf16 *p_L_h, *p_L_l, *p_R_h, *p_R_l;
    __half *p_P1, *p_P2T;
    float *pS, *prc, *pcc;
    cudaGetSymbolAddress((void**)&p_lhs_h, s_lhs_hi);
    cudaGetSymbolAddress((void**)&p_lhs_l, s_lhs_lo);
    cudaGetSymbolAddress((void**)&p_rhs_h, s_rhs_hi);
    cudaGetSymbolAddress((void**)&p_rhs_l, s_rhs_lo);
    cudaGetSymbolAddress((void**)&p_lhsT_h, s_lhsT_h);
    cudaGetSymbolAddress((void**)&p_rhsT_h, s_rhsT_h);
    cudaGetSymbolAddress((void**)&p_Wl_h, s_Wl_hi);
    cudaGetSymbolAddress((void**)&p_Wl_l, s_Wl_lo);
    cudaGetSymbolAddress((void**)&p_Wr_h, s_Wr_hi);
    cudaGetSymbolAddress((void**)&p_Wr_l, s_Wr_lo);
    cudaGetSymbolAddress((void**)&p_L_h, g_L_hi);
    cudaGetSymbolAddress((void**)&p_L_l, g_L_lo);
    cudaGetSymbolAddress((void**)&p_R_h, g_R_hi);
    cudaGetSymbolAddress((void**)&p_R_l, g_R_lo);
    cudaGetSymbolAddress((void**)&p_P1, g_P1);
    cudaGetSymbolAddress((void**)&p_P2T, g_P2T);
    cudaGetSymbolAddress((void**)&pS, g_S);
    cudaGetSymbolAddress((void**)&prc, g_rowc);
    cudaGetSymbolAddress((void**)&pcc, g_colc);

    const int SMEMB = 3 * STAGE_B3;  // 72 KB
    const int SMEMA = 3 * STAGEA;    // 96 KB
    cudaFuncSetAttribute(mm_bf16x3<0>, cudaFuncAttributeMaxDynamicSharedMemorySize, SMEMB);
    cudaFuncSetAttribute(mm_bf16x3<1>, cudaFuncAttributeMaxDynamicSharedMemorySize, SMEMB);
    cudaFuncSetAttribute(mm_f16_apply, cudaFuncAttributeMaxDynamicSharedMemorySize, SMEMA);

    // 1. operand prep: split + transpose + passthrough copy
    split_tr<<<dim3(DD / 32, LL / 32, BB), dim3(32, 8)>>>(
        lhs, p_lhs_h, p_lhs_l, p_lhsT_h, out);
    split_tr<<<dim3(DD / 32, LL / 32, BB), dim3(32, 8)>>>(
        rhs, p_rhs_h, p_rhs_l, p_rhsT_h, out + (size_t)BB * LL * 1536);
    split_w<<<(DD * DD + 255) / 256, 256>>>(Wl, Wr, p_Wl_h, p_Wl_l, p_Wr_h, p_Wr_l);

    // 2. both projections in ONE launch (z=0: lhs@Wl, z=1: rhs@Wr)
    mm_bf16x3<1><<<dim3(DD / 128, (BB * LL) / 64, 2), 256, SMEMB>>>(
        p_lhs_h, p_lhs_l, p_Wl_h, p_Wl_l,
        p_rhs_h, p_rhs_l, p_Wr_h, p_Wr_l,
        0, 0, DD, DD / 32, 1,
        nullptr, 0, DD, p_L_h, p_L_l, p_R_h, p_R_l);

    // 3. scores (per batch 1024 x 1024 x 768 -> fp32 S)
    mm_bf16x3<0><<<dim3(LL / 128, LL / 64, BB), 256, SMEMB>>>(
        p_L_h, p_L_l, p_R_h, p_R_l,
        nullptr, nullptr, nullptr, nullptr,
        (long)LL * DD, (long)LL * DD, DD, DD / 32, 0,
        pS, (long)LL * LL, LL, nullptr, nullptr, nullptr, nullptr);

    // 4. softmax stats + normalized fp16 probabilities
    row_stats<<<BB * LL, 256>>>(pS, prc);
    col_stats<<<dim3(LL / 32, BB), dim3(32, 8)>>>(pS, pcc);
    transform<<<dim3(LL / 32, LL / 32, BB), dim3(32, 8)>>>(pS, prc, pcc, p_P1, p_P2T);

    // 5. both applies in ONE launch (z<8: dir 0, z>=8: dir 1), V fp16 single
    mm_f16_apply<<<dim3(DD / 128, LL / 128, 2 * BB), 256, SMEMA>>>(
        p_P1, p_rhsT_h, out,
        p_P2T, p_lhsT_h, out + (size_t)BB * LL * 1536);
}

// round 10
// speedup vs baseline: 1.4515x; 1.0612x over previous
#include <cuda_runtime.h>
#include <cuda_bf16.h>
#include <cuda_fp16.h>
#include <cstdint>
#include <math.h>

#define BB 8
#define LL 1024
#define DD 768
#define INV_SCALE 0.03608439182435161f  /* 1/sqrt(768) */

typedef __nv_bfloat16 bf16;

// ---------------------------------------------------------------------------
// scratch (device globals; no allocation)
// ---------------------------------------------------------------------------
__device__ bf16 s_lhs_hi[BB * LL * DD], s_lhs_lo[BB * LL * DD];   // proj A
__device__ bf16 s_rhs_hi[BB * LL * DD], s_rhs_lo[BB * LL * DD];
__device__ __half s_lhsT_h[BB * DD * LL];   // apply B (fp16, single)
__device__ __half s_rhsT_h[BB * DD * LL];
__device__ bf16 s_Wl_hi[DD * DD], s_Wl_lo[DD * DD];
__device__ bf16 s_Wr_hi[DD * DD], s_Wr_lo[DD * DD];
__device__ bf16 g_L_hi[BB * LL * DD], g_L_lo[BB * LL * DD];
__device__ bf16 g_R_hi[BB * LL * DD], g_R_lo[BB * LL * DD];
__device__ __half g_P1[BB * LL * LL];    // row-softmax probs fp16 [l][r]
__device__ __half g_P2T[BB * LL * LL];   // col-softmax probs fp16, transposed [r][l]
__device__ float g_S[BB * LL * LL];
__device__ float g_rowc[BB * LL];
__device__ float g_colc[BB * LL];
// per-block softmax partials (m, s) written by the scores epilogue
__device__ float2 g_prow[8][BB * LL];    // indexed [col-block x][row]
__device__ float2 g_pcol[8][BB * LL];    // indexed [row-block y][col]

__device__ __forceinline__ float fast_tanh(float x) {
    return 1.0f - __fdividef(2.0f, __expf(2.0f * x) + 1.0f);
}

__device__ __forceinline__ uint32_t smem_to_u32(const void* p) {
    uint32_t a;
    asm("{ .reg .u64 t; cvta.to.shared.u64 t, %1; cvt.u32.u64 %0, t; }"
        : "=r"(a) : "l"(p));
    return a;
}

// merge two (max, sumexp) partials
__device__ __forceinline__ void merge_ms(float& m, float& s, float om, float os) {
    const float nm = fmaxf(m, om);
    s = s * __expf(m - nm) + os * __expf(om - nm);
    m = nm;
}

// ---------------------------------------------------------------------------
// MMA helpers
// ---------------------------------------------------------------------------
__device__ __forceinline__ void ldsm4(uint32_t* r, uint32_t addr) {
    asm volatile("ldmatrix.sync.aligned.m8n8.x4.shared.b16 {%0,%1,%2,%3}, [%4];"
                 : "=r"(r[0]), "=r"(r[1]), "=r"(r[2]), "=r"(r[3]) : "r"(addr));
}

__device__ __forceinline__ void mma16816_bf(float* d, const uint32_t* a,
                                            uint32_t b0, uint32_t b1) {
    asm volatile(
        "mma.sync.aligned.m16n8k16.row.col.f32.bf16.bf16.f32 "
        "{%0,%1,%2,%3}, {%4,%5,%6,%7}, {%8,%9}, {%0,%1,%2,%3};"
        : "+f"(d[0]), "+f"(d[1]), "+f"(d[2]), "+f"(d[3])
        : "r"(a[0]), "r"(a[1]), "r"(a[2]), "r"(a[3]), "r"(b0), "r"(b1));
}

__device__ __forceinline__ void mma16816_f16(float* d, const uint32_t* a,
                                             uint32_t b0, uint32_t b1) {
    asm volatile(
        "mma.sync.aligned.m16n8k16.row.col.f32.f16.f16.f32 "
        "{%0,%1,%2,%3}, {%4,%5,%6,%7}, {%8,%9}, {%0,%1,%2,%3};"
        : "+f"(d[0]), "+f"(d[1]), "+f"(d[2]), "+f"(d[3])
        : "r"(a[0]), "r"(a[1]), "r"(a[2]), "r"(a[3]), "r"(b0), "r"(b1));
}

#define CP_ASYNC16(saddr, gptr) \
    asm volatile("cp.async.cg.shared.global [%0], [%1], 16;" \
        :: "r"(saddr), "l"(gptr) : "memory")
#define CP_COMMIT() asm volatile("cp.async.commit_group;" ::: "memory")
#define CP_WAIT(n) asm volatile("cp.async.wait_group %0;" :: "n"(n) : "memory")

// 64B-row tile (K-chunk 32 bf16): swizzled 16B chunks
__device__ __forceinline__ uint32_t tile_addr(uint32_t matbase, int row, int chunk) {
    int swz = chunk ^ (row & 3) ^ ((row >> 2) & 1);
    return matbase + row * 64 + swz * 16;
}
__device__ __forceinline__ uint32_t frag_addr(uint32_t matbase, int baserow,
                                              int kg, int lane) {
    int row = baserow + (lane & 7) + ((lane >> 3) & 1) * 8;
    int chunk = kg * 2 + ((lane >> 4) & 1);
    return tile_addr(matbase, row, chunk);
}

// 128B-row tile (fp16 K-chunk 64): swizzled 16B chunks, 8 per row
__device__ __forceinline__ uint32_t tile2_addr(uint32_t matbase, int row, int chunk) {
    int swz = chunk ^ (row & 7);
    return matbase + row * 128 + swz * 16;
}
__device__ __forceinline__ uint32_t frag2_addr(uint32_t matbase, int baserow,
                                               int kg, int lane) {
    int row = baserow + (lane & 7) + ((lane >> 3) & 1) * 8;
    int chunk = kg * 2 + ((lane >> 4) & 1);
    return tile2_addr(matbase, row, chunk);
}

#define MAT_BYTES 8192

// ---------------------------------------------------------------------------
// bf16x3 HMMA GEMM (proj + scores).  C = act((Ahi+Alo) @ (Bhi+Blo)^T)
// Block 128x128, 8 warps (4m x 2n), K-chunk 32, 3-stage cp.async, 2 CTAs/SM.
// EPI 0: fp32 store + fused softmax partial stats.
// EPI 1: tanh + split -> bf16 hi/lo.
// ---------------------------------------------------------------------------
#define STAGE4 32768  /* 4 matrices x 8 KB */

template <int EPI>
__global__ __launch_bounds__(256, 2) void mm_bf16x3(
    const bf16* __restrict__ Ahi, const bf16* __restrict__ Alo,
    const bf16* __restrict__ Bhi, const bf16* __restrict__ Blo,
    const bf16* __restrict__ A2hi, const bf16* __restrict__ A2lo,
    const bf16* __restrict__ B2hi, const bf16* __restrict__ B2lo,
    long sA, long sB, int ldk, int nch, int zsplit,
    float* __restrict__ C, long sC, int ldc,
    bf16* __restrict__ Chi, bf16* __restrict__ Clo,
    bf16* __restrict__ C2hi, bf16* __restrict__ C2lo)
{
    extern __shared__ char smem[];
    const uint32_t sb = smem_to_u32(smem);
    const int tid = threadIdx.x;
    const int lane = tid & 31;
    const int wid = tid >> 5;
    const int warp_m = wid & 3;
    const int warp_n = wid >> 2;

    int bz = blockIdx.z;
    const bf16 *pAh = Ahi, *pAl = Alo, *pBh = Bhi, *pBl = Blo;
    bf16 *pCh = Chi, *pCl = Clo;
    if (zsplit > 0 && bz >= zsplit) {
        bz -= zsplit;
        pAh = A2hi; pAl = A2lo; pBh = B2hi; pBl = B2lo;
        pCh = C2hi; pCl = C2lo;
    }

    const bf16* mats[4];
    mats[0] = pAh + (long)bz * sA + (long)blockIdx.y * 128 * ldk;
    mats[1] = pAl + (long)bz * sA + (long)blockIdx.y * 128 * ldk;
    mats[2] = pBh + (long)bz * sB + (long)blockIdx.x * 128 * ldk;
    mats[3] = pBl + (long)bz * sB + (long)blockIdx.x * 128 * ldk;

    const int r0a = tid >> 2, c0a = tid & 3;
    const int r0b = (tid + 256) >> 2;

    auto load_chunk = [&](int slot, int k) {
        const uint32_t base = sb + slot * STAGE4;
        const long koff = (long)k * 32;
#pragma unroll
        for (int mat = 0; mat < 4; ++mat) {
            const bf16* g = mats[mat] + koff;
            const uint32_t mb = base + mat * MAT_BYTES;
            CP_ASYNC16(tile_addr(mb, r0a, c0a), g + (long)r0a * ldk + c0a * 8);
            CP_ASYNC16(tile_addr(mb, r0b, c0a), g + (long)r0b * ldk + c0a * 8);
        }
        CP_COMMIT();
    };

    float acc[2][8][4];
#pragma unroll
    for (int i = 0; i < 2; ++i)
#pragma unroll
        for (int j = 0; j < 8; ++j)
#pragma unroll
            for (int q = 0; q < 4; ++q) acc[i][j][q] = 0.0f;

    load_chunk(0, 0);
    load_chunk(1, 1);

#pragma unroll 1
    for (int k = 0; k < nch; ++k) {
        CP_WAIT(1);
        __syncthreads();
        if (k + 2 < nch) load_chunk((k + 2) % 3, k + 2);

        const uint32_t base = sb + (k % 3) * STAGE4;
        const uint32_t sAh = base, sAl = base + MAT_BYTES;
        const uint32_t sBh = base + 2 * MAT_BYTES, sBl = base + 3 * MAT_BYTES;

#pragma unroll
        for (int kg = 0; kg < 2; ++kg) {
            uint32_t ah[2][4], al[2][4], bh[4][4], bl[4][4];
#pragma unroll
            for (int mt = 0; mt < 2; ++mt) {
                ldsm4(ah[mt], frag_addr(sAh, warp_m * 32 + mt * 16, kg, lane));
                ldsm4(al[mt], frag_addr(sAl, warp_m * 32 + mt * 16, kg, lane));
            }
#pragma unroll
            for (int ng = 0; ng < 4; ++ng) {
                ldsm4(bh[ng], frag_addr(sBh, warp_n * 64 + ng * 16, kg, lane));
                ldsm4(bl[ng], frag_addr(sBl, warp_n * 64 + ng * 16, kg, lane));
            }
#pragma unroll
            for (int term = 0; term < 3; ++term)
#pragma unroll
                for (int mt = 0; mt < 2; ++mt)
#pragma unroll
                    for (int ng = 0; ng < 4; ++ng)
#pragma unroll
                        for (int h = 0; h < 2; ++h) {
                            float* d = acc[mt][ng * 2 + h];
                            const uint32_t* a = (term == 2) ? al[mt] : ah[mt];
                            const uint32_t* b = (term == 1) ? bl[ng] : bh[ng];
                            mma16816_bf(d, a, b[h], b[h + 2]);
                        }
        }
    }

    const int rbase = blockIdx.y * 128 + warp_m * 32 + (lane >> 2);
    const int cbase = blockIdx.x * 128 + warp_n * 64 + (lane & 3) * 2;

    if (EPI == 0) {
        // ---- store S tile ----
#pragma unroll
        for (int mt = 0; mt < 2; ++mt)
#pragma unroll
            for (int nt = 0; nt < 8; ++nt) {
                const long r = rbase + mt * 16;
                const long c = cbase + nt * 8;
                float* Cp = C + (long)bz * sC + r * ldc + c;
                *(float2*)Cp = make_float2(acc[mt][nt][0], acc[mt][nt][1]);
                *(float2*)(Cp + 8L * ldc) = make_float2(acc[mt][nt][2], acc[mt][nt][3]);
            }

        // ---- fused softmax partial stats ----
        __syncthreads();   // mainloop smem reads done; reuse smem for reductions
        float2* sm_row = (float2*)smem;          // [2 warp_n][128 rows]
        float2* sm_col = ((float2*)smem) + 256;  // [4 warp_m][128 cols]

        // row partials: each thread covers 16 cols of 4 rows
#pragma unroll
        for (int mt = 0; mt < 2; ++mt)
#pragma unroll
            for (int half = 0; half < 2; ++half) {
                float m = -1e30f;
#pragma unroll
                for (int nt = 0; nt < 8; ++nt) {
                    m = fmaxf(m, acc[mt][nt][half * 2 + 0]);
                    m = fmaxf(m, acc[mt][nt][half * 2 + 1]);
                }
                float s = 0.0f;
#pragma unroll
                for (int nt = 0; nt < 8; ++nt) {
                    s += __expf(acc[mt][nt][half * 2 + 0] - m);
                    s += __expf(acc[mt][nt][half * 2 + 1] - m);
                }
#pragma unroll
                for (int o = 1; o <= 2; o <<= 1) {
                    float om = __shfl_xor_sync(0xffffffffu, m, o);
                    float os = __shfl_xor_sync(0xffffffffu, s, o);
                    merge_ms(m, s, om, os);
                }
                if ((lane & 3) == 0) {
                    const int rowl = warp_m * 32 + mt * 16 + half * 8 + (lane >> 2);
                    sm_row[warp_n * 128 + rowl] = make_float2(m, s);
                }
            }

        // col partials (scaled): each thread covers 4 rows of 16 cols
#pragma unroll
        for (int nt = 0; nt < 8; ++nt)
#pragma unroll
            for (int c = 0; c < 2; ++c) {
                float v0 = acc[0][nt][c] * INV_SCALE;
                float v1 = acc[0][nt][2 + c] * INV_SCALE;
                float v2 = acc[1][nt][c] * INV_SCALE;
                float v3 = acc[1][nt][2 + c] * INV_SCALE;
                float m = fmaxf(fmaxf(v0, v1), fmaxf(v2, v3));
                float s = __expf(v0 - m) + __expf(v1 - m) +
                          __expf(v2 - m) + __expf(v3 - m);
#pragma unroll
                for (int o = 4; o <= 16; o <<= 1) {
                    float om = __shfl_xor_sync(0xffffffffu, m, o);
                    float os = __shfl_xor_sync(0xffffffffu, s, o);
                    merge_ms(m, s, om, os);
                }
                if ((lane >> 2) == 0) {
                    const int coll = warp_n * 64 + nt * 8 + (lane & 3) * 2 + c;
                    sm_col[warp_m * 128 + coll] = make_float2(m, s);
                }
            }

        __syncthreads();
        if (tid < 128) {
            float2 a = sm_row[tid];
            float2 b = sm_row[128 + tid];
            merge_ms(a.x, a.y, b.x, b.y);
            g_prow[blockIdx.x][(long)bz * LL + blockIdx.y * 128 + tid] = a;
        }
        if (tid < 128) {
            float2 a = sm_col[tid];
#pragma unroll
            for (int w = 1; w < 4; ++w) {
                float2 b = sm_col[w * 128 + tid];
                merge_ms(a.x, a.y, b.x, b.y);
            }
            g_pcol[blockIdx.y][(long)bz * LL + blockIdx.x * 128 + tid] = a;
        }
    } else {
#pragma unroll
        for (int mt = 0; mt < 2; ++mt)
#pragma unroll
            for (int nt = 0; nt < 8; ++nt)
#pragma unroll
                for (int half = 0; half < 2; ++half) {
                    const long r = rbase + mt * 16 + half * 8;
                    const long c = cbase + nt * 8;
                    float v0 = fast_tanh(acc[mt][nt][half * 2 + 0]);
                    float v1 = fast_tanh(acc[mt][nt][half * 2 + 1]);
                    bf16 h0 = __float2bfloat16(v0);
                    bf16 h1 = __float2bfloat16(v1);
                    bf16 l0 = __float2bfloat16(v0 - __bfloat162float(h0));
                    bf16 l1 = __float2bfloat16(v1 - __bfloat162float(h1));
                    __nv_bfloat162 hh; hh.x = h0; hh.y = h1;
                    __nv_bfloat162 llv; llv.x = l0; llv.y = l1;
                    *(uint32_t*)(pCh + r * ldc + c) = *(uint32_t*)&hh;
                    *(uint32_t*)(pCl + r * ldc + c) = *(uint32_t*)&llv;
                }
    }
}

// ---------------------------------------------------------------------------
// merge per-block stats partials -> rowc / colc
// grid (BB*LL/256, 2): y=0 rows, y=1 cols
// ---------------------------------------------------------------------------
__global__ void merge_stats()
{
    const int i = blockIdx.x * 256 + threadIdx.x;
    float m = -1e30f, s = 0.0f;
    if (blockIdx.y == 0) {
#pragma unroll
        for (int p = 0; p < 8; ++p) {
            const float2 v = g_prow[p][i];
            merge_ms(m, s, v.x, v.y);
        }
        g_rowc[i] = m + __logf(s);
    } else {
#pragma unroll
        for (int p = 0; p < 8; ++p) {
            const float2 v = g_pcol[p][i];
            merge_ms(m, s, v.x, v.y);
        }
        g_colc[i] = m + __logf(s);
    }
}

// ---------------------------------------------------------------------------
// fp16 single-V apply GEMM (both dirs merged): out = P @ V^T
// Block 128x128, 8 warps (4m x 2n), K-chunk 64, 3 stages, 2 CTAs/SM.
// ---------------------------------------------------------------------------
#define MAT2_BYTES 16384
#define STAGEA 32768  /* 2 matrices x 16 KB */

__global__ __launch_bounds__(256, 2) void mm_f16_apply(
    const __half* __restrict__ P1, const __half* __restrict__ V1,
    float* __restrict__ out1,
    const __half* __restrict__ P2, const __half* __restrict__ V2,
    float* __restrict__ out2)
{
    extern __shared__ char smem[];
    const uint32_t sb = smem_to_u32(smem);
    const int tid = threadIdx.x;
    const int lane = tid & 31;
    const int wid = tid >> 5;
    const int warp_m = wid & 3;
    const int warp_n = wid >> 2;

    const int bz = blockIdx.z & 7;
    const int dir = blockIdx.z >> 3;
    const __half* P = dir ? P2 : P1;
    const __half* V = dir ? V2 : V1;
    float* out = dir ? out2 : out1;

    const __half* mats[2];
    mats[0] = P + (long)bz * LL * LL + (long)blockIdx.y * 128 * LL;
    mats[1] = V + (long)bz * DD * LL + (long)blockIdx.x * 128 * LL;

    const int rr0 = tid >> 3, cc0 = tid & 7;

    auto load_chunk = [&](int slot, int k) {
        const uint32_t base = sb + slot * STAGEA;
        const long koff = (long)k * 64;
#pragma unroll
        for (int mat = 0; mat < 2; ++mat) {
            const __half* g = mats[mat] + koff;
            const uint32_t mb = base + mat * MAT2_BYTES;
#pragma unroll
            for (int i = 0; i < 4; ++i) {
                const int row = rr0 + i * 32;
                CP_ASYNC16(tile2_addr(mb, row, cc0), g + (long)row * LL + cc0 * 8);
            }
        }
        CP_COMMIT();
    };

    float acc[2][8][4];
#pragma unroll
    for (int i = 0; i < 2; ++i)
#pragma unroll
        for (int j = 0; j < 8; ++j)
#pragma unroll
            for (int q = 0; q < 4; ++q) acc[i][j][q] = 0.0f;

    load_chunk(0, 0);
    load_chunk(1, 1);

#pragma unroll 1
    for (int k = 0; k < 16; ++k) {
        CP_WAIT(1);
        __syncthreads();
        if (k + 2 < 16) load_chunk((k + 2) % 3, k + 2);

        const uint32_t base = sb + (k % 3) * STAGEA;
        const uint32_t sP = base;
        const uint32_t sV = base + MAT2_BYTES;

#pragma unroll
        for (int kg = 0; kg < 4; ++kg) {
            uint32_t a[2][4], b[4][4];
#pragma unroll
            for (int mt = 0; mt < 2; ++mt)
                ldsm4(a[mt], frag2_addr(sP, warp_m * 32 + mt * 16, kg, lane));
#pragma unroll
            for (int ng = 0; ng < 4; ++ng)
                ldsm4(b[ng], frag2_addr(sV, warp_n * 64 + ng * 16, kg, lane));
#pragma unroll
            for (int mt = 0; mt < 2; ++mt)
#pragma unroll
                for (int ng = 0; ng < 4; ++ng)
#pragma unroll
                    for (int h = 0; h < 2; ++h)
                        mma16816_f16(acc[mt][ng * 2 + h], a[mt],
                                     b[ng][h], b[ng][h + 2]);
        }
    }
    __syncthreads();

    const int rbase = blockIdx.y * 128 + warp_m * 32 + (lane >> 2);
    const int cbase = blockIdx.x * 128 + warp_n * 64 + (lane & 3) * 2;
    float* Ob = out + (long)bz * LL * 1536 + DD;
#pragma unroll
    for (int mt = 0; mt < 2; ++mt)
#pragma unroll
        for (int nt = 0; nt < 8; ++nt) {
            const long r = rbase + mt * 16;
            const long c = cbase + nt * 8;
            float* Cp = Ob + r * 1536 + c;
            *(float2*)Cp = make_float2(acc[mt][nt][0], acc[mt][nt][1]);
            *(float2*)(Cp + 8L * 1536) = make_float2(acc[mt][nt][2], acc[mt][nt][3]);
        }
}

// ---------------------------------------------------------------------------
// split + transpose + passthrough
// ---------------------------------------------------------------------------
__global__ void split_tr(const float* __restrict__ X,
                         bf16* __restrict__ Xhi, bf16* __restrict__ Xlo,
                         __half* __restrict__ XTh,
                         float* __restrict__ outbase)
{
    const int b = blockIdx.z;
    const int d0 = blockIdx.x * 32, l0 = blockIdx.y * 32;
    const int tx = threadIdx.x, ty = threadIdx.y;
    __shared__ __half thi[32][33];

#pragma unroll
    for (int i = 0; i < 4; ++i) {
        const int ll = ty + 8 * i;
        const size_t idx = (size_t)b * LL * DD + (size_t)(l0 + ll) * DD + d0 + tx;
        const float x = X[idx];
        const bf16 h = __float2bfloat16(x);
        Xhi[idx] = h;
        Xlo[idx] = __float2bfloat16(x - __bfloat162float(h));
        thi[ll][tx] = __float2half(x);
        outbase[(size_t)(b * LL + l0 + ll) * 1536 + d0 + tx] = x;
    }
    __syncthreads();
#pragma unroll
    for (int i = 0; i < 4; ++i) {
        const int dd = ty + 8 * i;
        XTh[(size_t)b * DD * LL + (size_t)(d0 + dd) * LL + l0 + tx] = thi[tx][dd];
    }
}

__global__ void split_w(const float* __restrict__ Wl, const float* __restrict__ Wr,
                        bf16* __restrict__ Wlh, bf16* __restrict__ Wll,
                        bf16* __restrict__ Wrh, bf16* __restrict__ Wrl)
{
    const int i = blockIdx.x * blockDim.x + threadIdx.x;
    if (i < DD * DD) {
        float x = Wl[i];
        bf16 h = __float2bfloat16(x);
        Wlh[i] = h; Wll[i] = __float2bfloat16(x - __bfloat162float(h));
        x = Wr[i];
        h = __float2bfloat16(x);
        Wrh[i] = h; Wrl[i] = __float2bfloat16(x - __bfloat162float(h));
    }
}

// normalize into P1 fp16 [l][r] and P2T fp16 [r][l]
__global__ void transform(const float* __restrict__ S,
                          const float* __restrict__ rowc,
                          const float* __restrict__ colc,
                          __half* __restrict__ P1, __half* __restrict__ P2T)
{
    const int n = blockIdx.z;
    const size_t base = (size_t)n * LL * LL;
    const int l0 = blockIdx.y * 32, r0 = blockIdx.x * 32;
    const int tx = threadIdx.x, ty = threadIdx.y;
    __shared__ float tile[32][33];
    const float cc = colc[n * LL + r0 + tx];

#pragma unroll
    for (int i = 0; i < 4; ++i) {
        const int ll = ty + 8 * i;
        const size_t idx = base + (size_t)(l0 + ll) * LL + r0 + tx;
        const float s = S[idx];
        P1[idx] = __float2half(__expf(s - rowc[n * LL + l0 + ll]));
        tile[ll][tx] = s * INV_SCALE - cc;
    }
    __syncthreads();
#pragma unroll
    for (int i = 0; i < 4; ++i) {
        const int rr = ty + 8 * i;
        P2T[base + (size_t)(r0 + rr) * LL + l0 + tx] = __float2half(__expf(tile[tx][rr]));
    }
}

// ---------------------------------------------------------------------------
// launch
// ---------------------------------------------------------------------------
extern "C" void kernel_launch(void* const* d_in, const int* in_sizes, int n_in,
                              void* d_out, int out_size)
{
    const float* lhs = (const float*)d_in[0];
    const float* rhs = (const float*)d_in[1];
    const float* Wl  = (const float*)d_in[2];
    const float* Wr  = (const float*)d_in[3];
    float* out = (float*)d_out;

    bf16 *p_lhs_h, *p_lhs_l, *p_rhs_h, *p_rhs_l;
    __half *p_lhsT_h, *p_rhsT_h;
    bf16 *p_Wl_h, *p_Wl_l, *p_Wr_h, *p_Wr_l;
    bf16 *p_L_h, *p_L_l, *p_R_h, *p_R_l;
    __half *p_P1, *p_P2T;
    float *pS, *prc, *pcc;
    cudaGetSymbolAddress((void**)&p_lhs_h, s_lhs_hi);
    cudaGetSymbolAddress((void**)&p_lhs_l, s_lhs_lo);
    cudaGetSymbolAddress((void**)&p_rhs_h, s_rhs_hi);
    cudaGetSymbolAddress((void**)&p_rhs_l, s_rhs_lo);
    cudaGetSymbolAddress((void**)&p_lhsT_h, s_lhsT_h);
    cudaGetSymbolAddress((void**)&p_rhsT_h, s_rhsT_h);
    cudaGetSymbolAddress((void**)&p_Wl_h, s_Wl_hi);
    cudaGetSymbolAddress((void**)&p_Wl_l, s_Wl_lo);
    cudaGetSymbolAddress((void**)&p_Wr_h, s_Wr_hi);
    cudaGetSymbolAddress((void**)&p_Wr_l, s_Wr_lo);
    cudaGetSymbolAddress((void**)&p_L_h, g_L_hi);
    cudaGetSymbolAddress((void**)&p_L_l, g_L_lo);
    cudaGetSymbolAddress((void**)&p_R_h, g_R_hi);
    cudaGetSymbolAddress((void**)&p_R_l, g_R_lo);
    cudaGetSymbolAddress((void**)&p_P1, g_P1);
    cudaGetSymbolAddress((void**)&p_P2T, g_P2T);
    cudaGetSymbolAddress((void**)&pS, g_S);
    cudaGetSymbolAddress((void**)&prc, g_rowc);
    cudaGetSymbolAddress((void**)&pcc, g_colc);

    const int SMEM4 = 3 * STAGE4;  // 96 KB
    const int SMEMA = 3 * STAGEA;  // 96 KB
    cudaFuncSetAttribute(mm_bf16x3<0>, cudaFuncAttributeMaxDynamicSharedMemorySize, SMEM4);
    cudaFuncSetAttribute(mm_bf16x3<1>, cudaFuncAttributeMaxDynamicSharedMemorySize, SMEM4);
    cudaFuncSetAttribute(mm_f16_apply, cudaFuncAttributeMaxDynamicSharedMemorySize, SMEMA);

    // 1. operand prep: split + transpose + passthrough copy
    split_tr<<<dim3(DD / 32, LL / 32, BB), dim3(32, 8)>>>(
        lhs, p_lhs_h, p_lhs_l, p_lhsT_h, out);
    split_tr<<<dim3(DD / 32, LL / 32, BB), dim3(32, 8)>>>(
        rhs, p_rhs_h, p_rhs_l, p_rhsT_h, out + (size_t)BB * LL * 1536);
    split_w<<<(DD * DD + 255) / 256, 256>>>(Wl, Wr, p_Wl_h, p_Wl_l, p_Wr_h, p_Wr_l);

    // 2. both projections in ONE launch (z=0: lhs@Wl, z=1: rhs@Wr)
    mm_bf16x3<1><<<dim3(DD / 128, (BB * LL) / 128, 2), 256, SMEM4>>>(
        p_lhs_h, p_lhs_l, p_Wl_h, p_Wl_l,
        p_rhs_h, p_rhs_l, p_Wr_h, p_Wr_l,
        0, 0, DD, DD / 32, 1,
        nullptr, 0, DD, p_L_h, p_L_l, p_R_h, p_R_l);

    // 3. scores + fused softmax partial stats
    mm_bf16x3<0><<<dim3(LL / 128, LL / 128, BB), 256, SMEM4>>>(
        p_L_h, p_L_l, p_R_h, p_R_l,
        nullptr, nullptr, nullptr, nullptr,
        (long)LL * DD, (long)LL * DD, DD, DD / 32, 0,
        pS, (long)LL * LL, LL, nullptr, nullptr, nullptr, nullptr);

    // 4. merge partials -> rowc/colc, then normalized fp16 probabilities
    merge_stats<<<dim3((BB * LL) / 256, 2), 256>>>();
    transform<<<dim3(LL / 32, LL / 32, BB), dim3(32, 8)>>>(pS, prc, pcc, p_P1, p_P2T);

    // 5. both applies in ONE launch (z<8: dir 0, z>=8: dir 1), V fp16 single
    mm_f16_apply<<<dim3(DD / 128, LL / 128, 2 * BB), 256, SMEMA>>>(
        p_P1, p_rhsT_h, out,
        p_P2T, p_lhsT_h, out + (size_t)BB * LL * 1536);
}

// round 11
// speedup vs baseline: 1.6289x; 1.1223x over previous
#include <cuda_runtime.h>
#include <cuda_bf16.h>
#include <cuda_fp16.h>
#include <cstdint>
#include <math.h>

#define BB 8
#define LL 1024
#define DD 768
#define INV_SCALE 0.03608439182435161f  /* 1/sqrt(768) */

typedef __nv_bfloat16 bf16;

// ---------------------------------------------------------------------------
// scratch (device globals; no allocation)
// ---------------------------------------------------------------------------
__device__ bf16 s_lhs_hi[BB * LL * DD], s_lhs_lo[BB * LL * DD];   // proj A
__device__ bf16 s_rhs_hi[BB * LL * DD], s_rhs_lo[BB * LL * DD];
__device__ __half s_lhsT_h[BB * DD * LL];   // apply B (fp16, single)
__device__ __half s_rhsT_h[BB * DD * LL];
__device__ bf16 s_Wl_hi[DD * DD], s_Wl_lo[DD * DD];
__device__ bf16 s_Wr_hi[DD * DD], s_Wr_lo[DD * DD];
__device__ bf16 g_L_hi[BB * LL * DD], g_L_lo[BB * LL * DD];
__device__ bf16 g_R_hi[BB * LL * DD], g_R_lo[BB * LL * DD];
__device__ __half g_P1[BB * LL * LL];    // row-softmax probs fp16 [l][r]
__device__ __half g_P2T[BB * LL * LL];   // col-softmax probs fp16, transposed [r][l]
__device__ float g_S[BB * LL * LL];
__device__ float2 g_prow[8][BB * LL];    // per-block row partials [col-block x][row]
__device__ float2 g_pcol[8][BB * LL];    // per-block col partials [row-block y][col]

// dependency counters:
// [0,128):  proj rowblocks done      [z*64 + by]          target 6
// [128,192): scores row-stat blocks  [bz*8 + y]           target 8
// [192,256): scores col-stat blocks  [bz*8 + x]           target 8
// [256,320): P1 rowblocks done       [bz*8 + yb]          target 8
// [320,384): P2T rowblocks done      [bz*8 + xb]          target 8
__device__ int c_all[384];

__device__ __forceinline__ float fast_tanh(float x) {
    return 1.0f - __fdividef(2.0f, __expf(2.0f * x) + 1.0f);
}

__device__ __forceinline__ uint32_t smem_to_u32(const void* p) {
    uint32_t a;
    asm("{ .reg .u64 t; cvta.to.shared.u64 t, %1; cvt.u32.u64 %0, t; }"
        : "=r"(a) : "l"(p));
    return a;
}

__device__ __forceinline__ void merge_ms(float& m, float& s, float om, float os) {
    const float nm = fmaxf(m, om);
    s = s * __expf(m - nm) + os * __expf(om - nm);
    m = nm;
}

// ---------------------------------------------------------------------------
// MMA helpers
// ---------------------------------------------------------------------------
__device__ __forceinline__ void ldsm4(uint32_t* r, uint32_t addr) {
    asm volatile("ldmatrix.sync.aligned.m8n8.x4.shared.b16 {%0,%1,%2,%3}, [%4];"
                 : "=r"(r[0]), "=r"(r[1]), "=r"(r[2]), "=r"(r[3]) : "r"(addr));
}

__device__ __forceinline__ void mma16816_bf(float* d, const uint32_t* a,
                                            uint32_t b0, uint32_t b1) {
    asm volatile(
        "mma.sync.aligned.m16n8k16.row.col.f32.bf16.bf16.f32 "
        "{%0,%1,%2,%3}, {%4,%5,%6,%7}, {%8,%9}, {%0,%1,%2,%3};"
        : "+f"(d[0]), "+f"(d[1]), "+f"(d[2]), "+f"(d[3])
        : "r"(a[0]), "r"(a[1]), "r"(a[2]), "r"(a[3]), "r"(b0), "r"(b1));
}

__device__ __forceinline__ void mma16816_f16(float* d, const uint32_t* a,
                                             uint32_t b0, uint32_t b1) {
    asm volatile(
        "mma.sync.aligned.m16n8k16.row.col.f32.f16.f16.f32 "
        "{%0,%1,%2,%3}, {%4,%5,%6,%7}, {%8,%9}, {%0,%1,%2,%3};"
        : "+f"(d[0]), "+f"(d[1]), "+f"(d[2]), "+f"(d[3])
        : "r"(a[0]), "r"(a[1]), "r"(a[2]), "r"(a[3]), "r"(b0), "r"(b1));
}

#define CP_ASYNC16(saddr, gptr) \
    asm volatile("cp.async.cg.shared.global [%0], [%1], 16;" \
        :: "r"(saddr), "l"(gptr) : "memory")
#define CP_COMMIT() asm volatile("cp.async.commit_group;" ::: "memory")
#define CP_WAIT(n) asm volatile("cp.async.wait_group %0;" :: "n"(n) : "memory")

// 64B-row tile (K-chunk 32 bf16)
__device__ __forceinline__ uint32_t tile_addr(uint32_t matbase, int row, int chunk) {
    int swz = chunk ^ (row & 3) ^ ((row >> 2) & 1);
    return matbase + row * 64 + swz * 16;
}
__device__ __forceinline__ uint32_t frag_addr(uint32_t matbase, int baserow,
                                              int kg, int lane) {
    int row = baserow + (lane & 7) + ((lane >> 3) & 1) * 8;
    int chunk = kg * 2 + ((lane >> 4) & 1);
    return tile_addr(matbase, row, chunk);
}
// 128B-row tile (fp16 K-chunk 64)
__device__ __forceinline__ uint32_t tile2_addr(uint32_t matbase, int row, int chunk) {
    int swz = chunk ^ (row & 7);
    return matbase + row * 128 + swz * 16;
}
__device__ __forceinline__ uint32_t frag2_addr(uint32_t matbase, int baserow,
                                               int kg, int lane) {
    int row = baserow + (lane & 7) + ((lane >> 3) & 1) * 8;
    int chunk = kg * 2 + ((lane >> 4) & 1);
    return tile2_addr(matbase, row, chunk);
}

#define MAT_BYTES 8192
#define STAGE4 32768
#define MAT2_BYTES 16384
#define STAGEA 32768
#define SMEM_DYN (3 * STAGE4)   /* 96 KB, shared by all phases */

// ---------------------------------------------------------------------------
// phase bodies (device functions inside the mega kernel)
// ---------------------------------------------------------------------------

// bf16x3 mainloop shared by proj and scores
__device__ __forceinline__ void bf3_mainloop(
    char* smem, uint32_t sb, int tid, int lane, int warp_m, int warp_n,
    const bf16* Ah, const bf16* Al, const bf16* Bh, const bf16* Bl,
    int ldk, int nch, float acc[2][8][4])
{
    const bf16* mats[4] = {Ah, Al, Bh, Bl};
    const int r0a = tid >> 2, c0a = tid & 3;
    const int r0b = (tid + 256) >> 2;

    auto load_chunk = [&](int slot, int k) {
        const uint32_t base = sb + slot * STAGE4;
        const long koff = (long)k * 32;
#pragma unroll
        for (int mat = 0; mat < 4; ++mat) {
            const bf16* g = mats[mat] + koff;
            const uint32_t mb = base + mat * MAT_BYTES;
            CP_ASYNC16(tile_addr(mb, r0a, c0a), g + (long)r0a * ldk + c0a * 8);
            CP_ASYNC16(tile_addr(mb, r0b, c0a), g + (long)r0b * ldk + c0a * 8);
        }
        CP_COMMIT();
    };

    load_chunk(0, 0);
    load_chunk(1, 1);

#pragma unroll 1
    for (int k = 0; k < nch; ++k) {
        CP_WAIT(1);
        __syncthreads();
        if (k + 2 < nch) load_chunk((k + 2) % 3, k + 2);

        const uint32_t base = sb + (k % 3) * STAGE4;
        const uint32_t sAh = base, sAl = base + MAT_BYTES;
        const uint32_t sBh = base + 2 * MAT_BYTES, sBl = base + 3 * MAT_BYTES;

#pragma unroll
        for (int kg = 0; kg < 2; ++kg) {
            uint32_t ah[2][4], al[2][4], bh[4][4], bl[4][4];
#pragma unroll
            for (int mt = 0; mt < 2; ++mt) {
                ldsm4(ah[mt], frag_addr(sAh, warp_m * 32 + mt * 16, kg, lane));
                ldsm4(al[mt], frag_addr(sAl, warp_m * 32 + mt * 16, kg, lane));
            }
#pragma unroll
            for (int ng = 0; ng < 4; ++ng) {
                ldsm4(bh[ng], frag_addr(sBh, warp_n * 64 + ng * 16, kg, lane));
                ldsm4(bl[ng], frag_addr(sBl, warp_n * 64 + ng * 16, kg, lane));
            }
#pragma unroll
            for (int term = 0; term < 3; ++term)
#pragma unroll
                for (int mt = 0; mt < 2; ++mt)
#pragma unroll
                    for (int ng = 0; ng < 4; ++ng)
#pragma unroll
                        for (int h = 0; h < 2; ++h) {
                            float* d = acc[mt][ng * 2 + h];
                            const uint32_t* a = (term == 2) ? al[mt] : ah[mt];
                            const uint32_t* b = (term == 1) ? bl[ng] : bh[ng];
                            mma16816_bf(d, a, b[h], b[h + 2]);
                        }
        }
    }
}

// ---------------------------------------------------------------------------
// the mega kernel: proj [0,768) | scores [768,1280) | transform [1280,1792)
//                  apply [1792,2560)
// ---------------------------------------------------------------------------
__global__ __launch_bounds__(256, 2) void mega(float* __restrict__ out)
{
    extern __shared__ char smem[];
    const uint32_t sb = smem_to_u32(smem);
    const int tid = threadIdx.x;
    const int lane = tid & 31;
    const int wid = tid >> 5;
    const int idx = blockIdx.x;

    if (idx < 768) {
        // =================== PROJ phase ===================
        const int warp_m = wid & 3, warp_n = wid >> 2;
        const int bx = idx % 6;
        const int by = (idx / 6) % 64;
        const int z = idx / 384;

        const bf16* Ah = (z ? s_rhs_hi : s_lhs_hi) + (long)by * 128 * DD;
        const bf16* Al = (z ? s_rhs_lo : s_lhs_lo) + (long)by * 128 * DD;
        const bf16* Bh = (z ? s_Wr_hi : s_Wl_hi) + (long)bx * 128 * DD;
        const bf16* Bl = (z ? s_Wr_lo : s_Wl_lo) + (long)bx * 128 * DD;
        bf16* Ch = z ? g_R_hi : g_L_hi;
        bf16* Cl = z ? g_R_lo : g_L_lo;

        float acc[2][8][4];
#pragma unroll
        for (int i = 0; i < 2; ++i)
#pragma unroll
            for (int j = 0; j < 8; ++j)
#pragma unroll
                for (int q = 0; q < 4; ++q) acc[i][j][q] = 0.0f;

        bf3_mainloop(smem, sb, tid, lane, warp_m, warp_n,
                     Ah, Al, Bh, Bl, DD, DD / 32, acc);

        const int rbase = by * 128 + warp_m * 32 + (lane >> 2);
        const int cbase = bx * 128 + warp_n * 64 + (lane & 3) * 2;
#pragma unroll
        for (int mt = 0; mt < 2; ++mt)
#pragma unroll
            for (int nt = 0; nt < 8; ++nt)
#pragma unroll
                for (int half = 0; half < 2; ++half) {
                    const long r = rbase + mt * 16 + half * 8;
                    const long c = cbase + nt * 8;
                    float v0 = fast_tanh(acc[mt][nt][half * 2 + 0]);
                    float v1 = fast_tanh(acc[mt][nt][half * 2 + 1]);
                    bf16 h0 = __float2bfloat16(v0);
                    bf16 h1 = __float2bfloat16(v1);
                    bf16 l0 = __float2bfloat16(v0 - __bfloat162float(h0));
                    bf16 l1 = __float2bfloat16(v1 - __bfloat162float(h1));
                    __nv_bfloat162 hh; hh.x = h0; hh.y = h1;
                    __nv_bfloat162 llv; llv.x = l0; llv.y = l1;
                    *(uint32_t*)(Ch + r * DD + c) = *(uint32_t*)&hh;
                    *(uint32_t*)(Cl + r * DD + c) = *(uint32_t*)&llv;
                }

        __threadfence();
        __syncthreads();
        if (tid == 0) atomicAdd(&c_all[z * 64 + by], 1);

    } else if (idx < 1280) {
        // =================== SCORES phase ===================
        const int warp_m = wid & 3, warp_n = wid >> 2;
        const int s = idx - 768;
        const int x = s & 7, y = (s >> 3) & 7, bz = s >> 6;

        if (tid == 0) {
            while (atomicAdd(&c_all[bz * 8 + y], 0) < 6) __nanosleep(128);
            while (atomicAdd(&c_all[64 + bz * 8 + x], 0) < 6) __nanosleep(128);
        }
        __syncthreads();

        const long aoff = ((long)bz * LL + (long)y * 128) * DD;
        const long boff = ((long)bz * LL + (long)x * 128) * DD;

        float acc[2][8][4];
#pragma unroll
        for (int i = 0; i < 2; ++i)
#pragma unroll
            for (int j = 0; j < 8; ++j)
#pragma unroll
                for (int q = 0; q < 4; ++q) acc[i][j][q] = 0.0f;

        bf3_mainloop(smem, sb, tid, lane, warp_m, warp_n,
                     g_L_hi + aoff, g_L_lo + aoff, g_R_hi + boff, g_R_lo + boff,
                     DD, DD / 32, acc);

        const int rbase = y * 128 + warp_m * 32 + (lane >> 2);
        const int cbase = x * 128 + warp_n * 64 + (lane & 3) * 2;
        float* Sp = g_S + (long)bz * LL * LL;
#pragma unroll
        for (int mt = 0; mt < 2; ++mt)
#pragma unroll
            for (int nt = 0; nt < 8; ++nt) {
                const long r = rbase + mt * 16;
                const long c = cbase + nt * 8;
                *(float2*)(Sp + r * LL + c) = make_float2(acc[mt][nt][0], acc[mt][nt][1]);
                *(float2*)(Sp + (r + 8) * LL + c) = make_float2(acc[mt][nt][2], acc[mt][nt][3]);
            }

        // fused softmax partial stats (reuse smem)
        __syncthreads();
        float2* sm_row = (float2*)smem;
        float2* sm_col = ((float2*)smem) + 256;

#pragma unroll
        for (int mt = 0; mt < 2; ++mt)
#pragma unroll
            for (int half = 0; half < 2; ++half) {
                float m = -1e30f;
#pragma unroll
                for (int nt = 0; nt < 8; ++nt) {
                    m = fmaxf(m, acc[mt][nt][half * 2 + 0]);
                    m = fmaxf(m, acc[mt][nt][half * 2 + 1]);
                }
                float sv = 0.0f;
#pragma unroll
                for (int nt = 0; nt < 8; ++nt) {
                    sv += __expf(acc[mt][nt][half * 2 + 0] - m);
                    sv += __expf(acc[mt][nt][half * 2 + 1] - m);
                }
#pragma unroll
                for (int o = 1; o <= 2; o <<= 1) {
                    float om = __shfl_xor_sync(0xffffffffu, m, o);
                    float os = __shfl_xor_sync(0xffffffffu, sv, o);
                    merge_ms(m, sv, om, os);
                }
                if ((lane & 3) == 0) {
                    const int rowl = warp_m * 32 + mt * 16 + half * 8 + (lane >> 2);
                    sm_row[warp_n * 128 + rowl] = make_float2(m, sv);
                }
            }

#pragma unroll
        for (int nt = 0; nt < 8; ++nt)
#pragma unroll
            for (int c = 0; c < 2; ++c) {
                float v0 = acc[0][nt][c] * INV_SCALE;
                float v1 = acc[0][nt][2 + c] * INV_SCALE;
                float v2 = acc[1][nt][c] * INV_SCALE;
                float v3 = acc[1][nt][2 + c] * INV_SCALE;
                float m = fmaxf(fmaxf(v0, v1), fmaxf(v2, v3));
                float sv = __expf(v0 - m) + __expf(v1 - m) +
                           __expf(v2 - m) + __expf(v3 - m);
#pragma unroll
                for (int o = 4; o <= 16; o <<= 1) {
                    float om = __shfl_xor_sync(0xffffffffu, m, o);
                    float os = __shfl_xor_sync(0xffffffffu, sv, o);
                    merge_ms(m, sv, om, os);
                }
                if ((lane >> 2) == 0) {
                    const int coll = warp_n * 64 + nt * 8 + (lane & 3) * 2 + c;
                    sm_col[warp_m * 128 + coll] = make_float2(m, sv);
                }
            }

        __syncthreads();
        if (tid < 128) {
            float2 a = sm_row[tid];
            float2 b = sm_row[128 + tid];
            merge_ms(a.x, a.y, b.x, b.y);
            g_prow[x][(long)bz * LL + y * 128 + tid] = a;

            float2 ac = sm_col[tid];
#pragma unroll
            for (int w = 1; w < 4; ++w) {
                float2 bc = sm_col[w * 128 + tid];
                merge_ms(ac.x, ac.y, bc.x, bc.y);
            }
            g_pcol[y][(long)bz * LL + x * 128 + tid] = ac;
        }

        __threadfence();
        __syncthreads();
        if (tid == 0) {
            atomicAdd(&c_all[128 + bz * 8 + y], 1);
            atomicAdd(&c_all[192 + bz * 8 + x], 1);
        }

    } else if (idx < 1792) {
        // =================== TRANSFORM phase ===================
        const int t = idx - 1280;
        const int xb = t & 7, yb = (t >> 3) & 7, bz = t >> 6;

        if (tid == 0) {
            while (atomicAdd(&c_all[128 + bz * 8 + yb], 0) < 8) __nanosleep(128);
            while (atomicAdd(&c_all[192 + bz * 8 + xb], 0) < 8) __nanosleep(128);
        }
        __syncthreads();

        float* rowc_s = (float*)smem;             // 128
        float* colc_s = rowc_s + 128;             // 128
        __half* tr = (__half*)(colc_s + 128);     // [128][130]

        if (tid < 128) {
            float m = -1e30f, sv = 0.0f;
#pragma unroll
            for (int p = 0; p < 8; ++p) {
                const float2 v = g_prow[p][(long)bz * LL + yb * 128 + tid];
                merge_ms(m, sv, v.x, v.y);
            }
            rowc_s[tid] = m + __logf(sv);
        } else {
            const int c = tid - 128;
            float m = -1e30f, sv = 0.0f;
#pragma unroll
            for (int p = 0; p < 8; ++p) {
                const float2 v = g_pcol[p][(long)bz * LL + xb * 128 + c];
                merge_ms(m, sv, v.x, v.y);
            }
            colc_s[c] = m + __logf(sv);
        }
        __syncthreads();

        const size_t base = (size_t)bz * LL * LL;
#pragma unroll 4
        for (int i = 0; i < 64; ++i) {
            const int r = i * 2 + (tid >> 7);
            const int c = tid & 127;
            const size_t gi = base + (size_t)(yb * 128 + r) * LL + xb * 128 + c;
            const float sval = g_S[gi];
            g_P1[gi] = __float2half(__expf(sval - rowc_s[r]));
            tr[c * 130 + r] = __float2half(__expf(sval * INV_SCALE - colc_s[c]));
        }
        __syncthreads();
#pragma unroll 4
        for (int i = 0; i < 64; ++i) {
            const int rr = i * 2 + (tid >> 7);
            const int cc = tid & 127;
            g_P2T[base + (size_t)(xb * 128 + rr) * LL + yb * 128 + cc] = tr[rr * 130 + cc];
        }

        __threadfence();
        __syncthreads();
        if (tid == 0) {
            atomicAdd(&c_all[256 + bz * 8 + yb], 1);
            atomicAdd(&c_all[320 + bz * 8 + xb], 1);
        }

    } else {
        // =================== APPLY phase ===================
        const int warp_m = wid & 3, warp_n = wid >> 2;
        const int a = idx - 1792;
        const int x = a % 6;
        const int y = (a / 6) % 8;
        const int zz = a / 48;
        const int bz = zz & 7, dir = zz >> 3;

        if (tid == 0) {
            int* cnt = dir ? &c_all[320 + bz * 8 + y] : &c_all[256 + bz * 8 + y];
            while (atomicAdd(cnt, 0) < 8) __nanosleep(128);
        }
        __syncthreads();

        const __half* P = dir ? g_P2T : g_P1;
        const __half* V = dir ? s_lhsT_h : s_rhsT_h;
        float* outp = dir ? out + (size_t)BB * LL * 1536 : out;

        const __half* mats[2];
        mats[0] = P + (long)bz * LL * LL + (long)y * 128 * LL;
        mats[1] = V + (long)bz * DD * LL + (long)x * 128 * LL;

        const int rr0 = tid >> 3, cc0 = tid & 7;

        auto load_chunk = [&](int slot, int k) {
            const uint32_t base = sb + slot * STAGEA;
            const long koff = (long)k * 64;
#pragma unroll
            for (int mat = 0; mat < 2; ++mat) {
                const __half* g = mats[mat] + koff;
                const uint32_t mb = base + mat * MAT2_BYTES;
#pragma unroll
                for (int i = 0; i < 4; ++i) {
                    const int row = rr0 + i * 32;
                    CP_ASYNC16(tile2_addr(mb, row, cc0), g + (long)row * LL + cc0 * 8);
                }
            }
            CP_COMMIT();
        };

        float acc[2][8][4];
#pragma unroll
        for (int i = 0; i < 2; ++i)
#pragma unroll
            for (int j = 0; j < 8; ++j)
#pragma unroll
                for (int q = 0; q < 4; ++q) acc[i][j][q] = 0.0f;

        load_chunk(0, 0);
        load_chunk(1, 1);

#pragma unroll 1
        for (int k = 0; k < 16; ++k) {
            CP_WAIT(1);
            __syncthreads();
            if (k + 2 < 16) load_chunk((k + 2) % 3, k + 2);

            const uint32_t base = sb + (k % 3) * STAGEA;
            const uint32_t sP = base;
            const uint32_t sV = base + MAT2_BYTES;

#pragma unroll
            for (int kg = 0; kg < 4; ++kg) {
                uint32_t af[2][4], bfr[4][4];
#pragma unroll
                for (int mt = 0; mt < 2; ++mt)
                    ldsm4(af[mt], frag2_addr(sP, warp_m * 32 + mt * 16, kg, lane));
#pragma unroll
                for (int ng = 0; ng < 4; ++ng)
                    ldsm4(bfr[ng], frag2_addr(sV, warp_n * 64 + ng * 16, kg, lane));
#pragma unroll
                for (int mt = 0; mt < 2; ++mt)
#pragma unroll
                    for (int ng = 0; ng < 4; ++ng)
#pragma unroll
                        for (int h = 0; h < 2; ++h)
                            mma16816_f16(acc[mt][ng * 2 + h], af[mt],
                                         bfr[ng][h], bfr[ng][h + 2]);
            }
        }
        __syncthreads();

        const int rbase = y * 128 + warp_m * 32 + (lane >> 2);
        const int cbase = x * 128 + warp_n * 64 + (lane & 3) * 2;
        float* Ob = outp + (long)bz * LL * 1536 + DD;
#pragma unroll
        for (int mt = 0; mt < 2; ++mt)
#pragma unroll
            for (int nt = 0; nt < 8; ++nt) {
                const long r = rbase + mt * 16;
                const long c = cbase + nt * 8;
                float* Cp = Ob + r * 1536 + c;
                *(float2*)Cp = make_float2(acc[mt][nt][0], acc[mt][nt][1]);
                *(float2*)(Cp + 8L * 1536) = make_float2(acc[mt][nt][2], acc[mt][nt][3]);
            }
    }
}

// ---------------------------------------------------------------------------
// split + transpose + passthrough
// ---------------------------------------------------------------------------
__global__ void split_tr(const float* __restrict__ X,
                         bf16* __restrict__ Xhi, bf16* __restrict__ Xlo,
                         __half* __restrict__ XTh,
                         float* __restrict__ outbase)
{
    const int b = blockIdx.z;
    const int d0 = blockIdx.x * 32, l0 = blockIdx.y * 32;
    const int tx = threadIdx.x, ty = threadIdx.y;
    __shared__ __half thi[32][33];

#pragma unroll
    for (int i = 0; i < 4; ++i) {
        const int ll = ty + 8 * i;
        const size_t idx = (size_t)b * LL * DD + (size_t)(l0 + ll) * DD + d0 + tx;
        const float x = X[idx];
        const bf16 h = __float2bfloat16(x);
        Xhi[idx] = h;
        Xlo[idx] = __float2bfloat16(x - __bfloat162float(h));
        thi[ll][tx] = __float2half(x);
        outbase[(size_t)(b * LL + l0 + ll) * 1536 + d0 + tx] = x;
    }
    __syncthreads();
#pragma unroll
    for (int i = 0; i < 4; ++i) {
        const int dd = ty + 8 * i;
        XTh[(size_t)b * DD * LL + (size_t)(d0 + dd) * LL + l0 + tx] = thi[tx][dd];
    }
}

// split weights + reset dependency counters (runs strictly before mega)
__global__ void split_w(const float* __restrict__ Wl, const float* __restrict__ Wr,
                        bf16* __restrict__ Wlh, bf16* __restrict__ Wll,
                        bf16* __restrict__ Wrh, bf16* __restrict__ Wrl)
{
    if (blockIdx.x == 0) {
        for (int i = threadIdx.x; i < 384; i += blockDim.x) c_all[i] = 0;
    }
    const int i = blockIdx.x * blockDim.x + threadIdx.x;
    if (i < DD * DD) {
        float x = Wl[i];
        bf16 h = __float2bfloat16(x);
        Wlh[i] = h; Wll[i] = __float2bfloat16(x - __bfloat162float(h));
        x = Wr[i];
        h = __float2bfloat16(x);
        Wrh[i] = h; Wrl[i] = __float2bfloat16(x - __bfloat162float(h));
    }
}

// ---------------------------------------------------------------------------
// launch
// ---------------------------------------------------------------------------
extern "C" void kernel_launch(void* const* d_in, const int* in_sizes, int n_in,
                              void* d_out, int out_size)
{
    const float* lhs = (const float*)d_in[0];
    const float* rhs = (const float*)d_in[1];
    const float* Wl  = (const float*)d_in[2];
    const float* Wr  = (const float*)d_in[3];
    float* out = (float*)d_out;

    bf16 *p_lhs_h, *p_lhs_l, *p_rhs_h, *p_rhs_l;
    __half *p_lhsT_h, *p_rhsT_h;
    bf16 *p_Wl_h, *p_Wl_l, *p_Wr_h, *p_Wr_l;
    cudaGetSymbolAddress((void**)&p_lhs_h, s_lhs_hi);
    cudaGetSymbolAddress((void**)&p_lhs_l, s_lhs_lo);
    cudaGetSymbolAddress((void**)&p_rhs_h, s_rhs_hi);
    cudaGetSymbolAddress((void**)&p_rhs_l, s_rhs_lo);
    cudaGetSymbolAddress((void**)&p_lhsT_h, s_lhsT_h);
    cudaGetSymbolAddress((void**)&p_rhsT_h, s_rhsT_h);
    cudaGetSymbolAddress((void**)&p_Wl_h, s_Wl_hi);
    cudaGetSymbolAddress((void**)&p_Wl_l, s_Wl_lo);
    cudaGetSymbolAddress((void**)&p_Wr_h, s_Wr_hi);
    cudaGetSymbolAddress((void**)&p_Wr_l, s_Wr_lo);

    cudaFuncSetAttribute(mega, cudaFuncAttributeMaxDynamicSharedMemorySize, SMEM_DYN);

    // 1. operand prep: split + transpose + passthrough copy (+ counter reset)
    split_tr<<<dim3(DD / 32, LL / 32, BB), dim3(32, 8)>>>(
        lhs, p_lhs_h, p_lhs_l, p_lhsT_h, out);
    split_tr<<<dim3(DD / 32, LL / 32, BB), dim3(32, 8)>>>(
        rhs, p_rhs_h, p_rhs_l, p_rhsT_h, out + (size_t)BB * LL * 1536);
    split_w<<<(DD * DD + 255) / 256, 256>>>(Wl, Wr, p_Wl_h, p_Wl_l, p_Wr_h, p_Wr_l);

    // 2. mega kernel: proj -> scores(+stats) -> transform -> applies,
    //    chained by device-side fine-grained counters
    mega<<<2560, 256, SMEM_DYN>>>(out);
}

// round 12
// speedup vs baseline: 1.6798x; 1.0312x over previous
#include <cuda_runtime.h>
#include <cuda_bf16.h>
#include <cuda_fp16.h>
#include <cstdint>
#include <math.h>

#define BB 8
#define LL 1024
#define DD 768
#define INV_SCALE 0.03608439182435161f  /* 1/sqrt(768) */

typedef __nv_bfloat16 bf16;

// ---------------------------------------------------------------------------
// scratch (device globals; no allocation)
// ---------------------------------------------------------------------------
__device__ bf16 s_lhs_hi[BB * LL * DD], s_lhs_lo[BB * LL * DD];   // proj A
__device__ bf16 s_rhs_hi[BB * LL * DD], s_rhs_lo[BB * LL * DD];
__device__ __half s_lhsT_h[BB * DD * LL];   // apply B (fp16, single)
__device__ __half s_rhsT_h[BB * DD * LL];
__device__ bf16 s_Wl_hi[DD * DD], s_Wl_lo[DD * DD];
__device__ bf16 s_Wr_hi[DD * DD], s_Wr_lo[DD * DD];
__device__ __half g_L_h[BB * LL * DD];                  // tanh(lhs@Wl) fp16 single
__device__ __half g_R_h[BB * LL * DD], g_R_l[BB * LL * DD];  // tanh(rhs@Wr) fp16 hi/lo
__device__ __half g_P1[BB * LL * LL];    // row-softmax probs fp16 [l][r]
__device__ __half g_P2T[BB * LL * LL];   // col-softmax probs fp16, transposed [r][l]
__device__ float g_S[BB * LL * LL];
__device__ float2 g_prow[8][BB * LL];    // per-block row partials [col-block x][row]
__device__ float2 g_pcol[8][BB * LL];    // per-block col partials [row-block y][col]

// dependency counters
#define CI_PREP_L 0     /* 64 entries, target 1 */
#define CI_PREP_R 64    /* 64 entries, target 1 */
#define CI_W 128        /* 1 entry, target 16 */
#define CI_PROJ 144     /* 128 entries [z*64+by], target 6 */
#define CI_SROW 272     /* 64 [bz*8+y], target 8 */
#define CI_SCOL 336     /* 64 [bz*8+x], target 8 */
#define CI_P1 400       /* 64 [bz*8+yb], target 8 */
#define CI_P2 464       /* 64 [bz*8+xb], target 8 */
#define CI_XT 528       /* 16 [side*8+b], target 8 */
#define NCTR 544
__device__ int c_all[NCTR];

__device__ __forceinline__ float fast_tanh(float x) {
    return 1.0f - __fdividef(2.0f, __expf(2.0f * x) + 1.0f);
}

__device__ __forceinline__ uint32_t smem_to_u32(const void* p) {
    uint32_t a;
    asm("{ .reg .u64 t; cvta.to.shared.u64 t, %1; cvt.u32.u64 %0, t; }"
        : "=r"(a) : "l"(p));
    return a;
}

__device__ __forceinline__ void merge_ms(float& m, float& s, float om, float os) {
    const float nm = fmaxf(m, om);
    s = s * __expf(m - nm) + os * __expf(om - nm);
    m = nm;
}

__device__ __forceinline__ void wait_ge(int* ctr, int target) {
    while (atomicAdd(ctr, 0) < target) __nanosleep(64);
}

// ---------------------------------------------------------------------------
// MMA helpers
// ---------------------------------------------------------------------------
__device__ __forceinline__ void ldsm4(uint32_t* r, uint32_t addr) {
    asm volatile("ldmatrix.sync.aligned.m8n8.x4.shared.b16 {%0,%1,%2,%3}, [%4];"
                 : "=r"(r[0]), "=r"(r[1]), "=r"(r[2]), "=r"(r[3]) : "r"(addr));
}

__device__ __forceinline__ void mma16816_bf(float* d, const uint32_t* a,
                                            uint32_t b0, uint32_t b1) {
    asm volatile(
        "mma.sync.aligned.m16n8k16.row.col.f32.bf16.bf16.f32 "
        "{%0,%1,%2,%3}, {%4,%5,%6,%7}, {%8,%9}, {%0,%1,%2,%3};"
        : "+f"(d[0]), "+f"(d[1]), "+f"(d[2]), "+f"(d[3])
        : "r"(a[0]), "r"(a[1]), "r"(a[2]), "r"(a[3]), "r"(b0), "r"(b1));
}

__device__ __forceinline__ void mma16816_f16(float* d, const uint32_t* a,
                                             uint32_t b0, uint32_t b1) {
    asm volatile(
        "mma.sync.aligned.m16n8k16.row.col.f32.f16.f16.f32 "
        "{%0,%1,%2,%3}, {%4,%5,%6,%7}, {%8,%9}, {%0,%1,%2,%3};"
        : "+f"(d[0]), "+f"(d[1]), "+f"(d[2]), "+f"(d[3])
        : "r"(a[0]), "r"(a[1]), "r"(a[2]), "r"(a[3]), "r"(b0), "r"(b1));
}

#define CP_ASYNC16(saddr, gptr) \
    asm volatile("cp.async.cg.shared.global [%0], [%1], 16;" \
        :: "r"(saddr), "l"(gptr) : "memory")
#define CP_COMMIT() asm volatile("cp.async.commit_group;" ::: "memory")
#define CP_WAIT(n) asm volatile("cp.async.wait_group %0;" :: "n"(n) : "memory")

// 64B-row tile (K-chunk 32 b16 elems)
__device__ __forceinline__ uint32_t tile_addr(uint32_t matbase, int row, int chunk) {
    int swz = chunk ^ (row & 3) ^ ((row >> 2) & 1);
    return matbase + row * 64 + swz * 16;
}
__device__ __forceinline__ uint32_t frag_addr(uint32_t matbase, int baserow,
                                              int kg, int lane) {
    int row = baserow + (lane & 7) + ((lane >> 3) & 1) * 8;
    int chunk = kg * 2 + ((lane >> 4) & 1);
    return tile_addr(matbase, row, chunk);
}
// 128B-row tile (fp16 K-chunk 64)
__device__ __forceinline__ uint32_t tile2_addr(uint32_t matbase, int row, int chunk) {
    int swz = chunk ^ (row & 7);
    return matbase + row * 128 + swz * 16;
}
__device__ __forceinline__ uint32_t frag2_addr(uint32_t matbase, int baserow,
                                               int kg, int lane) {
    int row = baserow + (lane & 7) + ((lane >> 3) & 1) * 8;
    int chunk = kg * 2 + ((lane >> 4) & 1);
    return tile2_addr(matbase, row, chunk);
}

#define MAT_BYTES 8192
#define STAGE4 32768
#define STAGE3 24576
#define MAT2_BYTES 16384
#define STAGEA 32768
#define SMEM_DYN (3 * STAGE4)   /* 96 KB, shared by all phases */

// bf16x3 mainloop (proj)
__device__ __forceinline__ void bf3_mainloop(
    uint32_t sb, int tid, int lane, int warp_m, int warp_n,
    const bf16* Ah, const bf16* Al, const bf16* Bh, const bf16* Bl,
    int ldk, int nch, float acc[2][8][4])
{
    const bf16* mats[4] = {Ah, Al, Bh, Bl};
    const int r0a = tid >> 2, c0a = tid & 3;
    const int r0b = (tid + 256) >> 2;

    auto load_chunk = [&](int slot, int k) {
        const uint32_t base = sb + slot * STAGE4;
        const long koff = (long)k * 32;
#pragma unroll
        for (int mat = 0; mat < 4; ++mat) {
            const bf16* g = mats[mat] + koff;
            const uint32_t mb = base + mat * MAT_BYTES;
            CP_ASYNC16(tile_addr(mb, r0a, c0a), g + (long)r0a * ldk + c0a * 8);
            CP_ASYNC16(tile_addr(mb, r0b, c0a), g + (long)r0b * ldk + c0a * 8);
        }
        CP_COMMIT();
    };

    load_chunk(0, 0);
    load_chunk(1, 1);

#pragma unroll 1
    for (int k = 0; k < nch; ++k) {
        CP_WAIT(1);
        __syncthreads();
        if (k + 2 < nch) load_chunk((k + 2) % 3, k + 2);

        const uint32_t base = sb + (k % 3) * STAGE4;
        const uint32_t sAh = base, sAl = base + MAT_BYTES;
        const uint32_t sBh = base + 2 * MAT_BYTES, sBl = base + 3 * MAT_BYTES;

#pragma unroll
        for (int kg = 0; kg < 2; ++kg) {
            uint32_t ah[2][4], al[2][4], bh[4][4], bl[4][4];
#pragma unroll
            for (int mt = 0; mt < 2; ++mt) {
                ldsm4(ah[mt], frag_addr(sAh, warp_m * 32 + mt * 16, kg, lane));
                ldsm4(al[mt], frag_addr(sAl, warp_m * 32 + mt * 16, kg, lane));
            }
#pragma unroll
            for (int ng = 0; ng < 4; ++ng) {
                ldsm4(bh[ng], frag_addr(sBh, warp_n * 64 + ng * 16, kg, lane));
                ldsm4(bl[ng], frag_addr(sBl, warp_n * 64 + ng * 16, kg, lane));
            }
#pragma unroll
            for (int term = 0; term < 3; ++term)
#pragma unroll
                for (int mt = 0; mt < 2; ++mt)
#pragma unroll
                    for (int ng = 0; ng < 4; ++ng)
#pragma unroll
                        for (int h = 0; h < 2; ++h) {
                            float* d = acc[mt][ng * 2 + h];
                            const uint32_t* a = (term == 2) ? al[mt] : ah[mt];
                            const uint32_t* b = (term == 1) ? bl[ng] : bh[ng];
                            mma16816_bf(d, a, b[h], b[h + 2]);
                        }
        }
    }
}

// ---------------------------------------------------------------------------
// mega kernel.  Grid layout:
// [0,128)     prep inputs (split + transpose + passthrough)
// [128,144)   prep W (split)
// [144,912)   proj (bf16x3, tanh, -> L fp16 single / R fp16 hi+lo)
// [912,1424)  scores (asym fp16x2) + fused softmax partial stats
// [1424,1936) transform (merge stats, P1 + P2T fp16)
// [1936,2704) apply (fp16 single)
// ---------------------------------------------------------------------------
__global__ __launch_bounds__(256, 2) void mega(
    const float* __restrict__ lhs, const float* __restrict__ rhs,
    const float* __restrict__ Wl, const float* __restrict__ Wr,
    float* __restrict__ out)
{
    extern __shared__ char smem[];
    const uint32_t sb = smem_to_u32(smem);
    const int tid = threadIdx.x;
    const int lane = tid & 31;
    const int wid = tid >> 5;
    const int idx = blockIdx.x;

    if (idx < 128) {
        // =================== PREP inputs ===================
        const int side = idx >> 6, by = idx & 63;
        const int b = by >> 3, l0v = (by & 7) * 128;
        const float* X = (side ? rhs : lhs) + ((size_t)b * LL + l0v) * DD;
        bf16* Xh = (side ? s_rhs_hi : s_lhs_hi) + ((size_t)b * LL + l0v) * DD;
        bf16* Xl = (side ? s_rhs_lo : s_lhs_lo) + ((size_t)b * LL + l0v) * DD;
        __half* XT = (side ? s_rhsT_h : s_lhsT_h) + (size_t)b * DD * LL + l0v;
        float* ob = out + (side ? (size_t)BB * LL * 1536 : 0)
                    + ((size_t)b * LL + l0v) * 1536;
        __half* tr = (__half*)smem;   // [32][136]

#pragma unroll 1
        for (int t = 0; t < 24; ++t) {
            const int d0 = t * 32;
#pragma unroll
            for (int i = 0; i < 4; ++i) {
                const int fi = tid + i * 256;
                const int row = fi >> 3, q = fi & 7;
                const float4 v = *(const float4*)(X + (size_t)row * DD + d0 + q * 4);
                const float vv[4] = {v.x, v.y, v.z, v.w};
                uint32_t hp[2], lp[2];
#pragma unroll
                for (int j = 0; j < 2; ++j) {
                    bf16 h0 = __float2bfloat16(vv[2 * j]);
                    bf16 h1 = __float2bfloat16(vv[2 * j + 1]);
                    bf16 lo0 = __float2bfloat16(vv[2 * j] - __bfloat162float(h0));
                    bf16 lo1 = __float2bfloat16(vv[2 * j + 1] - __bfloat162float(h1));
                    __nv_bfloat162 hh; hh.x = h0; hh.y = h1;
                    __nv_bfloat162 llv; llv.x = lo0; llv.y = lo1;
                    hp[j] = *(uint32_t*)&hh; lp[j] = *(uint32_t*)&llv;
                }
                *(uint2*)(Xh + (size_t)row * DD + d0 + q * 4) = make_uint2(hp[0], hp[1]);
                *(uint2*)(Xl + (size_t)row * DD + d0 + q * 4) = make_uint2(lp[0], lp[1]);
                *(float4*)(ob + (size_t)row * 1536 + d0 + q * 4) = v;
#pragma unroll
                for (int j = 0; j < 4; ++j)
                    tr[(q * 4 + j) * 136 + row] = __float2half(vv[j]);
            }
            __syncthreads();
            {
                const int d = tid >> 3, c = tid & 7;
                const float4 w0 = *(float4*)&tr[d * 136 + c * 16];
                const float4 w1 = *(float4*)&tr[d * 136 + c * 16 + 8];
                *(float4*)(XT + (size_t)(d0 + d) * LL + c * 16) = w0;
                *(float4*)(XT + (size_t)(d0 + d) * LL + c * 16 + 8) = w1;
            }
            __syncthreads();
        }
        __threadfence();
        __syncthreads();
        if (tid == 0) {
            atomicAdd(&c_all[(side ? CI_PREP_R : CI_PREP_L) + by], 1);
            atomicAdd(&c_all[CI_XT + side * 8 + b], 1);
        }

    } else if (idx < 144) {
        // =================== PREP W ===================
        const int wb = idx - 128;
#pragma unroll 1
        for (int w = 0; w < 2; ++w) {
            const float* W = w ? Wr : Wl;
            bf16* Wh = w ? s_Wr_hi : s_Wl_hi;
            bf16* Wlo = w ? s_Wr_lo : s_Wl_lo;
#pragma unroll 1
            for (int i = 0; i < 36; ++i) {
                const long f = (long)wb * 9216 + i * 256 + tid;
                const float4 v = *(const float4*)(W + f * 4);
                const float vv[4] = {v.x, v.y, v.z, v.w};
                uint32_t hp[2], lp[2];
#pragma unroll
                for (int j = 0; j < 2; ++j) {
                    bf16 h0 = __float2bfloat16(vv[2 * j]);
                    bf16 h1 = __float2bfloat16(vv[2 * j + 1]);
                    bf16 lo0 = __float2bfloat16(vv[2 * j] - __bfloat162float(h0));
                    bf16 lo1 = __float2bfloat16(vv[2 * j + 1] - __bfloat162float(h1));
                    __nv_bfloat162 hh; hh.x = h0; hh.y = h1;
                    __nv_bfloat162 llv; llv.x = lo0; llv.y = lo1;
                    hp[j] = *(uint32_t*)&hh; lp[j] = *(uint32_t*)&llv;
                }
                *(uint2*)(Wh + f * 4) = make_uint2(hp[0], hp[1]);
                *(uint2*)(Wlo + f * 4) = make_uint2(lp[0], lp[1]);
            }
        }
        __threadfence();
        __syncthreads();
        if (tid == 0) atomicAdd(&c_all[CI_W], 1);

    } else if (idx < 912) {
        // =================== PROJ ===================
        const int warp_m = wid & 3, warp_n = wid >> 2;
        const int p = idx - 144;
        const int bx = p % 6;
        const int by = (p / 6) % 64;
        const int z = p / 384;

        if (tid == 0) {
            wait_ge(&c_all[(z ? CI_PREP_R : CI_PREP_L) + by], 1);
            wait_ge(&c_all[CI_W], 16);
        }
        __syncthreads();

        const bf16* Ah = (z ? s_rhs_hi : s_lhs_hi) + (long)by * 128 * DD;
        const bf16* Al = (z ? s_rhs_lo : s_lhs_lo) + (long)by * 128 * DD;
        const bf16* Bh = (z ? s_Wr_hi : s_Wl_hi) + (long)bx * 128 * DD;
        const bf16* Bl = (z ? s_Wr_lo : s_Wl_lo) + (long)bx * 128 * DD;

        float acc[2][8][4];
#pragma unroll
        for (int i = 0; i < 2; ++i)
#pragma unroll
            for (int j = 0; j < 8; ++j)
#pragma unroll
                for (int q = 0; q < 4; ++q) acc[i][j][q] = 0.0f;

        bf3_mainloop(sb, tid, lane, warp_m, warp_n, Ah, Al, Bh, Bl, DD, DD / 32, acc);

        const int rbase = by * 128 + warp_m * 32 + (lane >> 2);
        const int cbase = bx * 128 + warp_n * 64 + (lane & 3) * 2;
#pragma unroll
        for (int mt = 0; mt < 2; ++mt)
#pragma unroll
            for (int nt = 0; nt < 8; ++nt)
#pragma unroll
                for (int half = 0; half < 2; ++half) {
                    const long r = rbase + mt * 16 + half * 8;
                    const long c = cbase + nt * 8;
                    const float v0 = fast_tanh(acc[mt][nt][half * 2 + 0]);
                    const float v1 = fast_tanh(acc[mt][nt][half * 2 + 1]);
                    if (z == 0) {
                        __half2 hh; hh.x = __float2half(v0); hh.y = __float2half(v1);
                        *(uint32_t*)(g_L_h + r * DD + c) = *(uint32_t*)&hh;
                    } else {
                        const __half h0 = __float2half(v0);
                        const __half h1 = __float2half(v1);
                        const __half lo0 = __float2half(v0 - __half2float(h0));
                        const __half lo1 = __float2half(v1 - __half2float(h1));
                        __half2 hh; hh.x = h0; hh.y = h1;
                        __half2 llv; llv.x = lo0; llv.y = lo1;
                        *(uint32_t*)(g_R_h + r * DD + c) = *(uint32_t*)&hh;
                        *(uint32_t*)(g_R_l + r * DD + c) = *(uint32_t*)&llv;
                    }
                }

        __threadfence();
        __syncthreads();
        if (tid == 0) atomicAdd(&c_all[CI_PROJ + z * 64 + by], 1);

    } else if (idx < 1424) {
        // =================== SCORES (asym fp16x2) ===================
        const int warp_m = wid & 3, warp_n = wid >> 2;
        const int s = idx - 912;
        const int x = s & 7, y = (s >> 3) & 7, bz = s >> 6;

        if (tid == 0) {
            wait_ge(&c_all[CI_PROJ + bz * 8 + y], 6);
            wait_ge(&c_all[CI_PROJ + 64 + bz * 8 + x], 6);
        }
        __syncthreads();

        const __half* A = g_L_h + ((long)bz * LL + (long)y * 128) * DD;
        const __half* Bh = g_R_h + ((long)bz * LL + (long)x * 128) * DD;
        const __half* Bl = g_R_l + ((long)bz * LL + (long)x * 128) * DD;
        const __half* mats[3] = {A, Bh, Bl};

        const int r0a = tid >> 2, c0a = tid & 3;
        const int r0b = (tid + 256) >> 2;

        auto load_chunk = [&](int slot, int k) {
            const uint32_t base = sb + slot * STAGE3;
            const long koff = (long)k * 32;
#pragma unroll
            for (int mat = 0; mat < 3; ++mat) {
                const __half* g = mats[mat] + koff;
                const uint32_t mb = base + mat * MAT_BYTES;
                CP_ASYNC16(tile_addr(mb, r0a, c0a), g + (long)r0a * DD + c0a * 8);
                CP_ASYNC16(tile_addr(mb, r0b, c0a), g + (long)r0b * DD + c0a * 8);
            }
            CP_COMMIT();
        };

        float acc[2][8][4];
#pragma unroll
        for (int i = 0; i < 2; ++i)
#pragma unroll
            for (int j = 0; j < 8; ++j)
#pragma unroll
                for (int q = 0; q < 4; ++q) acc[i][j][q] = 0.0f;

        load_chunk(0, 0);
        load_chunk(1, 1);

#pragma unroll 1
        for (int k = 0; k < DD / 32; ++k) {
            CP_WAIT(1);
            __syncthreads();
            if (k + 2 < DD / 32) load_chunk((k + 2) % 3, k + 2);

            const uint32_t base = sb + (k % 3) * STAGE3;
            const uint32_t sA = base;
            const uint32_t sBh = base + MAT_BYTES, sBl = base + 2 * MAT_BYTES;

#pragma unroll
            for (int kg = 0; kg < 2; ++kg) {
                uint32_t af[2][4], bh[4][4], bl[4][4];
#pragma unroll
                for (int mt = 0; mt < 2; ++mt)
                    ldsm4(af[mt], frag_addr(sA, warp_m * 32 + mt * 16, kg, lane));
#pragma unroll
                for (int ng = 0; ng < 4; ++ng) {
                    ldsm4(bh[ng], frag_addr(sBh, warp_n * 64 + ng * 16, kg, lane));
                    ldsm4(bl[ng], frag_addr(sBl, warp_n * 64 + ng * 16, kg, lane));
                }
#pragma unroll
                for (int term = 0; term < 2; ++term)
#pragma unroll
                    for (int mt = 0; mt < 2; ++mt)
#pragma unroll
                        for (int ng = 0; ng < 4; ++ng)
#pragma unroll
                            for (int h = 0; h < 2; ++h) {
                                const uint32_t* b = term ? bl[ng] : bh[ng];
                                mma16816_f16(acc[mt][ng * 2 + h], af[mt], b[h], b[h + 2]);
                            }
            }
        }

        const int rbase = y * 128 + warp_m * 32 + (lane >> 2);
        const int cbase = x * 128 + warp_n * 64 + (lane & 3) * 2;
        float* Sp = g_S + (long)bz * LL * LL;
#pragma unroll
        for (int mt = 0; mt < 2; ++mt)
#pragma unroll
            for (int nt = 0; nt < 8; ++nt) {
                const long r = rbase + mt * 16;
                const long c = cbase + nt * 8;
                *(float2*)(Sp + r * LL + c) = make_float2(acc[mt][nt][0], acc[mt][nt][1]);
                *(float2*)(Sp + (r + 8) * LL + c) = make_float2(acc[mt][nt][2], acc[mt][nt][3]);
            }

        // fused softmax partial stats (reuse smem)
        __syncthreads();
        float2* sm_row = (float2*)smem;
        float2* sm_col = ((float2*)smem) + 256;

#pragma unroll
        for (int mt = 0; mt < 2; ++mt)
#pragma unroll
            for (int half = 0; half < 2; ++half) {
                float m = -1e30f;
#pragma unroll
                for (int nt = 0; nt < 8; ++nt) {
                    m = fmaxf(m, acc[mt][nt][half * 2 + 0]);
                    m = fmaxf(m, acc[mt][nt][half * 2 + 1]);
                }
                float sv = 0.0f;
#pragma unroll
                for (int nt = 0; nt < 8; ++nt) {
                    sv += __expf(acc[mt][nt][half * 2 + 0] - m);
                    sv += __expf(acc[mt][nt][half * 2 + 1] - m);
                }
#pragma unroll
                for (int o = 1; o <= 2; o <<= 1) {
                    float om = __shfl_xor_sync(0xffffffffu, m, o);
                    float os = __shfl_xor_sync(0xffffffffu, sv, o);
                    merge_ms(m, sv, om, os);
                }
                if ((lane & 3) == 0) {
                    const int rowl = warp_m * 32 + mt * 16 + half * 8 + (lane >> 2);
                    sm_row[warp_n * 128 + rowl] = make_float2(m, sv);
                }
            }

#pragma unroll
        for (int nt = 0; nt < 8; ++nt)
#pragma unroll
            for (int c = 0; c < 2; ++c) {
                const float v0 = acc[0][nt][c] * INV_SCALE;
                const float v1 = acc[0][nt][2 + c] * INV_SCALE;
                const float v2 = acc[1][nt][c] * INV_SCALE;
                const float v3 = acc[1][nt][2 + c] * INV_SCALE;
                float m = fmaxf(fmaxf(v0, v1), fmaxf(v2, v3));
                float sv = __expf(v0 - m) + __expf(v1 - m) +
                           __expf(v2 - m) + __expf(v3 - m);
#pragma unroll
                for (int o = 4; o <= 16; o <<= 1) {
                    float om = __shfl_xor_sync(0xffffffffu, m, o);
                    float os = __shfl_xor_sync(0xffffffffu, sv, o);
                    merge_ms(m, sv, om, os);
                }
                if ((lane >> 2) == 0) {
                    const int coll = warp_n * 64 + nt * 8 + (lane & 3) * 2 + c;
                    sm_col[warp_m * 128 + coll] = make_float2(m, sv);
                }
            }

        __syncthreads();
        if (tid < 128) {
            float2 a = sm_row[tid];
            float2 b = sm_row[128 + tid];
            merge_ms(a.x, a.y, b.x, b.y);
            g_prow[x][(long)bz * LL + y * 128 + tid] = a;

            float2 ac = sm_col[tid];
#pragma unroll
            for (int w = 1; w < 4; ++w) {
                float2 bc = sm_col[w * 128 + tid];
                merge_ms(ac.x, ac.y, bc.x, bc.y);
            }
            g_pcol[y][(long)bz * LL + x * 128 + tid] = ac;
        }

        __threadfence();
        __syncthreads();
        if (tid == 0) {
            atomicAdd(&c_all[CI_SROW + bz * 8 + y], 1);
            atomicAdd(&c_all[CI_SCOL + bz * 8 + x], 1);
        }

    } else if (idx < 1936) {
        // =================== TRANSFORM ===================
        const int t = idx - 1424;
        const int xb = t & 7, yb = (t >> 3) & 7, bz = t >> 6;

        if (tid == 0) {
            wait_ge(&c_all[CI_SROW + bz * 8 + yb], 8);
            wait_ge(&c_all[CI_SCOL + bz * 8 + xb], 8);
        }
        __syncthreads();

        float* rowc_s = (float*)smem;             // 128
        float* colc_s = rowc_s + 128;             // 128
        __half* tr = (__half*)(colc_s + 128);     // [128][130]

        if (tid < 128) {
            float m = -1e30f, sv = 0.0f;
#pragma unroll
            for (int p = 0; p < 8; ++p) {
                const float2 v = g_prow[p][(long)bz * LL + yb * 128 + tid];
                merge_ms(m, sv, v.x, v.y);
            }
            rowc_s[tid] = m + __logf(sv);
        } else {
            const int c = tid - 128;
            float m = -1e30f, sv = 0.0f;
#pragma unroll
            for (int p = 0; p < 8; ++p) {
                const float2 v = g_pcol[p][(long)bz * LL + xb * 128 + c];
                merge_ms(m, sv, v.x, v.y);
            }
            colc_s[c] = m + __logf(sv);
        }
        __syncthreads();

        const size_t base = (size_t)bz * LL * LL;
#pragma unroll 4
        for (int i = 0; i < 64; ++i) {
            const int r = i * 2 + (tid >> 7);
            const int c = tid & 127;
            const size_t gi = base + (size_t)(yb * 128 + r) * LL + xb * 128 + c;
            const float sval = g_S[gi];
            g_P1[gi] = __float2half(__expf(sval - rowc_s[r]));
            tr[c * 130 + r] = __float2half(__expf(sval * INV_SCALE - colc_s[c]));
        }
        __syncthreads();
#pragma unroll 4
        for (int i = 0; i < 64; ++i) {
            const int rr = i * 2 + (tid >> 7);
            const int cc = tid & 127;
            g_P2T[base + (size_t)(xb * 128 + rr) * LL + yb * 128 + cc] = tr[rr * 130 + cc];
        }

        __threadfence();
        __syncthreads();
        if (tid == 0) {
            atomicAdd(&c_all[CI_P1 + bz * 8 + yb], 1);
            atomicAdd(&c_all[CI_P2 + bz * 8 + xb], 1);
        }

    } else {
        // =================== APPLY ===================
        const int warp_m = wid & 3, warp_n = wid >> 2;
        const int a = idx - 1936;
        const int x = a % 6;
        const int y = (a / 6) % 8;
        const int zz = a / 48;
        const int bz = zz & 7, dir = zz >> 3;

        if (tid == 0) {
            wait_ge(dir ? &c_all[CI_P2 + bz * 8 + y] : &c_all[CI_P1 + bz * 8 + y], 8);
            wait_ge(&c_all[CI_XT + (dir ? 0 : 8) + bz], 8);
        }
        __syncthreads();

        const __half* P = dir ? g_P2T : g_P1;
        const __half* V = dir ? s_lhsT_h : s_rhsT_h;
        float* outp = dir ? out + (size_t)BB * LL * 1536 : out;

        const __half* mats[2];
        mats[0] = P + (long)bz * LL * LL + (long)y * 128 * LL;
        mats[1] = V + (long)bz * DD * LL + (long)x * 128 * LL;

        const int rr0 = tid >> 3, cc0 = tid & 7;

        auto load_chunk = [&](int slot, int k) {
            const uint32_t base = sb + slot * STAGEA;
            const long koff = (long)k * 64;
#pragma unroll
            for (int mat = 0; mat < 2; ++mat) {
                const __half* g = mats[mat] + koff;
                const uint32_t mb = base + mat * MAT2_BYTES;
#pragma unroll
                for (int i = 0; i < 4; ++i) {
                    const int row = rr0 + i * 32;
                    CP_ASYNC16(tile2_addr(mb, row, cc0), g + (long)row * LL + cc0 * 8);
                }
            }
            CP_COMMIT();
        };

        float acc[2][8][4];
#pragma unroll
        for (int i = 0; i < 2; ++i)
#pragma unroll
            for (int j = 0; j < 8; ++j)
#pragma unroll
                for (int q = 0; q < 4; ++q) acc[i][j][q] = 0.0f;

        load_chunk(0, 0);
        load_chunk(1, 1);

#pragma unroll 1
        for (int k = 0; k < 16; ++k) {
            CP_WAIT(1);
            __syncthreads();
            if (k + 2 < 16) load_chunk((k + 2) % 3, k + 2);

            const uint32_t base = sb + (k % 3) * STAGEA;
            const uint32_t sP = base;
            const uint32_t sV = base + MAT2_BYTES;

#pragma unroll
            for (int kg = 0; kg < 4; ++kg) {
                uint32_t af[2][4], bfr[4][4];
#pragma unroll
                for (int mt = 0; mt < 2; ++mt)
                    ldsm4(af[mt], frag2_addr(sP, warp_m * 32 + mt * 16, kg, lane));
#pragma unroll
                for (int ng = 0; ng < 4; ++ng)
                    ldsm4(bfr[ng], frag2_addr(sV, warp_n * 64 + ng * 16, kg, lane));
#pragma unroll
                for (int mt = 0; mt < 2; ++mt)
#pragma unroll
                    for (int ng = 0; ng < 4; ++ng)
#pragma unroll
                        for (int h = 0; h < 2; ++h)
                            mma16816_f16(acc[mt][ng * 2 + h], af[mt],
                                         bfr[ng][h], bfr[ng][h + 2]);
            }
        }
        __syncthreads();

        const int rbase = y * 128 + warp_m * 32 + (lane >> 2);
        const int cbase = x * 128 + warp_n * 64 + (lane & 3) * 2;
        float* Ob = outp + (long)bz * LL * 1536 + DD;
#pragma unroll
        for (int mt = 0; mt < 2; ++mt)
#pragma unroll
            for (int nt = 0; nt < 8; ++nt) {
                const long r = rbase + mt * 16;
                const long c = cbase + nt * 8;
                float* Cp = Ob + r * 1536 + c;
                *(float2*)Cp = make_float2(acc[mt][nt][0], acc[mt][nt][1]);
                *(float2*)(Cp + 8L * 1536) = make_float2(acc[mt][nt][2], acc[mt][nt][3]);
            }
    }
}

// counter reset (must run before mega every replay)
__global__ void reset_ctr()
{
    const int i = blockIdx.x * blockDim.x + threadIdx.x;
    if (i < NCTR) c_all[i] = 0;
}

// ---------------------------------------------------------------------------
// launch
// ---------------------------------------------------------------------------
extern "C" void kernel_launch(void* const* d_in, const int* in_sizes, int n_in,
                              void* d_out, int out_size)
{
    const float* lhs = (const float*)d_in[0];
    const float* rhs = (const float*)d_in[1];
    const float* Wl  = (const float*)d_in[2];
    const float* Wr  = (const float*)d_in[3];
    float* out = (float*)d_out;

    cudaFuncSetAttribute(mega, cudaFuncAttributeMaxDynamicSharedMemorySize, SMEM_DYN);

    reset_ctr<<<3, 256>>>();
    mega<<<2704, 256, SMEM_DYN>>>(lhs, rhs, Wl, Wr, out);
}

// round 13
// speedup vs baseline: 1.8013x; 1.0724x over previous
#include <cuda_runtime.h>
#include <cuda_bf16.h>
#include <cuda_fp16.h>
#include <cstdint>
#include <math.h>

#define BB 8
#define LL 1024
#define DD 768
#define INV_SCALE 0.03608439182435161f  /* 1/sqrt(768) */

typedef __nv_bfloat16 bf16;

// ---------------------------------------------------------------------------
// scratch (device globals; no allocation)
// ---------------------------------------------------------------------------
__device__ bf16 s_lhs_hi[BB * LL * DD], s_lhs_lo[BB * LL * DD];   // proj A
__device__ bf16 s_rhs_hi[BB * LL * DD], s_rhs_lo[BB * LL * DD];
__device__ __half s_lhsT_h[BB * DD * LL];   // apply B (fp16, single)
__device__ __half s_rhsT_h[BB * DD * LL];
__device__ bf16 s_Wl_hi[DD * DD], s_Wl_lo[DD * DD];
__device__ bf16 s_Wr_hi[DD * DD], s_Wr_lo[DD * DD];
__device__ __half g_L_h[BB * LL * DD];   // tanh(lhs@Wl) fp16 single
__device__ __half g_R_h[BB * LL * DD];   // tanh(rhs@Wr) fp16 single
__device__ __half g_P1[BB * LL * LL];    // row-softmax probs fp16 [l][r]
__device__ __half g_P2T[BB * LL * LL];   // col-softmax probs fp16, transposed [r][l]
__device__ float g_S[BB * LL * LL];
__device__ float2 g_prow[8][BB * LL];    // per-block row partials [col-block x][row]
__device__ float2 g_pcol[8][BB * LL];    // per-block col partials [row-block y][col]

// dependency counters
#define CI_PREP_L 0     /* 64 entries, target 1 */
#define CI_PREP_R 64    /* 64 entries, target 1 */
#define CI_W 128        /* 1 entry, target 16 */
#define CI_PROJ 144     /* 128 entries [z*64+by], target 6 */
#define CI_SROW 272     /* 64 [bz*8+y], target 8 */
#define CI_SCOL 336     /* 64 [bz*8+x], target 8 */
#define CI_P1 400       /* 64 [bz*8+yb], target 8 */
#define CI_P2 464       /* 64 [bz*8+xb], target 8 */
#define CI_XT 528       /* 16 [side*8+b], target 8 */
#define NCTR 544
__device__ int c_all[NCTR];

__device__ __forceinline__ float fast_tanh(float x) {
    return 1.0f - __fdividef(2.0f, __expf(2.0f * x) + 1.0f);
}

__device__ __forceinline__ uint32_t smem_to_u32(const void* p) {
    uint32_t a;
    asm("{ .reg .u64 t; cvta.to.shared.u64 t, %1; cvt.u32.u64 %0, t; }"
        : "=r"(a) : "l"(p));
    return a;
}

__device__ __forceinline__ void merge_ms(float& m, float& s, float om, float os) {
    const float nm = fmaxf(m, om);
    s = s * __expf(m - nm) + os * __expf(om - nm);
    m = nm;
}

__device__ __forceinline__ void wait_ge(int* ctr, int target) {
    while (atomicAdd(ctr, 0) < target) __nanosleep(64);
}

// ---------------------------------------------------------------------------
// MMA helpers
// ---------------------------------------------------------------------------
__device__ __forceinline__ void ldsm4(uint32_t* r, uint32_t addr) {
    asm volatile("ldmatrix.sync.aligned.m8n8.x4.shared.b16 {%0,%1,%2,%3}, [%4];"
                 : "=r"(r[0]), "=r"(r[1]), "=r"(r[2]), "=r"(r[3]) : "r"(addr));
}

__device__ __forceinline__ void mma16816_bf(float* d, const uint32_t* a,
                                            uint32_t b0, uint32_t b1) {
    asm volatile(
        "mma.sync.aligned.m16n8k16.row.col.f32.bf16.bf16.f32 "
        "{%0,%1,%2,%3}, {%4,%5,%6,%7}, {%8,%9}, {%0,%1,%2,%3};"
        : "+f"(d[0]), "+f"(d[1]), "+f"(d[2]), "+f"(d[3])
        : "r"(a[0]), "r"(a[1]), "r"(a[2]), "r"(a[3]), "r"(b0), "r"(b1));
}

__device__ __forceinline__ void mma16816_f16(float* d, const uint32_t* a,
                                             uint32_t b0, uint32_t b1) {
    asm volatile(
        "mma.sync.aligned.m16n8k16.row.col.f32.f16.f16.f32 "
        "{%0,%1,%2,%3}, {%4,%5,%6,%7}, {%8,%9}, {%0,%1,%2,%3};"
        : "+f"(d[0]), "+f"(d[1]), "+f"(d[2]), "+f"(d[3])
        : "r"(a[0]), "r"(a[1]), "r"(a[2]), "r"(a[3]), "r"(b0), "r"(b1));
}

#define CP_ASYNC16(saddr, gptr) \
    asm volatile("cp.async.cg.shared.global [%0], [%1], 16;" \
        :: "r"(saddr), "l"(gptr) : "memory")
#define CP_COMMIT() asm volatile("cp.async.commit_group;" ::: "memory")
#define CP_WAIT(n) asm volatile("cp.async.wait_group %0;" :: "n"(n) : "memory")

// 64B-row tile (K-chunk 32 b16 elems)
__device__ __forceinline__ uint32_t tile_addr(uint32_t matbase, int row, int chunk) {
    int swz = chunk ^ (row & 3) ^ ((row >> 2) & 1);
    return matbase + row * 64 + swz * 16;
}
__device__ __forceinline__ uint32_t frag_addr(uint32_t matbase, int baserow,
                                              int kg, int lane) {
    int row = baserow + (lane & 7) + ((lane >> 3) & 1) * 8;
    int chunk = kg * 2 + ((lane >> 4) & 1);
    return tile_addr(matbase, row, chunk);
}
// 128B-row tile (fp16 K-chunk 64)
__device__ __forceinline__ uint32_t tile2_addr(uint32_t matbase, int row, int chunk) {
    int swz = chunk ^ (row & 7);
    return matbase + row * 128 + swz * 16;
}
__device__ __forceinline__ uint32_t frag2_addr(uint32_t matbase, int baserow,
                                               int kg, int lane) {
    int row = baserow + (lane & 7) + ((lane >> 3) & 1) * 8;
    int chunk = kg * 2 + ((lane >> 4) & 1);
    return tile2_addr(matbase, row, chunk);
}

#define MAT_BYTES 8192
#define STAGE4 32768
#define MAT2_BYTES 16384
#define STAGEA 32768
#define SMEM_DYN (3 * STAGE4)   /* 96 KB, shared by all phases */

// bf16x3 mainloop (proj only)
__device__ __forceinline__ void bf3_mainloop(
    uint32_t sb, int tid, int lane, int warp_m, int warp_n,
    const bf16* Ah, const bf16* Al, const bf16* Bh, const bf16* Bl,
    int ldk, int nch, float acc[2][8][4])
{
    const bf16* mats[4] = {Ah, Al, Bh, Bl};
    const int r0a = tid >> 2, c0a = tid & 3;
    const int r0b = (tid + 256) >> 2;

    auto load_chunk = [&](int slot, int k) {
        const uint32_t base = sb + slot * STAGE4;
        const long koff = (long)k * 32;
#pragma unroll
        for (int mat = 0; mat < 4; ++mat) {
            const bf16* g = mats[mat] + koff;
            const uint32_t mb = base + mat * MAT_BYTES;
            CP_ASYNC16(tile_addr(mb, r0a, c0a), g + (long)r0a * ldk + c0a * 8);
            CP_ASYNC16(tile_addr(mb, r0b, c0a), g + (long)r0b * ldk + c0a * 8);
        }
        CP_COMMIT();
    };

    load_chunk(0, 0);
    load_chunk(1, 1);

#pragma unroll 1
    for (int k = 0; k < nch; ++k) {
        CP_WAIT(1);
        __syncthreads();
        if (k + 2 < nch) load_chunk((k + 2) % 3, k + 2);

        const uint32_t base = sb + (k % 3) * STAGE4;
        const uint32_t sAh = base, sAl = base + MAT_BYTES;
        const uint32_t sBh = base + 2 * MAT_BYTES, sBl = base + 3 * MAT_BYTES;

#pragma unroll
        for (int kg = 0; kg < 2; ++kg) {
            uint32_t ah[2][4], al[2][4], bh[4][4], bl[4][4];
#pragma unroll
            for (int mt = 0; mt < 2; ++mt) {
                ldsm4(ah[mt], frag_addr(sAh, warp_m * 32 + mt * 16, kg, lane));
                ldsm4(al[mt], frag_addr(sAl, warp_m * 32 + mt * 16, kg, lane));
            }
#pragma unroll
            for (int ng = 0; ng < 4; ++ng) {
                ldsm4(bh[ng], frag_addr(sBh, warp_n * 64 + ng * 16, kg, lane));
                ldsm4(bl[ng], frag_addr(sBl, warp_n * 64 + ng * 16, kg, lane));
            }
#pragma unroll
            for (int term = 0; term < 3; ++term)
#pragma unroll
                for (int mt = 0; mt < 2; ++mt)
#pragma unroll
                    for (int ng = 0; ng < 4; ++ng)
#pragma unroll
                        for (int h = 0; h < 2; ++h) {
                            float* d = acc[mt][ng * 2 + h];
                            const uint32_t* a = (term == 2) ? al[mt] : ah[mt];
                            const uint32_t* b = (term == 1) ? bl[ng] : bh[ng];
                            mma16816_bf(d, a, b[h], b[h + 2]);
                        }
        }
    }
}

// fp16 single x single mainloop (scores + apply): tile2 layout, K-chunk 64
__device__ __forceinline__ void f16_mainloop(
    uint32_t sb, int tid, int lane, int warp_m, int warp_n,
    const __half* A, const __half* B, int ldk, int nch, float acc[2][8][4])
{
    const __half* mats[2] = {A, B};
    const int rr0 = tid >> 3, cc0 = tid & 7;

    auto load_chunk = [&](int slot, int k) {
        const uint32_t base = sb + slot * STAGEA;
        const long koff = (long)k * 64;
#pragma unroll
        for (int mat = 0; mat < 2; ++mat) {
            const __half* g = mats[mat] + koff;
            const uint32_t mb = base + mat * MAT2_BYTES;
#pragma unroll
            for (int i = 0; i < 4; ++i) {
                const int row = rr0 + i * 32;
                CP_ASYNC16(tile2_addr(mb, row, cc0), g + (long)row * ldk + cc0 * 8);
            }
        }
        CP_COMMIT();
    };

    load_chunk(0, 0);
    load_chunk(1, 1);

#pragma unroll 1
    for (int k = 0; k < nch; ++k) {
        CP_WAIT(1);
        __syncthreads();
        if (k + 2 < nch) load_chunk((k + 2) % 3, k + 2);

        const uint32_t base = sb + (k % 3) * STAGEA;
        const uint32_t sA = base;
        const uint32_t sB = base + MAT2_BYTES;

#pragma unroll
        for (int kg = 0; kg < 4; ++kg) {
            uint32_t af[2][4], bfr[4][4];
#pragma unroll
            for (int mt = 0; mt < 2; ++mt)
                ldsm4(af[mt], frag2_addr(sA, warp_m * 32 + mt * 16, kg, lane));
#pragma unroll
            for (int ng = 0; ng < 4; ++ng)
                ldsm4(bfr[ng], frag2_addr(sB, warp_n * 64 + ng * 16, kg, lane));
#pragma unroll
            for (int mt = 0; mt < 2; ++mt)
#pragma unroll
                for (int ng = 0; ng < 4; ++ng)
#pragma unroll
                    for (int h = 0; h < 2; ++h)
                        mma16816_f16(acc[mt][ng * 2 + h], af[mt],
                                     bfr[ng][h], bfr[ng][h + 2]);
        }
    }
}

// ---------------------------------------------------------------------------
// mega kernel.  Grid layout:
// [0,128)     prep inputs (split + transpose + passthrough)
// [128,144)   prep W (split)
// [144,912)   proj (bf16x3, tanh -> L/R fp16 single)
// [912,1424)  scores (fp16 x fp16) + fused softmax partial stats
// [1424,1936) transform (merge stats, P1 + P2T fp16)
// [1936,2704) apply (fp16 single)
// ---------------------------------------------------------------------------
__global__ __launch_bounds__(256, 2) void mega(
    const float* __restrict__ lhs, const float* __restrict__ rhs,
    const float* __restrict__ Wl, const float* __restrict__ Wr,
    float* __restrict__ out)
{
    extern __shared__ char smem[];
    const uint32_t sb = smem_to_u32(smem);
    const int tid = threadIdx.x;
    const int lane = tid & 31;
    const int wid = tid >> 5;
    const int idx = blockIdx.x;

    if (idx < 128) {
        // =================== PREP inputs ===================
        const int side = idx >> 6, by = idx & 63;
        const int b = by >> 3, l0v = (by & 7) * 128;
        const float* X = (side ? rhs : lhs) + ((size_t)b * LL + l0v) * DD;
        bf16* Xh = (side ? s_rhs_hi : s_lhs_hi) + ((size_t)b * LL + l0v) * DD;
        bf16* Xl = (side ? s_rhs_lo : s_lhs_lo) + ((size_t)b * LL + l0v) * DD;
        __half* XT = (side ? s_rhsT_h : s_lhsT_h) + (size_t)b * DD * LL + l0v;
        float* ob = out + (side ? (size_t)BB * LL * 1536 : 0)
                    + ((size_t)b * LL + l0v) * 1536;
        __half* tr = (__half*)smem;   // [32][136]

#pragma unroll 1
        for (int t = 0; t < 24; ++t) {
            const int d0 = t * 32;
#pragma unroll
            for (int i = 0; i < 4; ++i) {
                const int fi = tid + i * 256;
                const int row = fi >> 3, q = fi & 7;
                const float4 v = *(const float4*)(X + (size_t)row * DD + d0 + q * 4);
                const float vv[4] = {v.x, v.y, v.z, v.w};
                uint32_t hp[2], lp[2];
#pragma unroll
                for (int j = 0; j < 2; ++j) {
                    bf16 h0 = __float2bfloat16(vv[2 * j]);
                    bf16 h1 = __float2bfloat16(vv[2 * j + 1]);
                    bf16 lo0 = __float2bfloat16(vv[2 * j] - __bfloat162float(h0));
                    bf16 lo1 = __float2bfloat16(vv[2 * j + 1] - __bfloat162float(h1));
                    __nv_bfloat162 hh; hh.x = h0; hh.y = h1;
                    __nv_bfloat162 llv; llv.x = lo0; llv.y = lo1;
                    hp[j] = *(uint32_t*)&hh; lp[j] = *(uint32_t*)&llv;
                }
                *(uint2*)(Xh + (size_t)row * DD + d0 + q * 4) = make_uint2(hp[0], hp[1]);
                *(uint2*)(Xl + (size_t)row * DD + d0 + q * 4) = make_uint2(lp[0], lp[1]);
                *(float4*)(ob + (size_t)row * 1536 + d0 + q * 4) = v;
#pragma unroll
                for (int j = 0; j < 4; ++j)
                    tr[(q * 4 + j) * 136 + row] = __float2half(vv[j]);
            }
            __syncthreads();
            {
                const int d = tid >> 3, c = tid & 7;
                const float4 w0 = *(float4*)&tr[d * 136 + c * 16];
                const float4 w1 = *(float4*)&tr[d * 136 + c * 16 + 8];
                *(float4*)(XT + (size_t)(d0 + d) * LL + c * 16) = w0;
                *(float4*)(XT + (size_t)(d0 + d) * LL + c * 16 + 8) = w1;
            }
            __syncthreads();
        }
        __threadfence();
        __syncthreads();
        if (tid == 0) {
            atomicAdd(&c_all[(side ? CI_PREP_R : CI_PREP_L) + by], 1);
            atomicAdd(&c_all[CI_XT + side * 8 + b], 1);
        }

    } else if (idx < 144) {
        // =================== PREP W ===================
        const int wb = idx - 128;
#pragma unroll 1
        for (int w = 0; w < 2; ++w) {
            const float* W = w ? Wr : Wl;
            bf16* Wh = w ? s_Wr_hi : s_Wl_hi;
            bf16* Wlo = w ? s_Wr_lo : s_Wl_lo;
#pragma unroll 1
            for (int i = 0; i < 36; ++i) {
                const long f = (long)wb * 9216 + i * 256 + tid;
                const float4 v = *(const float4*)(W + f * 4);
                const float vv[4] = {v.x, v.y, v.z, v.w};
                uint32_t hp[2], lp[2];
#pragma unroll
                for (int j = 0; j < 2; ++j) {
                    bf16 h0 = __float2bfloat16(vv[2 * j]);
                    bf16 h1 = __float2bfloat16(vv[2 * j + 1]);
                    bf16 lo0 = __float2bfloat16(vv[2 * j] - __bfloat162float(h0));
                    bf16 lo1 = __float2bfloat16(vv[2 * j + 1] - __bfloat162float(h1));
                    __nv_bfloat162 hh; hh.x = h0; hh.y = h1;
                    __nv_bfloat162 llv; llv.x = lo0; llv.y = lo1;
                    hp[j] = *(uint32_t*)&hh; lp[j] = *(uint32_t*)&llv;
                }
                *(uint2*)(Wh + f * 4) = make_uint2(hp[0], hp[1]);
                *(uint2*)(Wlo + f * 4) = make_uint2(lp[0], lp[1]);
            }
        }
        __threadfence();
        __syncthreads();
        if (tid == 0) atomicAdd(&c_all[CI_W], 1);

    } else if (idx < 912) {
        // =================== PROJ ===================
        const int warp_m = wid & 3, warp_n = wid >> 2;
        const int p = idx - 144;
        const int bx = p % 6;
        const int by = (p / 6) % 64;
        const int z = p / 384;

        if (tid == 0) {
            wait_ge(&c_all[(z ? CI_PREP_R : CI_PREP_L) + by], 1);
            wait_ge(&c_all[CI_W], 16);
        }
        __syncthreads();

        const bf16* Ah = (z ? s_rhs_hi : s_lhs_hi) + (long)by * 128 * DD;
        const bf16* Al = (z ? s_rhs_lo : s_lhs_lo) + (long)by * 128 * DD;
        const bf16* Bh = (z ? s_Wr_hi : s_Wl_hi) + (long)bx * 128 * DD;
        const bf16* Bl = (z ? s_Wr_lo : s_Wl_lo) + (long)bx * 128 * DD;
        __half* Cd = z ? g_R_h : g_L_h;

        float acc[2][8][4];
#pragma unroll
        for (int i = 0; i < 2; ++i)
#pragma unroll
            for (int j = 0; j < 8; ++j)
#pragma unroll
                for (int q = 0; q < 4; ++q) acc[i][j][q] = 0.0f;

        bf3_mainloop(sb, tid, lane, warp_m, warp_n, Ah, Al, Bh, Bl, DD, DD / 32, acc);

        const int rbase = by * 128 + warp_m * 32 + (lane >> 2);
        const int cbase = bx * 128 + warp_n * 64 + (lane & 3) * 2;
#pragma unroll
        for (int mt = 0; mt < 2; ++mt)
#pragma unroll
            for (int nt = 0; nt < 8; ++nt)
#pragma unroll
                for (int half = 0; half < 2; ++half) {
                    const long r = rbase + mt * 16 + half * 8;
                    const long c = cbase + nt * 8;
                    __half2 hh;
                    hh.x = __float2half(fast_tanh(acc[mt][nt][half * 2 + 0]));
                    hh.y = __float2half(fast_tanh(acc[mt][nt][half * 2 + 1]));
                    *(uint32_t*)(Cd + r * DD + c) = *(uint32_t*)&hh;
                }

        __threadfence();
        __syncthreads();
        if (tid == 0) atomicAdd(&c_all[CI_PROJ + z * 64 + by], 1);

    } else if (idx < 1424) {
        // =================== SCORES (fp16 x fp16) ===================
        const int warp_m = wid & 3, warp_n = wid >> 2;
        const int s = idx - 912;
        const int x = s & 7, y = (s >> 3) & 7, bz = s >> 6;

        if (tid == 0) {
            wait_ge(&c_all[CI_PROJ + bz * 8 + y], 6);
            wait_ge(&c_all[CI_PROJ + 64 + bz * 8 + x], 6);
        }
        __syncthreads();

        const __half* A = g_L_h + ((long)bz * LL + (long)y * 128) * DD;
        const __half* B = g_R_h + ((long)bz * LL + (long)x * 128) * DD;

        float acc[2][8][4];
#pragma unroll
        for (int i = 0; i < 2; ++i)
#pragma unroll
            for (int j = 0; j < 8; ++j)
#pragma unroll
                for (int q = 0; q < 4; ++q) acc[i][j][q] = 0.0f;

        f16_mainloop(sb, tid, lane, warp_m, warp_n, A, B, DD, DD / 64, acc);

        const int rbase = y * 128 + warp_m * 32 + (lane >> 2);
        const int cbase = x * 128 + warp_n * 64 + (lane & 3) * 2;
        float* Sp = g_S + (long)bz * LL * LL;
#pragma unroll
        for (int mt = 0; mt < 2; ++mt)
#pragma unroll
            for (int nt = 0; nt < 8; ++nt) {
                const long r = rbase + mt * 16;
                const long c = cbase + nt * 8;
                *(float2*)(Sp + r * LL + c) = make_float2(acc[mt][nt][0], acc[mt][nt][1]);
                *(float2*)(Sp + (r + 8) * LL + c) = make_float2(acc[mt][nt][2], acc[mt][nt][3]);
            }

        // fused softmax partial stats (reuse smem)
        __syncthreads();
        float2* sm_row = (float2*)smem;
        float2* sm_col = ((float2*)smem) + 256;

#pragma unroll
        for (int mt = 0; mt < 2; ++mt)
#pragma unroll
            for (int half = 0; half < 2; ++half) {
                float m = -1e30f;
#pragma unroll
                for (int nt = 0; nt < 8; ++nt) {
                    m = fmaxf(m, acc[mt][nt][half * 2 + 0]);
                    m = fmaxf(m, acc[mt][nt][half * 2 + 1]);
                }
                float sv = 0.0f;
#pragma unroll
                for (int nt = 0; nt < 8; ++nt) {
                    sv += __expf(acc[mt][nt][half * 2 + 0] - m);
                    sv += __expf(acc[mt][nt][half * 2 + 1] - m);
                }
#pragma unroll
                for (int o = 1; o <= 2; o <<= 1) {
                    float om = __shfl_xor_sync(0xffffffffu, m, o);
                    float os = __shfl_xor_sync(0xffffffffu, sv, o);
                    merge_ms(m, sv, om, os);
                }
                if ((lane & 3) == 0) {
                    const int rowl = warp_m * 32 + mt * 16 + half * 8 + (lane >> 2);
                    sm_row[warp_n * 128 + rowl] = make_float2(m, sv);
                }
            }

#pragma unroll
        for (int nt = 0; nt < 8; ++nt)
#pragma unroll
            for (int c = 0; c < 2; ++c) {
                const float v0 = acc[0][nt][c] * INV_SCALE;
                const float v1 = acc[0][nt][2 + c] * INV_SCALE;
                const float v2 = acc[1][nt][c] * INV_SCALE;
                const float v3 = acc[1][nt][2 + c] * INV_SCALE;
                float m = fmaxf(fmaxf(v0, v1), fmaxf(v2, v3));
                float sv = __expf(v0 - m) + __expf(v1 - m) +
                           __expf(v2 - m) + __expf(v3 - m);
#pragma unroll
                for (int o = 4; o <= 16; o <<= 1) {
                    float om = __shfl_xor_sync(0xffffffffu, m, o);
                    float os = __shfl_xor_sync(0xffffffffu, sv, o);
                    merge_ms(m, sv, om, os);
                }
                if ((lane >> 2) == 0) {
                    const int coll = warp_n * 64 + nt * 8 + (lane & 3) * 2 + c;
                    sm_col[warp_m * 128 + coll] = make_float2(m, sv);
                }
            }

        __syncthreads();
        if (tid < 128) {
            float2 a = sm_row[tid];
            float2 b = sm_row[128 + tid];
            merge_ms(a.x, a.y, b.x, b.y);
            g_prow[x][(long)bz * LL + y * 128 + tid] = a;

            float2 ac = sm_col[tid];
#pragma unroll
            for (int w = 1; w < 4; ++w) {
                float2 bc = sm_col[w * 128 + tid];
                merge_ms(ac.x, ac.y, bc.x, bc.y);
            }
            g_pcol[y][(long)bz * LL + x * 128 + tid] = ac;
        }

        __threadfence();
        __syncthreads();
        if (tid == 0) {
            atomicAdd(&c_all[CI_SROW + bz * 8 + y], 1);
            atomicAdd(&c_all[CI_SCOL + bz * 8 + x], 1);
        }

    } else if (idx < 1936) {
        // =================== TRANSFORM ===================
        const int t = idx - 1424;
        const int xb = t & 7, yb = (t >> 3) & 7, bz = t >> 6;

        if (tid == 0) {
            wait_ge(&c_all[CI_SROW + bz * 8 + yb], 8);
            wait_ge(&c_all[CI_SCOL + bz * 8 + xb], 8);
        }
        __syncthreads();

        float* rowc_s = (float*)smem;             // 128
        float* colc_s = rowc_s + 128;             // 128
        __half* tr = (__half*)(colc_s + 128);     // [128][130]

        if (tid < 128) {
            float m = -1e30f, sv = 0.0f;
#pragma unroll
            for (int p = 0; p < 8; ++p) {
                const float2 v = g_prow[p][(long)bz * LL + yb * 128 + tid];
                merge_ms(m, sv, v.x, v.y);
            }
            rowc_s[tid] = m + __logf(sv);
        } else {
            const int c = tid - 128;
            float m = -1e30f, sv = 0.0f;
#pragma unroll
            for (int p = 0; p < 8; ++p) {
                const float2 v = g_pcol[p][(long)bz * LL + xb * 128 + c];
                merge_ms(m, sv, v.x, v.y);
            }
            colc_s[c] = m + __logf(sv);
        }
        __syncthreads();

        const size_t base = (size_t)bz * LL * LL;
#pragma unroll 4
        for (int i = 0; i < 64; ++i) {
            const int r = i * 2 + (tid >> 7);
            const int c = tid & 127;
            const size_t gi = base + (size_t)(yb * 128 + r) * LL + xb * 128 + c;
            const float sval = g_S[gi];
            g_P1[gi] = __float2half(__expf(sval - rowc_s[r]));
            tr[c * 130 + r] = __float2half(__expf(sval * INV_SCALE - colc_s[c]));
        }
        __syncthreads();
#pragma unroll 4
        for (int i = 0; i < 64; ++i) {
            const int rr = i * 2 + (tid >> 7);
            const int cc = tid & 127;
            g_P2T[base + (size_t)(xb * 128 + rr) * LL + yb * 128 + cc] = tr[rr * 130 + cc];
        }

        __threadfence();
        __syncthreads();
        if (tid == 0) {
            atomicAdd(&c_all[CI_P1 + bz * 8 + yb], 1);
            atomicAdd(&c_all[CI_P2 + bz * 8 + xb], 1);
        }

    } else {
        // =================== APPLY ===================
        const int warp_m = wid & 3, warp_n = wid >> 2;
        const int a = idx - 1936;
        const int x = a % 6;
        const int y = (a / 6) % 8;
        const int zz = a / 48;
        const int bz = zz & 7, dir = zz >> 3;

        if (tid == 0) {
            wait_ge(dir ? &c_all[CI_P2 + bz * 8 + y] : &c_all[CI_P1 + bz * 8 + y], 8);
            wait_ge(&c_all[CI_XT + (dir ? 0 : 8) + bz], 8);
        }
        __syncthreads();

        const __half* P = dir ? g_P2T : g_P1;
        const __half* V = dir ? s_lhsT_h : s_rhsT_h;
        float* outp = dir ? out + (size_t)BB * LL * 1536 : out;

        float acc[2][8][4];
#pragma unroll
        for (int i = 0; i < 2; ++i)
#pragma unroll
            for (int j = 0; j < 8; ++j)
#pragma unroll
                for (int q = 0; q < 4; ++q) acc[i][j][q] = 0.0f;

        f16_mainloop(sb, tid, lane, warp_m, warp_n,
                     P + (long)bz * LL * LL + (long)y * 128 * LL,
                     V + (long)bz * DD * LL + (long)x * 128 * LL,
                     LL, LL / 64, acc);
        __syncthreads();

        const int rbase = y * 128 + warp_m * 32 + (lane >> 2);
        const int cbase = x * 128 + warp_n * 64 + (lane & 3) * 2;
        float* Ob = outp + (long)bz * LL * 1536 + DD;
#pragma unroll
        for (int mt = 0; mt < 2; ++mt)
#pragma unroll
            for (int nt = 0; nt < 8; ++nt) {
                const long r = rbase + mt * 16;
                const long c = cbase + nt * 8;
                float* Cp = Ob + r * 1536 + c;
                *(float2*)Cp = make_float2(acc[mt][nt][0], acc[mt][nt][1]);
                *(float2*)(Cp + 8L * 1536) = make_float2(acc[mt][nt][2], acc[mt][nt][3]);
            }
    }
}

// counter reset (must run before mega every replay)
__global__ void reset_ctr()
{
    const int i = blockIdx.x * blockDim.x + threadIdx.x;
    if (i < NCTR) c_all[i] = 0;
}

// ---------------------------------------------------------------------------
// launch
// ---------------------------------------------------------------------------
extern "C" void kernel_launch(void* const* d_in, const int* in_sizes, int n_in,
                              void* d_out, int out_size)
{
    const float* lhs = (const float*)d_in[0];
    const float* rhs = (const float*)d_in[1];
    const float* Wl  = (const float*)d_in[2];
    const float* Wr  = (const float*)d_in[3];
    float* out = (float*)d_out;

    cudaFuncSetAttribute(mega, cudaFuncAttributeMaxDynamicSharedMemorySize, SMEM_DYN);

    reset_ctr<<<3, 256>>>();
    mega<<<2704, 256, SMEM_DYN>>>(lhs, rhs, Wl, Wr, out);
}

// round 14
// speedup vs baseline: 2.1323x; 1.1838x over previous
#include <cuda_runtime.h>
#include <cuda_bf16.h>
#include <cuda_fp16.h>
#include <cstdint>
#include <math.h>

#define BB 8
#define LL 1024
#define DD 768
#define INV_SCALE 0.03608439182435161f  /* 1/sqrt(768) */

typedef __nv_bfloat16 bf16;

// ---------------------------------------------------------------------------
// scratch (device globals; no allocation)
// ---------------------------------------------------------------------------
__device__ __half s_lhs_h[BB * LL * DD], s_lhs_l[BB * LL * DD];   // proj A fp16 hi/lo
__device__ __half s_rhs_h[BB * LL * DD], s_rhs_l[BB * LL * DD];
__device__ __half s_lhsT_h[BB * DD * LL];   // apply B (fp16, single, transposed)
__device__ __half s_rhsT_h[BB * DD * LL];
__device__ __half s_Wl_h[DD * DD];          // W fp16 single
__device__ __half s_Wr_h[DD * DD];
__device__ __half g_L_h[BB * LL * DD];   // tanh(lhs@Wl) fp16 single
__device__ __half g_R_h[BB * LL * DD];   // tanh(rhs@Wr) fp16 single
__device__ __half g_P1[BB * LL * LL];    // row-softmax probs fp16 [l][r]
__device__ __half g_P2T[BB * LL * LL];   // col-softmax probs fp16, transposed [r][l]
__device__ float g_S[BB * LL * LL];
__device__ float2 g_prow[8][BB * LL];    // per-block row partials [col-block x][row]
__device__ float2 g_pcol[8][BB * LL];    // per-block col partials [row-block y][col]

// dependency counters
#define CI_PREP_L 0     /* 64 entries, target 1 */
#define CI_PREP_R 64    /* 64 entries, target 1 */
#define CI_W 128        /* 1 entry, target 16 */
#define CI_PROJ 144     /* 128 entries [z*64+by], target 6 */
#define CI_SROW 272     /* 64 [bz*8+y], target 8 */
#define CI_SCOL 336     /* 64 [bz*8+x], target 8 */
#define CI_P1 400       /* 64 [bz*8+yb], target 8 */
#define CI_P2 464       /* 64 [bz*8+xb], target 8 */
#define CI_XT 528       /* 16 [side*8+b], target 8 */
#define NCTR 544
__device__ int c_all[NCTR];

__device__ __forceinline__ float fast_tanh(float x) {
    return 1.0f - __fdividef(2.0f, __expf(2.0f * x) + 1.0f);
}

__device__ __forceinline__ uint32_t smem_to_u32(const void* p) {
    uint32_t a;
    asm("{ .reg .u64 t; cvta.to.shared.u64 t, %1; cvt.u32.u64 %0, t; }"
        : "=r"(a) : "l"(p));
    return a;
}

__device__ __forceinline__ void merge_ms(float& m, float& s, float om, float os) {
    const float nm = fmaxf(m, om);
    s = s * __expf(m - nm) + os * __expf(om - nm);
    m = nm;
}

__device__ __forceinline__ void wait_ge(int* ctr, int target) {
    while (atomicAdd(ctr, 0) < target) __nanosleep(64);
}

// ---------------------------------------------------------------------------
// MMA helpers
// ---------------------------------------------------------------------------
__device__ __forceinline__ void ldsm4(uint32_t* r, uint32_t addr) {
    asm volatile("ldmatrix.sync.aligned.m8n8.x4.shared.b16 {%0,%1,%2,%3}, [%4];"
                 : "=r"(r[0]), "=r"(r[1]), "=r"(r[2]), "=r"(r[3]) : "r"(addr));
}

__device__ __forceinline__ void mma16816_f16(float* d, const uint32_t* a,
                                             uint32_t b0, uint32_t b1) {
    asm volatile(
        "mma.sync.aligned.m16n8k16.row.col.f32.f16.f16.f32 "
        "{%0,%1,%2,%3}, {%4,%5,%6,%7}, {%8,%9}, {%0,%1,%2,%3};"
        : "+f"(d[0]), "+f"(d[1]), "+f"(d[2]), "+f"(d[3])
        : "r"(a[0]), "r"(a[1]), "r"(a[2]), "r"(a[3]), "r"(b0), "r"(b1));
}

#define CP_ASYNC16(saddr, gptr) \
    asm volatile("cp.async.cg.shared.global [%0], [%1], 16;" \
        :: "r"(saddr), "l"(gptr) : "memory")
#define CP_COMMIT() asm volatile("cp.async.commit_group;" ::: "memory")
#define CP_WAIT(n) asm volatile("cp.async.wait_group %0;" :: "n"(n) : "memory")

// 64B-row tile (K-chunk 32 b16 elems)
__device__ __forceinline__ uint32_t tile_addr(uint32_t matbase, int row, int chunk) {
    int swz = chunk ^ (row & 3) ^ ((row >> 2) & 1);
    return matbase + row * 64 + swz * 16;
}
__device__ __forceinline__ uint32_t frag_addr(uint32_t matbase, int baserow,
                                              int kg, int lane) {
    int row = baserow + (lane & 7) + ((lane >> 3) & 1) * 8;
    int chunk = kg * 2 + ((lane >> 4) & 1);
    return tile_addr(matbase, row, chunk);
}
// 128B-row tile (fp16 K-chunk 64)
__device__ __forceinline__ uint32_t tile2_addr(uint32_t matbase, int row, int chunk) {
    int swz = chunk ^ (row & 7);
    return matbase + row * 128 + swz * 16;
}
__device__ __forceinline__ uint32_t frag2_addr(uint32_t matbase, int baserow,
                                               int kg, int lane) {
    int row = baserow + (lane & 7) + ((lane >> 3) & 1) * 8;
    int chunk = kg * 2 + ((lane >> 4) & 1);
    return tile2_addr(matbase, row, chunk);
}

#define MAT_BYTES 8192
#define STAGE_P 24576   /* proj: 3 matrices x 8 KB */
#define STAGE4 32768
#define MAT2_BYTES 16384
#define STAGEA 32768
#define SMEM_DYN (3 * STAGE4)   /* 96 KB, shared by all phases */

// fp16 asym-2 proj mainloop: (Ah + Al) @ Wh^T, K-chunk 32
__device__ __forceinline__ void f16x2_mainloop(
    uint32_t sb, int tid, int lane, int warp_m, int warp_n,
    const __half* Ah, const __half* Al, const __half* Wh,
    int ldk, int nch, float acc[2][8][4])
{
    const __half* mats[3] = {Ah, Al, Wh};
    const int r0a = tid >> 2, c0a = tid & 3;
    const int r0b = (tid + 256) >> 2;

    auto load_chunk = [&](int slot, int k) {
        const uint32_t base = sb + slot * STAGE_P;
        const long koff = (long)k * 32;
#pragma unroll
        for (int mat = 0; mat < 3; ++mat) {
            const __half* g = mats[mat] + koff;
            const uint32_t mb = base + mat * MAT_BYTES;
            CP_ASYNC16(tile_addr(mb, r0a, c0a), g + (long)r0a * ldk + c0a * 8);
            CP_ASYNC16(tile_addr(mb, r0b, c0a), g + (long)r0b * ldk + c0a * 8);
        }
        CP_COMMIT();
    };

    load_chunk(0, 0);
    load_chunk(1, 1);

#pragma unroll 1
    for (int k = 0; k < nch; ++k) {
        CP_WAIT(1);
        __syncthreads();
        if (k + 2 < nch) load_chunk((k + 2) % 3, k + 2);

        const uint32_t base = sb + (k % 3) * STAGE_P;
        const uint32_t sAh = base, sAl = base + MAT_BYTES;
        const uint32_t sW = base + 2 * MAT_BYTES;

#pragma unroll
        for (int kg = 0; kg < 2; ++kg) {
            uint32_t ah[2][4], al[2][4], bw[4][4];
#pragma unroll
            for (int mt = 0; mt < 2; ++mt) {
                ldsm4(ah[mt], frag_addr(sAh, warp_m * 32 + mt * 16, kg, lane));
                ldsm4(al[mt], frag_addr(sAl, warp_m * 32 + mt * 16, kg, lane));
            }
#pragma unroll
            for (int ng = 0; ng < 4; ++ng)
                ldsm4(bw[ng], frag_addr(sW, warp_n * 64 + ng * 16, kg, lane));
#pragma unroll
            for (int term = 0; term < 2; ++term)
#pragma unroll
                for (int mt = 0; mt < 2; ++mt)
#pragma unroll
                    for (int ng = 0; ng < 4; ++ng)
#pragma unroll
                        for (int h = 0; h < 2; ++h) {
                            const uint32_t* a = term ? al[mt] : ah[mt];
                            mma16816_f16(acc[mt][ng * 2 + h], a,
                                         bw[ng][h], bw[ng][h + 2]);
                        }
        }
    }
}

// fp16 single x single mainloop (scores + apply): tile2 layout, K-chunk 64
__device__ __forceinline__ void f16_mainloop(
    uint32_t sb, int tid, int lane, int warp_m, int warp_n,
    const __half* A, const __half* B, int ldk, int nch, float acc[2][8][4])
{
    const __half* mats[2] = {A, B};
    const int rr0 = tid >> 3, cc0 = tid & 7;

    auto load_chunk = [&](int slot, int k) {
        const uint32_t base = sb + slot * STAGEA;
        const long koff = (long)k * 64;
#pragma unroll
        for (int mat = 0; mat < 2; ++mat) {
            const __half* g = mats[mat] + koff;
            const uint32_t mb = base + mat * MAT2_BYTES;
#pragma unroll
            for (int i = 0; i < 4; ++i) {
                const int row = rr0 + i * 32;
                CP_ASYNC16(tile2_addr(mb, row, cc0), g + (long)row * ldk + cc0 * 8);
            }
        }
        CP_COMMIT();
    };

    load_chunk(0, 0);
    load_chunk(1, 1);

#pragma unroll 1
    for (int k = 0; k < nch; ++k) {
        CP_WAIT(1);
        __syncthreads();
        if (k + 2 < nch) load_chunk((k + 2) % 3, k + 2);

        const uint32_t base = sb + (k % 3) * STAGEA;
        const uint32_t sA = base;
        const uint32_t sB = base + MAT2_BYTES;

#pragma unroll
        for (int kg = 0; kg < 4; ++kg) {
            uint32_t af[2][4], bfr[4][4];
#pragma unroll
            for (int mt = 0; mt < 2; ++mt)
                ldsm4(af[mt], frag2_addr(sA, warp_m * 32 + mt * 16, kg, lane));
#pragma unroll
            for (int ng = 0; ng < 4; ++ng)
                ldsm4(bfr[ng], frag2_addr(sB, warp_n * 64 + ng * 16, kg, lane));
#pragma unroll
            for (int mt = 0; mt < 2; ++mt)
#pragma unroll
                for (int ng = 0; ng < 4; ++ng)
#pragma unroll
                    for (int h = 0; h < 2; ++h)
                        mma16816_f16(acc[mt][ng * 2 + h], af[mt],
                                     bfr[ng][h], bfr[ng][h + 2]);
        }
    }
}

// ---------------------------------------------------------------------------
// mega kernel.  Grid layout:
// [0,128)     prep inputs (fp16 split + transpose + passthrough)
// [128,144)   prep W (fp16 single)
// [144,912)   proj (fp16x2, tanh -> L/R fp16 single)
// [912,1424)  scores (fp16 x fp16) + fused softmax partial stats
// [1424,1936) transform (merge stats, P1 + P2T fp16)
// [1936,2704) apply (fp16 single)
// ---------------------------------------------------------------------------
__global__ __launch_bounds__(256, 2) void mega(
    const float* __restrict__ lhs, const float* __restrict__ rhs,
    const float* __restrict__ Wl, const float* __restrict__ Wr,
    float* __restrict__ out)
{
    extern __shared__ char smem[];
    const uint32_t sb = smem_to_u32(smem);
    const int tid = threadIdx.x;
    const int lane = tid & 31;
    const int wid = tid >> 5;
    const int idx = blockIdx.x;

    if (idx < 128) {
        // =================== PREP inputs ===================
        const int side = idx >> 6, by = idx & 63;
        const int b = by >> 3, l0v = (by & 7) * 128;
        const float* X = (side ? rhs : lhs) + ((size_t)b * LL + l0v) * DD;
        __half* Xh = (side ? s_rhs_h : s_lhs_h) + ((size_t)b * LL + l0v) * DD;
        __half* Xl = (side ? s_rhs_l : s_lhs_l) + ((size_t)b * LL + l0v) * DD;
        __half* XT = (side ? s_rhsT_h : s_lhsT_h) + (size_t)b * DD * LL + l0v;
        float* ob = out + (side ? (size_t)BB * LL * 1536 : 0)
                    + ((size_t)b * LL + l0v) * 1536;
        __half* tr = (__half*)smem;   // [32][136]

#pragma unroll 1
        for (int t = 0; t < 24; ++t) {
            const int d0 = t * 32;
#pragma unroll
            for (int i = 0; i < 4; ++i) {
                const int fi = tid + i * 256;
                const int row = fi >> 3, q = fi & 7;
                const float4 v = *(const float4*)(X + (size_t)row * DD + d0 + q * 4);
                const float vv[4] = {v.x, v.y, v.z, v.w};
                uint32_t hp[2], lp[2];
#pragma unroll
                for (int j = 0; j < 2; ++j) {
                    const __half h0 = __float2half(vv[2 * j]);
                    const __half h1 = __float2half(vv[2 * j + 1]);
                    const __half lo0 = __float2half(vv[2 * j] - __half2float(h0));
                    const __half lo1 = __float2half(vv[2 * j + 1] - __half2float(h1));
                    __half2 hh; hh.x = h0; hh.y = h1;
                    __half2 llv; llv.x = lo0; llv.y = lo1;
                    hp[j] = *(uint32_t*)&hh; lp[j] = *(uint32_t*)&llv;
                }
                *(uint2*)(Xh + (size_t)row * DD + d0 + q * 4) = make_uint2(hp[0], hp[1]);
                *(uint2*)(Xl + (size_t)row * DD + d0 + q * 4) = make_uint2(lp[0], lp[1]);
                *(float4*)(ob + (size_t)row * 1536 + d0 + q * 4) = v;
#pragma unroll
                for (int j = 0; j < 4; ++j)
                    tr[(q * 4 + j) * 136 + row] = __float2half(vv[j]);
            }
            __syncthreads();
            {
                const int d = tid >> 3, c = tid & 7;
                const float4 w0 = *(float4*)&tr[d * 136 + c * 16];
                const float4 w1 = *(float4*)&tr[d * 136 + c * 16 + 8];
                *(float4*)(XT + (size_t)(d0 + d) * LL + c * 16) = w0;
                *(float4*)(XT + (size_t)(d0 + d) * LL + c * 16 + 8) = w1;
            }
            __syncthreads();
        }
        __threadfence();
        __syncthreads();
        if (tid == 0) {
            atomicAdd(&c_all[(side ? CI_PREP_R : CI_PREP_L) + by], 1);
            atomicAdd(&c_all[CI_XT + side * 8 + b], 1);
        }

    } else if (idx < 144) {
        // =================== PREP W (fp16 single) ===================
        const int wb = idx - 128;
#pragma unroll 1
        for (int w = 0; w < 2; ++w) {
            const float* W = w ? Wr : Wl;
            __half* Wh = w ? s_Wr_h : s_Wl_h;
#pragma unroll 1
            for (int i = 0; i < 36; ++i) {
                const long f = (long)wb * 9216 + i * 256 + tid;
                const float4 v = *(const float4*)(W + f * 4);
                __half2 a; a.x = __float2half(v.x); a.y = __float2half(v.y);
                __half2 b; b.x = __float2half(v.z); b.y = __float2half(v.w);
                *(uint2*)(Wh + f * 4) = make_uint2(*(uint32_t*)&a, *(uint32_t*)&b);
            }
        }
        __threadfence();
        __syncthreads();
        if (tid == 0) atomicAdd(&c_all[CI_W], 1);

    } else if (idx < 912) {
        // =================== PROJ (fp16 x2) ===================
        const int warp_m = wid & 3, warp_n = wid >> 2;
        const int p = idx - 144;
        const int bx = p % 6;
        const int by = (p / 6) % 64;
        const int z = p / 384;

        if (tid == 0) {
            wait_ge(&c_all[(z ? CI_PREP_R : CI_PREP_L) + by], 1);
            wait_ge(&c_all[CI_W], 16);
        }
        __syncthreads();

        const __half* Ah = (z ? s_rhs_h : s_lhs_h) + (long)by * 128 * DD;
        const __half* Al = (z ? s_rhs_l : s_lhs_l) + (long)by * 128 * DD;
        const __half* Wh = (z ? s_Wr_h : s_Wl_h) + (long)bx * 128 * DD;
        __half* Cd = z ? g_R_h : g_L_h;

        float acc[2][8][4];
#pragma unroll
        for (int i = 0; i < 2; ++i)
#pragma unroll
            for (int j = 0; j < 8; ++j)
#pragma unroll
                for (int q = 0; q < 4; ++q) acc[i][j][q] = 0.0f;

        f16x2_mainloop(sb, tid, lane, warp_m, warp_n, Ah, Al, Wh, DD, DD / 32, acc);

        const int rbase = by * 128 + warp_m * 32 + (lane >> 2);
        const int cbase = bx * 128 + warp_n * 64 + (lane & 3) * 2;
#pragma unroll
        for (int mt = 0; mt < 2; ++mt)
#pragma unroll
            for (int nt = 0; nt < 8; ++nt)
#pragma unroll
                for (int half = 0; half < 2; ++half) {
                    const long r = rbase + mt * 16 + half * 8;
                    const long c = cbase + nt * 8;
                    __half2 hh;
                    hh.x = __float2half(fast_tanh(acc[mt][nt][half * 2 + 0]));
                    hh.y = __float2half(fast_tanh(acc[mt][nt][half * 2 + 1]));
                    *(uint32_t*)(Cd + r * DD + c) = *(uint32_t*)&hh;
                }

        __threadfence();
        __syncthreads();
        if (tid == 0) atomicAdd(&c_all[CI_PROJ + z * 64 + by], 1);

    } else if (idx < 1424) {
        // =================== SCORES (fp16 x fp16) ===================
        const int warp_m = wid & 3, warp_n = wid >> 2;
        const int s = idx - 912;
        const int x = s & 7, y = (s >> 3) & 7, bz = s >> 6;

        if (tid == 0) {
            wait_ge(&c_all[CI_PROJ + bz * 8 + y], 6);
            wait_ge(&c_all[CI_PROJ + 64 + bz * 8 + x], 6);
        }
        __syncthreads();

        const __half* A = g_L_h + ((long)bz * LL + (long)y * 128) * DD;
        const __half* B = g_R_h + ((long)bz * LL + (long)x * 128) * DD;

        float acc[2][8][4];
#pragma unroll
        for (int i = 0; i < 2; ++i)
#pragma unroll
            for (int j = 0; j < 8; ++j)
#pragma unroll
                for (int q = 0; q < 4; ++q) acc[i][j][q] = 0.0f;

        f16_mainloop(sb, tid, lane, warp_m, warp_n, A, B, DD, DD / 64, acc);

        const int rbase = y * 128 + warp_m * 32 + (lane >> 2);
        const int cbase = x * 128 + warp_n * 64 + (lane & 3) * 2;
        float* Sp = g_S + (long)bz * LL * LL;
#pragma unroll
        for (int mt = 0; mt < 2; ++mt)
#pragma unroll
            for (int nt = 0; nt < 8; ++nt) {
                const long r = rbase + mt * 16;
                const long c = cbase + nt * 8;
                *(float2*)(Sp + r * LL + c) = make_float2(acc[mt][nt][0], acc[mt][nt][1]);
                *(float2*)(Sp + (r + 8) * LL + c) = make_float2(acc[mt][nt][2], acc[mt][nt][3]);
            }

        // fused softmax partial stats (reuse smem)
        __syncthreads();
        float2* sm_row = (float2*)smem;
        float2* sm_col = ((float2*)smem) + 256;

#pragma unroll
        for (int mt = 0; mt < 2; ++mt)
#pragma unroll
            for (int half = 0; half < 2; ++half) {
                float m = -1e30f;
#pragma unroll
                for (int nt = 0; nt < 8; ++nt) {
                    m = fmaxf(m, acc[mt][nt][half * 2 + 0]);
                    m = fmaxf(m, acc[mt][nt][half * 2 + 1]);
                }
                float sv = 0.0f;
#pragma unroll
                for (int nt = 0; nt < 8; ++nt) {
                    sv += __expf(acc[mt][nt][half * 2 + 0] - m);
                    sv += __expf(acc[mt][nt][half * 2 + 1] - m);
                }
#pragma unroll
                for (int o = 1; o <= 2; o <<= 1) {
                    float om = __shfl_xor_sync(0xffffffffu, m, o);
                    float os = __shfl_xor_sync(0xffffffffu, sv, o);
                    merge_ms(m, sv, om, os);
                }
                if ((lane & 3) == 0) {
                    const int rowl = warp_m * 32 + mt * 16 + half * 8 + (lane >> 2);
                    sm_row[warp_n * 128 + rowl] = make_float2(m, sv);
                }
            }

#pragma unroll
        for (int nt = 0; nt < 8; ++nt)
#pragma unroll
            for (int c = 0; c < 2; ++c) {
                const float v0 = acc[0][nt][c] * INV_SCALE;
                const float v1 = acc[0][nt][2 + c] * INV_SCALE;
                const float v2 = acc[1][nt][c] * INV_SCALE;
                const float v3 = acc[1][nt][2 + c] * INV_SCALE;
                float m = fmaxf(fmaxf(v0, v1), fmaxf(v2, v3));
                float sv = __expf(v0 - m) + __expf(v1 - m) +
                           __expf(v2 - m) + __expf(v3 - m);
#pragma unroll
                for (int o = 4; o <= 16; o <<= 1) {
                    float om = __shfl_xor_sync(0xffffffffu, m, o);
                    float os = __shfl_xor_sync(0xffffffffu, sv, o);
                    merge_ms(m, sv, om, os);
                }
                if ((lane >> 2) == 0) {
                    const int coll = warp_n * 64 + nt * 8 + (lane & 3) * 2 + c;
                    sm_col[warp_m * 128 + coll] = make_float2(m, sv);
                }
            }

        __syncthreads();
        if (tid < 128) {
            float2 a = sm_row[tid];
            float2 b = sm_row[128 + tid];
            merge_ms(a.x, a.y, b.x, b.y);
            g_prow[x][(long)bz * LL + y * 128 + tid] = a;

            float2 ac = sm_col[tid];
#pragma unroll
            for (int w = 1; w < 4; ++w) {
                float2 bc = sm_col[w * 128 + tid];
                merge_ms(ac.x, ac.y, bc.x, bc.y);
            }
            g_pcol[y][(long)bz * LL + x * 128 + tid] = ac;
        }

        __threadfence();
        __syncthreads();
        if (tid == 0) {
            atomicAdd(&c_all[CI_SROW + bz * 8 + y], 1);
            atomicAdd(&c_all[CI_SCOL + bz * 8 + x], 1);
        }

    } else if (idx < 1936) {
        // =================== TRANSFORM ===================
        const int t = idx - 1424;
        const int xb = t & 7, yb = (t >> 3) & 7, bz = t >> 6;

        if (tid == 0) {
            wait_ge(&c_all[CI_SROW + bz * 8 + yb], 8);
            wait_ge(&c_all[CI_SCOL + bz * 8 + xb], 8);
        }
        __syncthreads();

        float* rowc_s = (float*)smem;             // 128
        float* colc_s = rowc_s + 128;             // 128
        __half* tr = (__half*)(colc_s + 128);     // [128][130]

        if (tid < 128) {
            float m = -1e30f, sv = 0.0f;
#pragma unroll
            for (int p = 0; p < 8; ++p) {
                const float2 v = g_prow[p][(long)bz * LL + yb * 128 + tid];
                merge_ms(m, sv, v.x, v.y);
            }
            rowc_s[tid] = m + __logf(sv);
        } else {
            const int c = tid - 128;
            float m = -1e30f, sv = 0.0f;
#pragma unroll
            for (int p = 0; p < 8; ++p) {
                const float2 v = g_pcol[p][(long)bz * LL + xb * 128 + c];
                merge_ms(m, sv, v.x, v.y);
            }
            colc_s[c] = m + __logf(sv);
        }
        __syncthreads();

        const size_t base = (size_t)bz * LL * LL;
#pragma unroll 4
        for (int i = 0; i < 64; ++i) {
            const int r = i * 2 + (tid >> 7);
            const int c = tid & 127;
            const size_t gi = base + (size_t)(yb * 128 + r) * LL + xb * 128 + c;
            const float sval = g_S[gi];
            g_P1[gi] = __float2half(__expf(sval - rowc_s[r]));
            tr[c * 130 + r] = __float2half(__expf(sval * INV_SCALE - colc_s[c]));
        }
        __syncthreads();
#pragma unroll 4
        for (int i = 0; i < 64; ++i) {
            const int rr = i * 2 + (tid >> 7);
            const int cc = tid & 127;
            g_P2T[base + (size_t)(xb * 128 + rr) * LL + yb * 128 + cc] = tr[rr * 130 + cc];
        }

        __threadfence();
        __syncthreads();
        if (tid == 0) {
            atomicAdd(&c_all[CI_P1 + bz * 8 + yb], 1);
            atomicAdd(&c_all[CI_P2 + bz * 8 + xb], 1);
        }

    } else {
        // =================== APPLY ===================
        const int warp_m = wid & 3, warp_n = wid >> 2;
        const int a = idx - 1936;
        const int x = a % 6;
        const int y = (a / 6) % 8;
        const int zz = a / 48;
        const int bz = zz & 7, dir = zz >> 3;

        if (tid == 0) {
            wait_ge(dir ? &c_all[CI_P2 + bz * 8 + y] : &c_all[CI_P1 + bz * 8 + y], 8);
            wait_ge(&c_all[CI_XT + (dir ? 0 : 8) + bz], 8);
        }
        __syncthreads();

        const __half* P = dir ? g_P2T : g_P1;
        const __half* V = dir ? s_lhsT_h : s_rhsT_h;
        float* outp = dir ? out + (size_t)BB * LL * 1536 : out;

        float acc[2][8][4];
#pragma unroll
        for (int i = 0; i < 2; ++i)
#pragma unroll
            for (int j = 0; j < 8; ++j)
#pragma unroll
                for (int q = 0; q < 4; ++q) acc[i][j][q] = 0.0f;

        f16_mainloop(sb, tid, lane, warp_m, warp_n,
                     P + (long)bz * LL * LL + (long)y * 128 * LL,
                     V + (long)bz * DD * LL + (long)x * 128 * LL,
                     LL, LL / 64, acc);
        __syncthreads();

        const int rbase = y * 128 + warp_m * 32 + (lane >> 2);
        const int cbase = x * 128 + warp_n * 64 + (lane & 3) * 2;
        float* Ob = outp + (long)bz * LL * 1536 + DD;
#pragma unroll
        for (int mt = 0; mt < 2; ++mt)
#pragma unroll
            for (int nt = 0; nt < 8; ++nt) {
                const long r = rbase + mt * 16;
                const long c = cbase + nt * 8;
                float* Cp = Ob + r * 1536 + c;
                *(float2*)Cp = make_float2(acc[mt][nt][0], acc[mt][nt][1]);
                *(float2*)(Cp + 8L * 1536) = make_float2(acc[mt][nt][2], acc[mt][nt][3]);
            }
    }
}

// counter reset (must run before mega every replay)
__global__ void reset_ctr()
{
    const int i = blockIdx.x * blockDim.x + threadIdx.x;
    if (i < NCTR) c_all[i] = 0;
}

// ---------------------------------------------------------------------------
// launch
// ---------------------------------------------------------------------------
extern "C" void kernel_launch(void* const* d_in, const int* in_sizes, int n_in,
                              void* d_out, int out_size)
{
    const float* lhs = (const float*)d_in[0];
    const float* rhs = (const float*)d_in[1];
    const float* Wl  = (const float*)d_in[2];
    const float* Wr  = (const float*)d_in[3];
    float* out = (float*)d_out;

    cudaFuncSetAttribute(mega, cudaFuncAttributeMaxDynamicSharedMemorySize, SMEM_DYN);

    reset_ctr<<<3, 256>>>();
    mega<<<2704, 256, SMEM_DYN>>>(lhs, rhs, Wl, Wr, out);
}

// round 15
// speedup vs baseline: 2.1411x; 1.0041x over previous
#include <cuda_runtime.h>
#include <cuda_bf16.h>
#include <cuda_fp16.h>
#include <cstdint>
#include <math.h>

#define BB 8
#define LL 1024
#define DD 768
#define INV_SCALE 0.03608439182435161f  /* 1/sqrt(768) */

// ---------------------------------------------------------------------------
// scratch (device globals; no allocation)
// ---------------------------------------------------------------------------
__device__ __half s_lhs_h[BB * LL * DD], s_lhs_l[BB * LL * DD];   // proj A fp16 hi/lo
__device__ __half s_rhs_h[BB * LL * DD], s_rhs_l[BB * LL * DD];
__device__ __half s_lhsT_h[BB * DD * LL];   // apply B (fp16, single, transposed)
__device__ __half s_rhsT_h[BB * DD * LL];
__device__ __half s_Wl_h[DD * DD];          // W fp16 single
__device__ __half s_Wr_h[DD * DD];
__device__ __half g_L_h[BB * LL * DD];   // tanh(lhs@Wl) fp16 single
__device__ __half g_R_h[BB * LL * DD];   // tanh(rhs@Wr) fp16 single
__device__ __half g_P1[BB * LL * LL];    // row-softmax probs fp16 [l][r]
__device__ __half g_P2T[BB * LL * LL];   // col-softmax probs fp16, transposed [r][l]
__device__ float g_S[BB * LL * LL];
__device__ float2 g_prow[8][BB * LL];    // per-block row partials [col-block x][row]
__device__ float2 g_pcol[8][BB * LL];    // per-block col partials [row-block y][col]

// dependency counters
#define CI_PREP_L 0     /* 64 entries [by128], target 2 */
#define CI_PREP_R 64    /* 64 entries, target 2 */
#define CI_W 128        /* 1 entry, target 32 */
#define CI_PROJ 144     /* 128 entries [z*64+by], target 6 */
#define CI_SROW 272     /* 64 [bz*8+y], target 8 */
#define CI_SCOL 336     /* 64 [bz*8+x], target 8 */
#define CI_P1 400       /* 64 [bz*8+yb], target 8 */
#define CI_P2 464       /* 64 [bz*8+xb], target 8 */
#define CI_XT 528       /* 16 [side*8+b], target 16 */
#define NCTR 544
__device__ int c_all[NCTR];

__device__ __forceinline__ float fast_tanh(float x) {
    return 1.0f - __fdividef(2.0f, __expf(2.0f * x) + 1.0f);
}

__device__ __forceinline__ uint32_t smem_to_u32(const void* p) {
    uint32_t a;
    asm("{ .reg .u64 t; cvta.to.shared.u64 t, %1; cvt.u32.u64 %0, t; }"
        : "=r"(a) : "l"(p));
    return a;
}

__device__ __forceinline__ void merge_ms(float& m, float& s, float om, float os) {
    const float nm = fmaxf(m, om);
    s = s * __expf(m - nm) + os * __expf(om - nm);
    m = nm;
}

__device__ __forceinline__ void wait_ge(int* ctr, int target) {
    while (atomicAdd(ctr, 0) < target) __nanosleep(64);
}

// ---------------------------------------------------------------------------
// MMA helpers
// ---------------------------------------------------------------------------
__device__ __forceinline__ void ldsm4(uint32_t* r, uint32_t addr) {
    asm volatile("ldmatrix.sync.aligned.m8n8.x4.shared.b16 {%0,%1,%2,%3}, [%4];"
                 : "=r"(r[0]), "=r"(r[1]), "=r"(r[2]), "=r"(r[3]) : "r"(addr));
}

__device__ __forceinline__ void mma16816_f16(float* d, const uint32_t* a,
                                             uint32_t b0, uint32_t b1) {
    asm volatile(
        "mma.sync.aligned.m16n8k16.row.col.f32.f16.f16.f32 "
        "{%0,%1,%2,%3}, {%4,%5,%6,%7}, {%8,%9}, {%0,%1,%2,%3};"
        : "+f"(d[0]), "+f"(d[1]), "+f"(d[2]), "+f"(d[3])
        : "r"(a[0]), "r"(a[1]), "r"(a[2]), "r"(a[3]), "r"(b0), "r"(b1));
}

#define CP_ASYNC16(saddr, gptr) \
    asm volatile("cp.async.cg.shared.global [%0], [%1], 16;" \
        :: "r"(saddr), "l"(gptr) : "memory")
#define CP_COMMIT() asm volatile("cp.async.commit_group;" ::: "memory")
#define CP_WAIT(n) asm volatile("cp.async.wait_group %0;" :: "n"(n) : "memory")

// 64B-row tile (K-chunk 32 b16 elems)
__device__ __forceinline__ uint32_t tile_addr(uint32_t matbase, int row, int chunk) {
    int swz = chunk ^ (row & 3) ^ ((row >> 2) & 1);
    return matbase + row * 64 + swz * 16;
}
__device__ __forceinline__ uint32_t frag_addr(uint32_t matbase, int baserow,
                                              int kg, int lane) {
    int row = baserow + (lane & 7) + ((lane >> 3) & 1) * 8;
    int chunk = kg * 2 + ((lane >> 4) & 1);
    return tile_addr(matbase, row, chunk);
}
// 128B-row tile (fp16 K-chunk 64)
__device__ __forceinline__ uint32_t tile2_addr(uint32_t matbase, int row, int chunk) {
    int swz = chunk ^ (row & 7);
    return matbase + row * 128 + swz * 16;
}
__device__ __forceinline__ uint32_t frag2_addr(uint32_t matbase, int baserow,
                                               int kg, int lane) {
    int row = baserow + (lane & 7) + ((lane >> 3) & 1) * 8;
    int chunk = kg * 2 + ((lane >> 4) & 1);
    return tile2_addr(matbase, row, chunk);
}

#define MAT_BYTES 8192
#define STAGE_P 24576   /* proj: 3 matrices x 8 KB */
#define MAT2_BYTES 16384
#define STAGEA 32768    /* scores: 2 matrices x 16 KB */
#define STAGE_AP 24576  /* apply: A 16 KB + B 8 KB */
#define SMEM_DYN (3 * STAGEA)   /* 96 KB, shared by all phases */

// fp16 asym-2 proj mainloop: (Ah + Al) @ Wh^T, K-chunk 32
__device__ __forceinline__ void f16x2_mainloop(
    uint32_t sb, int tid, int lane, int warp_m, int warp_n,
    const __half* Ah, const __half* Al, const __half* Wh,
    int ldk, int nch, float acc[2][8][4])
{
    const __half* mats[3] = {Ah, Al, Wh};
    const int r0a = tid >> 2, c0a = tid & 3;
    const int r0b = (tid + 256) >> 2;

    auto load_chunk = [&](int slot, int k) {
        const uint32_t base = sb + slot * STAGE_P;
        const long koff = (long)k * 32;
#pragma unroll
        for (int mat = 0; mat < 3; ++mat) {
            const __half* g = mats[mat] + koff;
            const uint32_t mb = base + mat * MAT_BYTES;
            CP_ASYNC16(tile_addr(mb, r0a, c0a), g + (long)r0a * ldk + c0a * 8);
            CP_ASYNC16(tile_addr(mb, r0b, c0a), g + (long)r0b * ldk + c0a * 8);
        }
        CP_COMMIT();
    };

    load_chunk(0, 0);
    load_chunk(1, 1);

#pragma unroll 1
    for (int k = 0; k < nch; ++k) {
        CP_WAIT(1);
        __syncthreads();
        if (k + 2 < nch) load_chunk((k + 2) % 3, k + 2);

        const uint32_t base = sb + (k % 3) * STAGE_P;
        const uint32_t sAh = base, sAl = base + MAT_BYTES;
        const uint32_t sW = base + 2 * MAT_BYTES;

#pragma unroll
        for (int kg = 0; kg < 2; ++kg) {
            uint32_t ah[2][4], al[2][4], bw[4][4];
#pragma unroll
            for (int mt = 0; mt < 2; ++mt) {
                ldsm4(ah[mt], frag_addr(sAh, warp_m * 32 + mt * 16, kg, lane));
                ldsm4(al[mt], frag_addr(sAl, warp_m * 32 + mt * 16, kg, lane));
            }
#pragma unroll
            for (int ng = 0; ng < 4; ++ng)
                ldsm4(bw[ng], frag_addr(sW, warp_n * 64 + ng * 16, kg, lane));
#pragma unroll
            for (int term = 0; term < 2; ++term)
#pragma unroll
                for (int mt = 0; mt < 2; ++mt)
#pragma unroll
                    for (int ng = 0; ng < 4; ++ng)
#pragma unroll
                        for (int h = 0; h < 2; ++h) {
                            const uint32_t* a = term ? al[mt] : ah[mt];
                            mma16816_f16(acc[mt][ng * 2 + h], a,
                                         bw[ng][h], bw[ng][h + 2]);
                        }
        }
    }
}

// fp16 single x single mainloop (scores): 128x128, K-chunk 64
__device__ __forceinline__ void f16_mainloop(
    uint32_t sb, int tid, int lane, int warp_m, int warp_n,
    const __half* A, const __half* B, int ldk, int nch, float acc[2][8][4])
{
    const __half* mats[2] = {A, B};
    const int rr0 = tid >> 3, cc0 = tid & 7;

    auto load_chunk = [&](int slot, int k) {
        const uint32_t base = sb + slot * STAGEA;
        const long koff = (long)k * 64;
#pragma unroll
        for (int mat = 0; mat < 2; ++mat) {
            const __half* g = mats[mat] + koff;
            const uint32_t mb = base + mat * MAT2_BYTES;
#pragma unroll
            for (int i = 0; i < 4; ++i) {
                const int row = rr0 + i * 32;
                CP_ASYNC16(tile2_addr(mb, row, cc0), g + (long)row * ldk + cc0 * 8);
            }
        }
        CP_COMMIT();
    };

    load_chunk(0, 0);
    load_chunk(1, 1);

#pragma unroll 1
    for (int k = 0; k < nch; ++k) {
        CP_WAIT(1);
        __syncthreads();
        if (k + 2 < nch) load_chunk((k + 2) % 3, k + 2);

        const uint32_t base = sb + (k % 3) * STAGEA;
        const uint32_t sA = base;
        const uint32_t sB = base + MAT2_BYTES;

#pragma unroll
        for (int kg = 0; kg < 4; ++kg) {
            uint32_t af[2][4], bfr[4][4];
#pragma unroll
            for (int mt = 0; mt < 2; ++mt)
                ldsm4(af[mt], frag2_addr(sA, warp_m * 32 + mt * 16, kg, lane));
#pragma unroll
            for (int ng = 0; ng < 4; ++ng)
                ldsm4(bfr[ng], frag2_addr(sB, warp_n * 64 + ng * 16, kg, lane));
#pragma unroll
            for (int mt = 0; mt < 2; ++mt)
#pragma unroll
                for (int ng = 0; ng < 4; ++ng)
#pragma unroll
                    for (int h = 0; h < 2; ++h)
                        mma16816_f16(acc[mt][ng * 2 + h], af[mt],
                                     bfr[ng][h], bfr[ng][h + 2]);
        }
    }
}

// ---------------------------------------------------------------------------
// mega kernel.  Grid layout:
// [0,256)     prep inputs (64 rows each)
// [256,288)   prep W
// [288,1056)  proj (fp16x2, tanh -> L/R fp16 single), 128x128
// [1056,1568) scores (fp16) + fused softmax partial stats, 128x128
// [1568,2080) transform
// [2080,3616) apply (fp16), 128x64 tiles
// ---------------------------------------------------------------------------
__global__ __launch_bounds__(256, 2) void mega(
    const float* __restrict__ lhs, const float* __restrict__ rhs,
    const float* __restrict__ Wl, const float* __restrict__ Wr,
    float* __restrict__ out)
{
    extern __shared__ char smem[];
    const uint32_t sb = smem_to_u32(smem);
    const int tid = threadIdx.x;
    const int lane = tid & 31;
    const int wid = tid >> 5;
    const int idx = blockIdx.x;

    if (idx < 256) {
        // =================== PREP inputs (64 rows) ===================
        const int side = idx >> 7, q64 = idx & 127;
        const int b = q64 >> 4, l0v = (q64 & 15) * 64;
        const float* X = (side ? rhs : lhs) + ((size_t)b * LL + l0v) * DD;
        __half* Xh = (side ? s_rhs_h : s_lhs_h) + ((size_t)b * LL + l0v) * DD;
        __half* Xl = (side ? s_rhs_l : s_lhs_l) + ((size_t)b * LL + l0v) * DD;
        __half* XT = (side ? s_rhsT_h : s_lhsT_h) + (size_t)b * DD * LL + l0v;
        float* ob = out + (side ? (size_t)BB * LL * 1536 : 0)
                    + ((size_t)b * LL + l0v) * 1536;
        __half* tr = (__half*)smem;   // [32][72]

#pragma unroll 1
        for (int t = 0; t < 24; ++t) {
            const int d0 = t * 32;
#pragma unroll
            for (int i = 0; i < 2; ++i) {
                const int fi = tid + i * 256;   // 0..511
                const int row = fi >> 3, q = fi & 7;
                const float4 v = *(const float4*)(X + (size_t)row * DD + d0 + q * 4);
                const float vv[4] = {v.x, v.y, v.z, v.w};
                uint32_t hp[2], lp[2];
#pragma unroll
                for (int j = 0; j < 2; ++j) {
                    const __half h0 = __float2half(vv[2 * j]);
                    const __half h1 = __float2half(vv[2 * j + 1]);
                    const __half lo0 = __float2half(vv[2 * j] - __half2float(h0));
                    const __half lo1 = __float2half(vv[2 * j + 1] - __half2float(h1));
                    __half2 hh; hh.x = h0; hh.y = h1;
                    __half2 llv; llv.x = lo0; llv.y = lo1;
                    hp[j] = *(uint32_t*)&hh; lp[j] = *(uint32_t*)&llv;
                }
                *(uint2*)(Xh + (size_t)row * DD + d0 + q * 4) = make_uint2(hp[0], hp[1]);
                *(uint2*)(Xl + (size_t)row * DD + d0 + q * 4) = make_uint2(lp[0], lp[1]);
                *(float4*)(ob + (size_t)row * 1536 + d0 + q * 4) = v;
#pragma unroll
                for (int j = 0; j < 4; ++j)
                    tr[(q * 4 + j) * 72 + row] = __float2half(vv[j]);
            }
            __syncthreads();
            {
                const int d = tid >> 3, c = tid & 7;     // 32 d x 8 c (8 halfs)
                const float4 w0 = *(float4*)&tr[d * 72 + c * 8];
                *(float4*)(XT + (size_t)(d0 + d) * LL + c * 8) = w0;
            }
            __syncthreads();
        }
        __threadfence();
        __syncthreads();
        if (tid == 0) {
            atomicAdd(&c_all[(side ? CI_PREP_R : CI_PREP_L) + (q64 >> 1)], 1);
            atomicAdd(&c_all[CI_XT + side * 8 + b], 1);
        }

    } else if (idx < 288) {
        // =================== PREP W (fp16 single) ===================
        const int wb = idx - 256;   // 0..31
#pragma unroll 1
        for (int w = 0; w < 2; ++w) {
            const float* W = w ? Wr : Wl;
            __half* Wh = w ? s_Wr_h : s_Wl_h;
#pragma unroll 1
            for (int i = 0; i < 18; ++i) {
                const long f = (long)wb * 4608 + i * 256 + tid;
                const float4 v = *(const float4*)(W + f * 4);
                __half2 a; a.x = __float2half(v.x); a.y = __float2half(v.y);
                __half2 b; b.x = __float2half(v.z); b.y = __float2half(v.w);
                *(uint2*)(Wh + f * 4) = make_uint2(*(uint32_t*)&a, *(uint32_t*)&b);
            }
        }
        __threadfence();
        __syncthreads();
        if (tid == 0) atomicAdd(&c_all[CI_W], 1);

    } else if (idx < 1056) {
        // =================== PROJ (fp16 x2) ===================
        const int warp_m = wid & 3, warp_n = wid >> 2;
        const int p = idx - 288;
        const int bx = p % 6;
        const int by = (p / 6) % 64;
        const int z = p / 384;

        if (tid == 0) {
            wait_ge(&c_all[(z ? CI_PREP_R : CI_PREP_L) + by], 2);
            wait_ge(&c_all[CI_W], 32);
        }
        __syncthreads();

        const __half* Ah = (z ? s_rhs_h : s_lhs_h) + (long)by * 128 * DD;
        const __half* Al = (z ? s_rhs_l : s_lhs_l) + (long)by * 128 * DD;
        const __half* Wh = (z ? s_Wr_h : s_Wl_h) + (long)bx * 128 * DD;
        __half* Cd = z ? g_R_h : g_L_h;

        float acc[2][8][4];
#pragma unroll
        for (int i = 0; i < 2; ++i)
#pragma unroll
            for (int j = 0; j < 8; ++j)
#pragma unroll
                for (int q = 0; q < 4; ++q) acc[i][j][q] = 0.0f;

        f16x2_mainloop(sb, tid, lane, warp_m, warp_n, Ah, Al, Wh, DD, DD / 32, acc);

        const int rbase = by * 128 + warp_m * 32 + (lane >> 2);
        const int cbase = bx * 128 + warp_n * 64 + (lane & 3) * 2;
#pragma unroll
        for (int mt = 0; mt < 2; ++mt)
#pragma unroll
            for (int nt = 0; nt < 8; ++nt)
#pragma unroll
                for (int half = 0; half < 2; ++half) {
                    const long r = rbase + mt * 16 + half * 8;
                    const long c = cbase + nt * 8;
                    __half2 hh;
                    hh.x = __float2half(fast_tanh(acc[mt][nt][half * 2 + 0]));
                    hh.y = __float2half(fast_tanh(acc[mt][nt][half * 2 + 1]));
                    *(uint32_t*)(Cd + r * DD + c) = *(uint32_t*)&hh;
                }

        __threadfence();
        __syncthreads();
        if (tid == 0) atomicAdd(&c_all[CI_PROJ + z * 64 + by], 1);

    } else if (idx < 1568) {
        // =================== SCORES (fp16 x fp16) ===================
        const int warp_m = wid & 3, warp_n = wid >> 2;
        const int s = idx - 1056;
        const int x = s & 7, y = (s >> 3) & 7, bz = s >> 6;

        if (tid == 0) {
            wait_ge(&c_all[CI_PROJ + bz * 8 + y], 6);
            wait_ge(&c_all[CI_PROJ + 64 + bz * 8 + x], 6);
        }
        __syncthreads();

        const __half* A = g_L_h + ((long)bz * LL + (long)y * 128) * DD;
        const __half* B = g_R_h + ((long)bz * LL + (long)x * 128) * DD;

        float acc[2][8][4];
#pragma unroll
        for (int i = 0; i < 2; ++i)
#pragma unroll
            for (int j = 0; j < 8; ++j)
#pragma unroll
                for (int q = 0; q < 4; ++q) acc[i][j][q] = 0.0f;

        f16_mainloop(sb, tid, lane, warp_m, warp_n, A, B, DD, DD / 64, acc);

        const int rbase = y * 128 + warp_m * 32 + (lane >> 2);
        const int cbase = x * 128 + warp_n * 64 + (lane & 3) * 2;
        float* Sp = g_S + (long)bz * LL * LL;
#pragma unroll
        for (int mt = 0; mt < 2; ++mt)
#pragma unroll
            for (int nt = 0; nt < 8; ++nt) {
                const long r = rbase + mt * 16;
                const long c = cbase + nt * 8;
                *(float2*)(Sp + r * LL + c) = make_float2(acc[mt][nt][0], acc[mt][nt][1]);
                *(float2*)(Sp + (r + 8) * LL + c) = make_float2(acc[mt][nt][2], acc[mt][nt][3]);
            }

        // fused softmax partial stats (reuse smem)
        __syncthreads();
        float2* sm_row = (float2*)smem;
        float2* sm_col = ((float2*)smem) + 256;

#pragma unroll
        for (int mt = 0; mt < 2; ++mt)
#pragma unroll
            for (int half = 0; half < 2; ++half) {
                float m = -1e30f;
#pragma unroll
                for (int nt = 0; nt < 8; ++nt) {
                    m = fmaxf(m, acc[mt][nt][half * 2 + 0]);
                    m = fmaxf(m, acc[mt][nt][half * 2 + 1]);
                }
                float sv = 0.0f;
#pragma unroll
                for (int nt = 0; nt < 8; ++nt) {
                    sv += __expf(acc[mt][nt][half * 2 + 0] - m);
                    sv += __expf(acc[mt][nt][half * 2 + 1] - m);
                }
#pragma unroll
                for (int o = 1; o <= 2; o <<= 1) {
                    float om = __shfl_xor_sync(0xffffffffu, m, o);
                    float os = __shfl_xor_sync(0xffffffffu, sv, o);
                    merge_ms(m, sv, om, os);
                }
                if ((lane & 3) == 0) {
                    const int rowl = warp_m * 32 + mt * 16 + half * 8 + (lane >> 2);
                    sm_row[warp_n * 128 + rowl] = make_float2(m, sv);
                }
            }

#pragma unroll
        for (int nt = 0; nt < 8; ++nt)
#pragma unroll
            for (int c = 0; c < 2; ++c) {
                const float v0 = acc[0][nt][c] * INV_SCALE;
                const float v1 = acc[0][nt][2 + c] * INV_SCALE;
                const float v2 = acc[1][nt][c] * INV_SCALE;
                const float v3 = acc[1][nt][2 + c] * INV_SCALE;
                float m = fmaxf(fmaxf(v0, v1), fmaxf(v2, v3));
                float sv = __expf(v0 - m) + __expf(v1 - m) +
                           __expf(v2 - m) + __expf(v3 - m);
#pragma unroll
                for (int o = 4; o <= 16; o <<= 1) {
                    float om = __shfl_xor_sync(0xffffffffu, m, o);
                    float os = __shfl_xor_sync(0xffffffffu, sv, o);
                    merge_ms(m, sv, om, os);
                }
                if ((lane >> 2) == 0) {
                    const int coll = warp_n * 64 + nt * 8 + (lane & 3) * 2 + c;
                    sm_col[warp_m * 128 + coll] = make_float2(m, sv);
                }
            }

        __syncthreads();
        if (tid < 128) {
            float2 a = sm_row[tid];
            float2 b = sm_row[128 + tid];
            merge_ms(a.x, a.y, b.x, b.y);
            g_prow[x][(long)bz * LL + y * 128 + tid] = a;

            float2 ac = sm_col[tid];
#pragma unroll
            for (int w = 1; w < 4; ++w) {
                float2 bc = sm_col[w * 128 + tid];
                merge_ms(ac.x, ac.y, bc.x, bc.y);
            }
            g_pcol[y][(long)bz * LL + x * 128 + tid] = ac;
        }

        __threadfence();
        __syncthreads();
        if (tid == 0) {
            atomicAdd(&c_all[CI_SROW + bz * 8 + y], 1);
            atomicAdd(&c_all[CI_SCOL + bz * 8 + x], 1);
        }

    } else if (idx < 2080) {
        // =================== TRANSFORM ===================
        const int t = idx - 1568;
        const int xb = t & 7, yb = (t >> 3) & 7, bz = t >> 6;

        if (tid == 0) {
            wait_ge(&c_all[CI_SROW + bz * 8 + yb], 8);
            wait_ge(&c_all[CI_SCOL + bz * 8 + xb], 8);
        }
        __syncthreads();

        float* rowc_s = (float*)smem;             // 128
        float* colc_s = rowc_s + 128;             // 128
        __half* tr = (__half*)(colc_s + 128);     // [128][130]

        if (tid < 128) {
            float m = -1e30f, sv = 0.0f;
#pragma unroll
            for (int p = 0; p < 8; ++p) {
                const float2 v = g_prow[p][(long)bz * LL + yb * 128 + tid];
                merge_ms(m, sv, v.x, v.y);
            }
            rowc_s[tid] = m + __logf(sv);
        } else {
            const int c = tid - 128;
            float m = -1e30f, sv = 0.0f;
#pragma unroll
            for (int p = 0; p < 8; ++p) {
                const float2 v = g_pcol[p][(long)bz * LL + xb * 128 + c];
                merge_ms(m, sv, v.x, v.y);
            }
            colc_s[c] = m + __logf(sv);
        }
        __syncthreads();

        const size_t base = (size_t)bz * LL * LL;
#pragma unroll 4
        for (int i = 0; i < 64; ++i) {
            const int r = i * 2 + (tid >> 7);
            const int c = tid & 127;
            const size_t gi = base + (size_t)(yb * 128 + r) * LL + xb * 128 + c;
            const float sval = g_S[gi];
            g_P1[gi] = __float2half(__expf(sval - rowc_s[r]));
            tr[c * 130 + r] = __float2half(__expf(sval * INV_SCALE - colc_s[c]));
        }
        __syncthreads();
#pragma unroll 4
        for (int i = 0; i < 64; ++i) {
            const int rr = i * 2 + (tid >> 7);
            const int cc = tid & 127;
            g_P2T[base + (size_t)(xb * 128 + rr) * LL + yb * 128 + cc] = tr[rr * 130 + cc];
        }

        __threadfence();
        __syncthreads();
        if (tid == 0) {
            atomicAdd(&c_all[CI_P1 + bz * 8 + yb], 1);
            atomicAdd(&c_all[CI_P2 + bz * 8 + xb], 1);
        }

    } else {
        // =================== APPLY (128x64 tiles) ===================
        const int warp_m = wid & 3, warp_n = wid >> 2;
        const int a = idx - 2080;
        const int x = a % 12;
        const int y = (a / 12) % 8;
        const int zz = a / 96;
        const int bz = zz & 7, dir = zz >> 3;

        if (tid == 0) {
            wait_ge(dir ? &c_all[CI_P2 + bz * 8 + y] : &c_all[CI_P1 + bz * 8 + y], 8);
            wait_ge(&c_all[CI_XT + (dir ? 0 : 8) + bz], 16);
        }
        __syncthreads();

        const __half* P = dir ? g_P2T : g_P1;
        const __half* V = dir ? s_lhsT_h : s_rhsT_h;
        float* outp = dir ? out + (size_t)BB * LL * 1536 : out;

        const __half* Ap = P + (long)bz * LL * LL + (long)y * 128 * LL;
        const __half* Bp = V + (long)bz * DD * LL + (long)x * 64 * LL;

        const int rr0 = tid >> 3, cc0 = tid & 7;

        auto load_chunk = [&](int slot, int k) {
            const uint32_t base = sb + slot * STAGE_AP;
            const long koff = (long)k * 64;
            // A: 128 rows (16 KB)
#pragma unroll
            for (int i = 0; i < 4; ++i) {
                const int row = rr0 + i * 32;
                CP_ASYNC16(tile2_addr(base, row, cc0), Ap + (long)row * LL + koff + cc0 * 8);
            }
            // B: 64 rows (8 KB)
#pragma unroll
            for (int i = 0; i < 2; ++i) {
                const int row = rr0 + i * 32;
                CP_ASYNC16(tile2_addr(base + 16384, row, cc0),
                           Bp + (long)row * LL + koff + cc0 * 8);
            }
            CP_COMMIT();
        };

        float acc[2][4][4];
#pragma unroll
        for (int i = 0; i < 2; ++i)
#pragma unroll
            for (int j = 0; j < 4; ++j)
#pragma unroll
                for (int q = 0; q < 4; ++q) acc[i][j][q] = 0.0f;

        load_chunk(0, 0);
        load_chunk(1, 1);

#pragma unroll 1
        for (int k = 0; k < 16; ++k) {
            CP_WAIT(1);
            __syncthreads();
            if (k + 2 < 16) load_chunk((k + 2) % 3, k + 2);

            const uint32_t base = sb + (k % 3) * STAGE_AP;
            const uint32_t sA = base;
            const uint32_t sB = base + 16384;

#pragma unroll
            for (int kg = 0; kg < 4; ++kg) {
                uint32_t af[2][4], bfr[2][4];
#pragma unroll
                for (int mt = 0; mt < 2; ++mt)
                    ldsm4(af[mt], frag2_addr(sA, warp_m * 32 + mt * 16, kg, lane));
#pragma unroll
                for (int bt = 0; bt < 2; ++bt)
                    ldsm4(bfr[bt], frag2_addr(sB, warp_n * 32 + bt * 16, kg, lane));
#pragma unroll
                for (int mt = 0; mt < 2; ++mt)
#pragma unroll
                    for (int bt = 0; bt < 2; ++bt)
#pragma unroll
                        for (int h = 0; h < 2; ++h)
                            mma16816_f16(acc[mt][bt * 2 + h], af[mt],
                                         bfr[bt][h], bfr[bt][h + 2]);
            }
        }
        __syncthreads();

        const int rbase = y * 128 + warp_m * 32 + (lane >> 2);
        const int cbase = x * 64 + warp_n * 32 + (lane & 3) * 2;
        float* Ob = outp + (long)bz * LL * 1536 + DD;
#pragma unroll
        for (int mt = 0; mt < 2; ++mt)
#pragma unroll
            for (int nt = 0; nt < 4; ++nt) {
                const long r = rbase + mt * 16;
                const long c = cbase + nt * 8;
                float* Cp = Ob + r * 1536 + c;
                *(float2*)Cp = make_float2(acc[mt][nt][0], acc[mt][nt][1]);
                *(float2*)(Cp + 8L * 1536) = make_float2(acc[mt][nt][2], acc[mt][nt][3]);
            }
    }
}

// counter reset (must run before mega every replay)
__global__ void reset_ctr()
{
    const int i = blockIdx.x * blockDim.x + threadIdx.x;
    if (i < NCTR) c_all[i] = 0;
}

// ---------------------------------------------------------------------------
// launch
// ---------------------------------------------------------------------------
extern "C" void kernel_launch(void* const* d_in, const int* in_sizes, int n_in,
                              void* d_out, int out_size)
{
    const float* lhs = (const float*)d_in[0];
    const float* rhs = (const float*)d_in[1];
    const float* Wl  = (const float*)d_in[2];
    const float* Wr  = (const float*)d_in[3];
    float* out = (float*)d_out;

    cudaFuncSetAttribute(mega, cudaFuncAttributeMaxDynamicSharedMemorySize, SMEM_DYN);

    reset_ctr<<<3, 256>>>();
    mega<<<3616, 256, SMEM_DYN>>>(lhs, rhs, Wl, Wr, out);
}